// round 1
// baseline (speedup 1.0000x reference)
#include <cuda_runtime.h>
#include <float.h>
#include <math.h>

#define BB 16
#define NP 1024
#define KNN 20
#define EDGES (BB*NP*KNN)

// ---------------- scratch (static device globals; no allocation) ----------------
__device__ float g_gram[BB*NP*NP];        // 64 MB pairwise distances (per layer, reused)
__device__ float g_u[BB*NP*1024];         // u = X@Wa ; later overwritten with max-edge value
__device__ float g_v[BB*NP*1024];         // v = X@(Wb-Wa)
__device__ float g_x[BB*NP*1024];         // current layer features
__device__ float g_wv[128*1024];          // Wb - Wa
__device__ float g_sq[BB*NP];             // squared norms
__device__ int   g_idx[BB*NP*KNN];        // knn indices
__device__ float g_sum[1024];
__device__ float g_sum2[1024];
__device__ float g_scale[1024];
__device__ float g_shift[1024];
__device__ float g_pool[BB*1024];
__device__ float g_fc1[BB*512];

__device__ __forceinline__ const float* xsel(const float* xin) { return xin ? xin : g_x; }

// ---------------- squared norms ----------------
__global__ void k_sqnorm(const float* xin, int C) {
    const float* x = xsel(xin);
    int i = blockIdx.x * blockDim.x + threadIdx.x;
    if (i >= BB * NP) return;
    const float* r = x + (size_t)i * C;
    float s = 0.f;
    for (int c = 0; c < C; c++) { float v = r[c]; s += v * v; }
    g_sq[i] = s;
}

// ---------------- pairwise distance (Gram) : 64x64 tiles, 4x4 per thread ----------------
__global__ __launch_bounds__(256) void k_gram(const float* xin, int C) {
    const float* x = xsel(xin);
    int b = blockIdx.z;
    const float* xb = x + (size_t)b * NP * C;
    int m0 = blockIdx.y * 64, n0 = blockIdx.x * 64;
    int tid = threadIdx.x;
    int tx = tid & 15, ty = tid >> 4;

    __shared__ float As[64][17];
    __shared__ float Bs[16][65];

    float acc[4][4];
    #pragma unroll
    for (int i = 0; i < 4; i++)
        #pragma unroll
        for (int j = 0; j < 4; j++) acc[i][j] = 0.f;

    for (int k0 = 0; k0 < C; k0 += 16) {
        #pragma unroll
        for (int i = 0; i < 4; i++) {
            int s = tid + i * 256; int r = s >> 4, c = s & 15;
            As[r][c] = (k0 + c < C) ? xb[(size_t)(m0 + r) * C + k0 + c] : 0.f;
        }
        #pragma unroll
        for (int i = 0; i < 4; i++) {
            int s = tid + i * 256; int r = s >> 4, c = s & 15;
            Bs[c][r] = (k0 + c < C) ? xb[(size_t)(n0 + r) * C + k0 + c] : 0.f;
        }
        __syncthreads();
        #pragma unroll
        for (int kk = 0; kk < 16; kk++) {
            float ra[4], rb[4];
            #pragma unroll
            for (int i = 0; i < 4; i++) ra[i] = As[ty * 4 + i][kk];
            #pragma unroll
            for (int j = 0; j < 4; j++) rb[j] = Bs[kk][tx * 4 + j];
            #pragma unroll
            for (int i = 0; i < 4; i++)
                #pragma unroll
                for (int j = 0; j < 4; j++) acc[i][j] += ra[i] * rb[j];
        }
        __syncthreads();
    }

    #pragma unroll
    for (int i = 0; i < 4; i++) {
        int row = m0 + ty * 4 + i;
        float sqr = g_sq[b * NP + row];
        #pragma unroll
        for (int j = 0; j < 4; j++) {
            int col = n0 + tx * 4 + j;
            float d = sqr + g_sq[b * NP + col] - 2.f * acc[i][j];
            if (row == col) d += 1e10f;
            g_gram[((size_t)b * NP + row) * NP + col] = d;
        }
    }
}

// ---------------- kNN top-20: one warp per row ----------------
__global__ void k_knn() {
    int gt = blockIdx.x * blockDim.x + threadIdx.x;
    int w = gt >> 5;
    int lane = gt & 31;
    if (w >= BB * NP) return;
    const float* row = g_gram + (size_t)w * NP;
    float val[32];
    #pragma unroll
    for (int j = 0; j < 32; j++) val[j] = row[lane + j * 32];
    unsigned used = 0u;
    for (int t = 0; t < KNN; t++) {
        float bv = FLT_MAX; int bi = 1 << 30;
        #pragma unroll
        for (int j = 0; j < 32; j++) {
            int m = lane + j * 32;
            bool free_ = !((used >> j) & 1u);
            if (free_ && (val[j] < bv || (val[j] == bv && m < bi))) { bv = val[j]; bi = m; }
        }
        #pragma unroll
        for (int off = 16; off; off >>= 1) {
            float ov = __shfl_down_sync(0xffffffffu, bv, off);
            int   oi = __shfl_down_sync(0xffffffffu, bi, off);
            if (ov < bv || (ov == bv && oi < bi)) { bv = ov; bi = oi; }
        }
        int wi = __shfl_sync(0xffffffffu, bi, 0);
        if ((wi & 31) == lane) used |= (1u << (wi >> 5));
        if (lane == 0) g_idx[w * KNN + t] = wi;
    }
}

// ---------------- Wv = Wb - Wa ----------------
__global__ void k_wv(const float* W, int cin, int cout) {
    int i = blockIdx.x * 256 + threadIdx.x;
    if (i < cin * cout) g_wv[i] = W[cin * cout + i] - W[i];
}

// ---------------- GEMM: C[M,N] = A[M,K] @ B[K,N] ; 64x64 tile, 4x4/thread ----------------
__global__ __launch_bounds__(256) void k_gemm(const float* Ain, const float* Bm_in,
                                              int dst, int M, int K, int N) {
    const float* A  = xsel(Ain);
    const float* Bm = Bm_in ? Bm_in : g_wv;
    float* C = dst ? g_v : g_u;

    int n0 = blockIdx.x * 64, m0 = blockIdx.y * 64;
    int tid = threadIdx.x;
    int tx = tid & 15, ty = tid >> 4;

    __shared__ float As[64][17];
    __shared__ float Bs[16][64];

    float acc[4][4];
    #pragma unroll
    for (int i = 0; i < 4; i++)
        #pragma unroll
        for (int j = 0; j < 4; j++) acc[i][j] = 0.f;

    for (int k0 = 0; k0 < K; k0 += 16) {
        #pragma unroll
        for (int i = 0; i < 4; i++) {
            int s = tid + i * 256; int r = s >> 4, c = s & 15;
            As[r][c] = (k0 + c < K) ? A[(size_t)(m0 + r) * K + k0 + c] : 0.f;
        }
        #pragma unroll
        for (int i = 0; i < 4; i++) {
            int s = tid + i * 256; int r = s >> 6, c = s & 63;
            Bs[r][c] = (k0 + r < K) ? Bm[(size_t)(k0 + r) * N + n0 + c] : 0.f;
        }
        __syncthreads();
        #pragma unroll
        for (int kk = 0; kk < 16; kk++) {
            float ra[4];
            #pragma unroll
            for (int i = 0; i < 4; i++) ra[i] = As[ty * 4 + i][kk];
            float4 b4 = *reinterpret_cast<const float4*>(&Bs[kk][tx * 4]);
            float rb[4] = { b4.x, b4.y, b4.z, b4.w };
            #pragma unroll
            for (int i = 0; i < 4; i++)
                #pragma unroll
                for (int j = 0; j < 4; j++) acc[i][j] += ra[i] * rb[j];
        }
        __syncthreads();
    }
    #pragma unroll
    for (int i = 0; i < 4; i++)
        #pragma unroll
        for (int j = 0; j < 4; j++)
            C[(size_t)(m0 + ty * 4 + i) * N + n0 + tx * 4 + j] = acc[i][j];
}

// ---------------- zero the per-channel accumulators ----------------
__global__ void k_zero() {
    int i = blockIdx.x * 256 + threadIdx.x;
    if (i < 1024) g_sum[i] = 0.f;
    else if (i < 2048) g_sum2[i - 1024] = 0.f;
}

// ---------------- gather over k : max + channel stats ----------------
#define PTS 16
__global__ __launch_bounds__(256) void k_edge(int cout) {
    int tid = threadIdx.x;
    int base = blockIdx.x * PTS;                 // first point index (16 per block, same batch)
    int b = base / NP;
    float sume[4]  = {0.f, 0.f, 0.f, 0.f};
    float sume2[4] = {0.f, 0.f, 0.f, 0.f};

    for (int p = 0; p < PTS; p++) {
        int bn = base + p;
        const int* idxp = g_idx + (size_t)bn * KNN;
        int jj[KNN];
        #pragma unroll
        for (int k = 0; k < KNN; k++) jj[k] = __ldg(&idxp[k]);

        for (int co = 0; co < 4 && co * 256 + tid < cout; co++) {
            int o = co * 256 + tid;
            float uv = g_u[(size_t)bn * cout + o];
            float mv = -FLT_MAX;
            float se = 0.f, se2 = 0.f;
            #pragma unroll
            for (int k = 0; k < KNN; k++) {
                float vv = g_v[((size_t)b * NP + jj[k]) * cout + o];
                mv = fmaxf(mv, vv);
                float e = uv + vv;
                se  += e;
                se2 += e * e;
            }
            sume[co]  += se;
            sume2[co] += se2;
            g_u[(size_t)bn * cout + o] = uv + mv;   // in-place: now holds max_k e
        }
    }
    for (int co = 0; co < 4 && co * 256 + tid < cout; co++) {
        atomicAdd(&g_sum[co * 256 + tid],  sume[co]);
        atomicAdd(&g_sum2[co * 256 + tid], sume2[co]);
    }
}

// ---------------- BN finalize (bias cancels; scale = rsqrt(var)*gamma) ----------------
__global__ void k_fin(const float* gam, const float* bet, int cout) {
    int o = blockIdx.x * 256 + threadIdx.x;
    if (o >= cout) return;
    float inv = 1.f / (float)EDGES;
    float mean = g_sum[o] * inv;
    float var  = g_sum2[o] * inv - mean * mean;
    float s = rsqrtf(var + 1e-5f) * gam[o];
    g_scale[o] = s;
    g_shift[o] = bet[o] - mean * s;
}

// ---------------- apply BN + relu, write next features ----------------
__global__ void k_apply(int cout) {
    int i = blockIdx.x * 256 + threadIdx.x;      // < BB*NP*cout (grid sized exactly)
    int o = i & (cout - 1);                      // cout is a power of two
    float v = g_u[i] * g_scale[o] + g_shift[o];
    g_x[i] = fmaxf(v, 0.f);
}

// ---------------- global max pool over N ----------------
__global__ void k_pool() {
    int b = blockIdx.y;
    int o = blockIdx.x * 256 + threadIdx.x;
    float m = -FLT_MAX;
    for (int n = 0; n < NP; n++)
        m = fmaxf(m, g_x[((size_t)b * NP + n) * 1024 + o]);
    g_pool[b * 1024 + o] = m;
}

// ---------------- FC layers ----------------
__global__ void k_fc1(const float* W, const float* bias) {
    int b = blockIdx.x, t = threadIdx.x;
    float a0 = bias[t], a1 = bias[t + 256];
    const float* y = g_pool + b * 1024;
    #pragma unroll 4
    for (int c = 0; c < 1024; c++) {
        float xv = y[c];
        a0 += xv * W[c * 512 + t];
        a1 += xv * W[c * 512 + t + 256];
    }
    g_fc1[b * 512 + t]       = fmaxf(a0, 0.f);
    g_fc1[b * 512 + t + 256] = fmaxf(a1, 0.f);
}

__global__ void k_fc2(const float* W, const float* bias, float* out) {
    int b = blockIdx.x, o = threadIdx.x;
    if (o >= 40) return;
    float a = bias[o];
    const float* y = g_fc1 + b * 512;
    #pragma unroll 4
    for (int c = 0; c < 512; c++) a += y[c] * W[c * 40 + o];
    out[b * 40 + o] = a;
}

// ---------------- launcher ----------------
extern "C" void kernel_launch(void* const* d_in, const int* in_sizes, int n_in,
                              void* d_out, int out_size) {
    (void)in_sizes; (void)n_in; (void)out_size;
    const float* pos = (const float*)d_in[0];
    const float* W[4]  = {(const float*)d_in[1],  (const float*)d_in[5],
                          (const float*)d_in[9],  (const float*)d_in[13]};
    const float* gm[4] = {(const float*)d_in[3],  (const float*)d_in[7],
                          (const float*)d_in[11], (const float*)d_in[15]};
    const float* bt[4] = {(const float*)d_in[4],  (const float*)d_in[8],
                          (const float*)d_in[12], (const float*)d_in[16]};
    const float* Wc1 = (const float*)d_in[17];
    const float* bc1 = (const float*)d_in[18];
    const float* Wc2 = (const float*)d_in[19];
    const float* bc2 = (const float*)d_in[20];

    const int cin[4]  = {3, 64, 64, 128};
    const int cout[4] = {64, 64, 128, 1024};
    const int M = BB * NP;

    for (int l = 0; l < 4; l++) {
        const float* xin = (l == 0) ? pos : nullptr;  // nullptr -> g_x inside kernels
        k_sqnorm<<<M / 256, 256>>>(xin, cin[l]);
        k_gram<<<dim3(16, 16, BB), 256>>>(xin, cin[l]);
        k_knn<<<(M * 32) / 256, 256>>>();
        k_wv<<<(cin[l] * cout[l] + 255) / 256, 256>>>(W[l], cin[l], cout[l]);
        k_gemm<<<dim3(cout[l] / 64, M / 64), 256>>>(xin, W[l],   0, M, cin[l], cout[l]);
        k_gemm<<<dim3(cout[l] / 64, M / 64), 256>>>(xin, nullptr, 1, M, cin[l], cout[l]);
        k_zero<<<8, 256>>>();
        k_edge<<<M / PTS, 256>>>(cout[l]);
        k_fin<<<4, 256>>>(gm[l], bt[l], cout[l]);
        k_apply<<<(M * cout[l]) / 256, 256>>>(cout[l]);
    }
    k_pool<<<dim3(4, BB), 256>>>();
    k_fc1<<<BB, 256>>>(Wc1, bc1);
    k_fc2<<<BB, 64>>>(Wc2, bc2, (float*)d_out);
}

// round 2
// speedup vs baseline: 1.1114x; 1.1114x over previous
#include <cuda_runtime.h>
#include <float.h>
#include <math.h>

#define BB 16
#define NP 1024
#define KNN 20
#define EDGES (BB*NP*KNN)
#define TM 128
#define TN 128
#define TK 8

// ---------------- scratch ----------------
__device__ float g_gram[BB*NP*NP];        // pairwise distances
__device__ float g_uv[BB*NP*2048];        // [u | v] concatenated, stride 2*cout
__device__ float g_u[BB*NP*1024];         // max-edge value per point
__device__ float g_x[BB*NP*1024];         // current layer features
__device__ float g_wv[128*2048];          // [Wa | Wb-Wa]
__device__ float g_sq[BB*NP];
__device__ int   g_idx[BB*NP*KNN];
__device__ float g_sum[1024];
__device__ float g_sum2[1024];
__device__ float g_scale[1024];
__device__ float g_shift[1024];
__device__ float g_pool[BB*1024];
__device__ float g_fc1[BB*512];

__device__ __forceinline__ const float* xsel(const float* xin) { return xin ? xin : g_x; }

// ---------------- squared norms ----------------
__global__ void k_sqnorm(const float* xin, int C) {
    const float* x = xsel(xin);
    int i = blockIdx.x * blockDim.x + threadIdx.x;
    if (i >= BB * NP) return;
    const float* r = x + (size_t)i * C;
    float s = 0.f;
    for (int c = 0; c < C; c++) { float v = r[c]; s += v * v; }
    g_sq[i] = s;
}

// ---------------- Gram/distance: 128x128 tile, 8x8/thread, double buffered ----------------
__global__ __launch_bounds__(256, 2) void k_gram128(const float* xin, int C) {
    const float* x = xsel(xin);
    int b = blockIdx.z;
    const float* xb = x + (size_t)b * NP * C;
    int m0 = blockIdx.y * TM, n0 = blockIdx.x * TN;
    int tid = threadIdx.x;
    int tx = tid & 15, ty = tid >> 4;

    __shared__ float As[2][TK][TM + 4];
    __shared__ float Bs[2][TK][TN + 4];

    float acc[8][8];
    #pragma unroll
    for (int i = 0; i < 8; i++)
        #pragma unroll
        for (int j = 0; j < 8; j++) acc[i][j] = 0.f;

    int KT = (C + TK - 1) / TK;

    // prologue
    #pragma unroll
    for (int i = 0; i < 4; i++) {
        int e = i * 256 + tid; int m = e >> 3, k = e & 7;
        As[0][k][m] = (k < C) ? xb[(size_t)(m0 + m) * C + k] : 0.f;
        Bs[0][k][m] = (k < C) ? xb[(size_t)(n0 + m) * C + k] : 0.f;
    }
    __syncthreads();

    int cur = 0;
    for (int kt = 0; kt < KT; kt++) {
        int k0n = (kt + 1) * TK;
        bool has_next = (kt + 1 < KT);
        float a_st[4], b_st[4];
        if (has_next) {
            #pragma unroll
            for (int i = 0; i < 4; i++) {
                int e = i * 256 + tid; int m = e >> 3, k = e & 7;
                a_st[i] = (k0n + k < C) ? xb[(size_t)(m0 + m) * C + k0n + k] : 0.f;
                b_st[i] = (k0n + k < C) ? xb[(size_t)(n0 + m) * C + k0n + k] : 0.f;
            }
        }
        #pragma unroll
        for (int kk = 0; kk < TK; kk++) {
            float ra[8], rb[8];
            #pragma unroll
            for (int i = 0; i < 8; i++) ra[i] = As[cur][kk][ty * 8 + i];
            #pragma unroll
            for (int j = 0; j < 8; j++) rb[j] = Bs[cur][kk][tx * 8 + j];
            #pragma unroll
            for (int i = 0; i < 8; i++)
                #pragma unroll
                for (int j = 0; j < 8; j++) acc[i][j] += ra[i] * rb[j];
        }
        if (has_next) {
            #pragma unroll
            for (int i = 0; i < 4; i++) {
                int e = i * 256 + tid; int m = e >> 3, k = e & 7;
                As[cur ^ 1][k][m] = a_st[i];
                Bs[cur ^ 1][k][m] = b_st[i];
            }
            __syncthreads();
            cur ^= 1;
        }
    }

    float sqn[8];
    #pragma unroll
    for (int j = 0; j < 8; j++) sqn[j] = g_sq[b * NP + n0 + tx * 8 + j];
    #pragma unroll
    for (int i = 0; i < 8; i++) {
        int row = m0 + ty * 8 + i;
        float sqr = g_sq[b * NP + row];
        float dv[8];
        #pragma unroll
        for (int j = 0; j < 8; j++) {
            int col = n0 + tx * 8 + j;
            float d = sqr + sqn[j] - 2.f * acc[i][j];
            if (row == col) d += 1e10f;
            dv[j] = d;
        }
        float* dst = &g_gram[((size_t)b * NP + row) * NP + n0 + tx * 8];
        *(float4*)dst       = make_float4(dv[0], dv[1], dv[2], dv[3]);
        *(float4*)(dst + 4) = make_float4(dv[4], dv[5], dv[6], dv[7]);
    }
}

// ---------------- kNN top-20: one warp per row ----------------
__global__ void k_knn() {
    int gt = blockIdx.x * blockDim.x + threadIdx.x;
    int w = gt >> 5;
    int lane = gt & 31;
    if (w >= BB * NP) return;
    const float* row = g_gram + (size_t)w * NP;
    float val[32];
    #pragma unroll
    for (int j = 0; j < 32; j++) val[j] = row[lane + j * 32];
    unsigned used = 0u;
    for (int t = 0; t < KNN; t++) {
        float bv = FLT_MAX; int bi = 1 << 30;
        #pragma unroll
        for (int j = 0; j < 32; j++) {
            int m = lane + j * 32;
            bool free_ = !((used >> j) & 1u);
            if (free_ && (val[j] < bv || (val[j] == bv && m < bi))) { bv = val[j]; bi = m; }
        }
        #pragma unroll
        for (int off = 16; off; off >>= 1) {
            float ov = __shfl_down_sync(0xffffffffu, bv, off);
            int   oi = __shfl_down_sync(0xffffffffu, bi, off);
            if (ov < bv || (ov == bv && oi < bi)) { bv = ov; bi = oi; }
        }
        int wi = __shfl_sync(0xffffffffu, bi, 0);
        if ((wi & 31) == lane) used |= (1u << (wi >> 5));
        if (lane == 0) g_idx[w * KNN + t] = wi;
    }
}

// ---------------- build [Wa | Wb-Wa] ----------------
__global__ void k_wcat(const float* W, int cin, int cout) {
    int i = blockIdx.x * 256 + threadIdx.x;
    int tot = cin * cout;
    if (i >= tot) return;
    int k = i / cout, o = i % cout;
    float wa = W[i];
    g_wv[(size_t)k * 2 * cout + o]        = wa;
    g_wv[(size_t)k * 2 * cout + cout + o] = W[tot + i] - wa;
}

// ---------------- fused GEMM: g_uv[M, 2*cout] = A[M,K] @ g_wv[K, 2*cout] ----------------
__global__ __launch_bounds__(256, 2) void k_gemm128(const float* Ain, int M, int K, int N) {
    const float* A = xsel(Ain);
    const float* Bm = g_wv;
    float* C = g_uv;

    __shared__ float As[2][TK][TM + 4];
    __shared__ float Bs[2][TK][TN];

    int tid = threadIdx.x;
    int m0 = blockIdx.y * TM, n0 = blockIdx.x * TN;
    int tx = tid & 15, ty = tid >> 4;

    float acc[8][8];
    #pragma unroll
    for (int i = 0; i < 8; i++)
        #pragma unroll
        for (int j = 0; j < 8; j++) acc[i][j] = 0.f;

    int KT = (K + TK - 1) / TK;
    int bk = tid >> 5, bn = (tid & 31) * 4;

    // prologue
    #pragma unroll
    for (int i = 0; i < 4; i++) {
        int e = i * 256 + tid; int m = e >> 3, k = e & 7;
        As[0][k][m] = (k < K) ? A[(size_t)(m0 + m) * K + k] : 0.f;
    }
    {
        float4 v = (bk < K) ? *(const float4*)&Bm[(size_t)bk * N + n0 + bn]
                            : make_float4(0.f, 0.f, 0.f, 0.f);
        *(float4*)&Bs[0][bk][bn] = v;
    }
    __syncthreads();

    int cur = 0;
    for (int kt = 0; kt < KT; kt++) {
        int k0n = (kt + 1) * TK;
        bool has_next = (kt + 1 < KT);
        float a_st[4]; float4 b_st;
        if (has_next) {
            #pragma unroll
            for (int i = 0; i < 4; i++) {
                int e = i * 256 + tid; int m = e >> 3, k = e & 7;
                a_st[i] = (k0n + k < K) ? A[(size_t)(m0 + m) * K + k0n + k] : 0.f;
            }
            b_st = (k0n + bk < K) ? *(const float4*)&Bm[(size_t)(k0n + bk) * N + n0 + bn]
                                  : make_float4(0.f, 0.f, 0.f, 0.f);
        }
        #pragma unroll
        for (int kk = 0; kk < TK; kk++) {
            float ra[8], rb[8];
            #pragma unroll
            for (int i = 0; i < 8; i++) ra[i] = As[cur][kk][ty * 8 + i];
            #pragma unroll
            for (int j = 0; j < 8; j++) rb[j] = Bs[cur][kk][tx * 8 + j];
            #pragma unroll
            for (int i = 0; i < 8; i++)
                #pragma unroll
                for (int j = 0; j < 8; j++) acc[i][j] += ra[i] * rb[j];
        }
        if (has_next) {
            #pragma unroll
            for (int i = 0; i < 4; i++) {
                int e = i * 256 + tid;
                As[cur ^ 1][e & 7][e >> 3] = a_st[i];
            }
            *(float4*)&Bs[cur ^ 1][bk][bn] = b_st;
            __syncthreads();
            cur ^= 1;
        }
    }

    #pragma unroll
    for (int i = 0; i < 8; i++) {
        int m = m0 + ty * 8 + i;
        float* dst = &C[(size_t)m * N + n0 + tx * 8];
        *(float4*)dst       = make_float4(acc[i][0], acc[i][1], acc[i][2], acc[i][3]);
        *(float4*)(dst + 4) = make_float4(acc[i][4], acc[i][5], acc[i][6], acc[i][7]);
    }
}

// ---------------- zero accumulators ----------------
__global__ void k_zero() {
    int i = blockIdx.x * 256 + threadIdx.x;
    if (i < 1024) g_sum[i] = 0.f;
    else if (i < 2048) g_sum2[i - 1024] = 0.f;
}

// ---------------- gather over k : max + channel stats ----------------
#define PTS 16
__global__ __launch_bounds__(256) void k_edge(int cout) {
    int tid = threadIdx.x;
    int base = blockIdx.x * PTS;
    int b = base / NP;
    int C2 = 2 * cout;
    float sume[4]  = {0.f, 0.f, 0.f, 0.f};
    float sume2[4] = {0.f, 0.f, 0.f, 0.f};

    for (int p = 0; p < PTS; p++) {
        int bn = base + p;
        const int* idxp = g_idx + (size_t)bn * KNN;
        int jj[KNN];
        #pragma unroll
        for (int k = 0; k < KNN; k++) jj[k] = __ldg(&idxp[k]);

        for (int co = 0; co < 4 && co * 256 + tid < cout; co++) {
            int o = co * 256 + tid;
            float uv = g_uv[(size_t)bn * C2 + o];
            float mv = -FLT_MAX;
            float se = 0.f, se2 = 0.f;
            #pragma unroll
            for (int k = 0; k < KNN; k++) {
                float vv = g_uv[((size_t)b * NP + jj[k]) * C2 + cout + o];
                mv = fmaxf(mv, vv);
                float e = uv + vv;
                se  += e;
                se2 += e * e;
            }
            sume[co]  += se;
            sume2[co] += se2;
            g_u[(size_t)bn * cout + o] = uv + mv;
        }
    }
    for (int co = 0; co < 4 && co * 256 + tid < cout; co++) {
        atomicAdd(&g_sum[co * 256 + tid],  sume[co]);
        atomicAdd(&g_sum2[co * 256 + tid], sume2[co]);
    }
}

// ---------------- BN finalize ----------------
__global__ void k_fin(const float* gam, const float* bet, int cout) {
    int o = blockIdx.x * 256 + threadIdx.x;
    if (o >= cout) return;
    float inv = 1.f / (float)EDGES;
    float mean = g_sum[o] * inv;
    float var  = g_sum2[o] * inv - mean * mean;
    float s = rsqrtf(var + 1e-5f) * gam[o];
    g_scale[o] = s;
    g_shift[o] = bet[o] - mean * s;
}

// ---------------- apply BN + relu ----------------
__global__ void k_apply(int cout) {
    int i = blockIdx.x * 256 + threadIdx.x;
    int o = i & (cout - 1);
    float v = g_u[i] * g_scale[o] + g_shift[o];
    g_x[i] = fmaxf(v, 0.f);
}

// ---------------- pool init + atomic-max pool (values >= 0 post relu) ----------------
__global__ void k_pzero() {
    int i = blockIdx.x * 256 + threadIdx.x;
    if (i < BB * 1024) g_pool[i] = 0.f;
}

__global__ void k_pool() {
    int b = blockIdx.z;
    int o = blockIdx.x * 256 + threadIdx.x;
    int n0 = blockIdx.y * 128;
    float m = 0.f;
    for (int n = n0; n < n0 + 128; n++)
        m = fmaxf(m, g_x[((size_t)b * NP + n) * 1024 + o]);
    atomicMax((int*)&g_pool[b * 1024 + o], __float_as_int(m));
}

// ---------------- FC layers ----------------
__global__ void k_fc1(const float* W, const float* bias) {
    int b = blockIdx.x, t = threadIdx.x;
    float a0 = bias[t], a1 = bias[t + 256];
    const float* y = g_pool + b * 1024;
    #pragma unroll 4
    for (int c = 0; c < 1024; c++) {
        float xv = y[c];
        a0 += xv * W[c * 512 + t];
        a1 += xv * W[c * 512 + t + 256];
    }
    g_fc1[b * 512 + t]       = fmaxf(a0, 0.f);
    g_fc1[b * 512 + t + 256] = fmaxf(a1, 0.f);
}

__global__ void k_fc2(const float* W, const float* bias, float* out) {
    int b = blockIdx.x, o = threadIdx.x;
    if (o >= 40) return;
    float a = bias[o];
    const float* y = g_fc1 + b * 512;
    #pragma unroll 4
    for (int c = 0; c < 512; c++) a += y[c] * W[c * 40 + o];
    out[b * 40 + o] = a;
}

// ---------------- launcher ----------------
extern "C" void kernel_launch(void* const* d_in, const int* in_sizes, int n_in,
                              void* d_out, int out_size) {
    (void)in_sizes; (void)n_in; (void)out_size;
    const float* pos = (const float*)d_in[0];
    const float* W[4]  = {(const float*)d_in[1],  (const float*)d_in[5],
                          (const float*)d_in[9],  (const float*)d_in[13]};
    const float* gm[4] = {(const float*)d_in[3],  (const float*)d_in[7],
                          (const float*)d_in[11], (const float*)d_in[15]};
    const float* bt[4] = {(const float*)d_in[4],  (const float*)d_in[8],
                          (const float*)d_in[12], (const float*)d_in[16]};
    const float* Wc1 = (const float*)d_in[17];
    const float* bc1 = (const float*)d_in[18];
    const float* Wc2 = (const float*)d_in[19];
    const float* bc2 = (const float*)d_in[20];

    const int cin[4]  = {3, 64, 64, 128};
    const int cout[4] = {64, 64, 128, 1024};
    const int M = BB * NP;

    for (int l = 0; l < 4; l++) {
        const float* xin = (l == 0) ? pos : nullptr;
        k_sqnorm<<<M / 256, 256>>>(xin, cin[l]);
        k_gram128<<<dim3(NP / TN, NP / TM, BB), 256>>>(xin, cin[l]);
        k_knn<<<(M * 32) / 256, 256>>>();
        k_wcat<<<(cin[l] * cout[l] + 255) / 256, 256>>>(W[l], cin[l], cout[l]);
        k_gemm128<<<dim3(2 * cout[l] / TN, M / TM), 256>>>(xin, M, cin[l], 2 * cout[l]);
        k_zero<<<8, 256>>>();
        k_edge<<<M / PTS, 256>>>(cout[l]);
        k_fin<<<4, 256>>>(gm[l], bt[l], cout[l]);
        k_apply<<<(M * cout[l]) / 256, 256>>>(cout[l]);
    }
    k_pzero<<<64, 256>>>();
    k_pool<<<dim3(4, 8, BB), 256>>>();
    k_fc1<<<BB, 256>>>(Wc1, bc1);
    k_fc2<<<BB, 64>>>(Wc2, bc2, (float*)d_out);
}

// round 3
// speedup vs baseline: 1.2841x; 1.1553x over previous
#include <cuda_runtime.h>
#include <float.h>
#include <math.h>

#define BB 16
#define NP 1024
#define KNN 20
#define EDGES (BB*NP*KNN)
#define TM 128
#define TN 128
#define TK 8

// ---------------- scratch ----------------
__device__ float g_gram[BB*NP*NP];
__device__ float g_uv[BB*NP*2048];        // [u | v], stride 2*cout
__device__ float g_u[BB*NP*1024];         // u + max_k v  (per point)
__device__ float g_x[BB*NP*1024];         // layer features (layers 1-3)
__device__ float g_sq[BB*NP];
__device__ int   g_idx[BB*NP*KNN];
__device__ float g_sum[1024];
__device__ float g_sum2[1024];
__device__ float g_scale[1024];
__device__ float g_shift[1024];
__device__ float g_pool[BB*1024];
__device__ float g_fc1[BB*512];

__device__ __forceinline__ const float* xsel(const float* xin) { return xin ? xin : g_x; }

// ---------------- squared norms ----------------
__global__ void k_sqnorm(const float* xin, int C) {
    const float* x = xsel(xin);
    int i = blockIdx.x * blockDim.x + threadIdx.x;
    if (i >= BB * NP) return;
    const float* r = x + (size_t)i * C;
    float s = 0.f;
    for (int c = 0; c < C; c++) { float v = r[c]; s += v * v; }
    g_sq[i] = s;
}

// ---------------- Gram: symmetric, 36 upper-tri tile pairs, 8x8/thread ----------------
__global__ __launch_bounds__(256, 2) void k_gram128(const float* xin, int C) {
    const float* x = xsel(xin);
    int b = blockIdx.z;
    const float* xb = x + (size_t)b * NP * C;

    // map blockIdx.x (0..35) -> (mt, nt) with mt <= nt, 8 tiles per dim
    int p = blockIdx.x, mt = 0;
    while (p >= 8 - mt) { p -= 8 - mt; mt++; }
    int nt = mt + p;

    int m0 = mt * TM, n0 = nt * TN;
    int tid = threadIdx.x;
    int tx = tid & 15, ty = tid >> 4;

    __shared__ float As[2][TK][TM + 4];
    __shared__ float Bs[2][TK][TN + 4];

    float acc[8][8];
    #pragma unroll
    for (int i = 0; i < 8; i++)
        #pragma unroll
        for (int j = 0; j < 8; j++) acc[i][j] = 0.f;

    int KT = (C + TK - 1) / TK;

    #pragma unroll
    for (int i = 0; i < 4; i++) {
        int e = i * 256 + tid; int m = e >> 3, k = e & 7;
        As[0][k][m] = (k < C) ? xb[(size_t)(m0 + m) * C + k] : 0.f;
        Bs[0][k][m] = (k < C) ? xb[(size_t)(n0 + m) * C + k] : 0.f;
    }
    __syncthreads();

    int cur = 0;
    for (int kt = 0; kt < KT; kt++) {
        int k0n = (kt + 1) * TK;
        bool has_next = (kt + 1 < KT);
        float a_st[4], b_st[4];
        if (has_next) {
            #pragma unroll
            for (int i = 0; i < 4; i++) {
                int e = i * 256 + tid; int m = e >> 3, k = e & 7;
                a_st[i] = (k0n + k < C) ? xb[(size_t)(m0 + m) * C + k0n + k] : 0.f;
                b_st[i] = (k0n + k < C) ? xb[(size_t)(n0 + m) * C + k0n + k] : 0.f;
            }
        }
        #pragma unroll
        for (int kk = 0; kk < TK; kk++) {
            float ra[8], rb[8];
            #pragma unroll
            for (int i = 0; i < 8; i++) ra[i] = As[cur][kk][ty * 8 + i];
            #pragma unroll
            for (int j = 0; j < 8; j++) rb[j] = Bs[cur][kk][tx * 8 + j];
            #pragma unroll
            for (int i = 0; i < 8; i++)
                #pragma unroll
                for (int j = 0; j < 8; j++) acc[i][j] += ra[i] * rb[j];
        }
        if (has_next) {
            #pragma unroll
            for (int i = 0; i < 4; i++) {
                int e = i * 256 + tid; int m = e >> 3, k = e & 7;
                As[cur ^ 1][k][m] = a_st[i];
                Bs[cur ^ 1][k][m] = b_st[i];
            }
            __syncthreads();
            cur ^= 1;
        }
    }

    // convert acc -> distances in-place
    float sqr[8], sqn[8];
    #pragma unroll
    for (int i = 0; i < 8; i++) sqr[i] = g_sq[b * NP + m0 + ty * 8 + i];
    #pragma unroll
    for (int j = 0; j < 8; j++) sqn[j] = g_sq[b * NP + n0 + tx * 8 + j];
    #pragma unroll
    for (int i = 0; i < 8; i++)
        #pragma unroll
        for (int j = 0; j < 8; j++) {
            float d = sqr[i] + sqn[j] - 2.f * acc[i][j];
            if (mt == nt && (m0 + ty * 8 + i) == (n0 + tx * 8 + j)) d += 1e10f;
            acc[i][j] = d;
        }

    // normal tile write
    #pragma unroll
    for (int i = 0; i < 8; i++) {
        float* dst = &g_gram[((size_t)b * NP + m0 + ty * 8 + i) * NP + n0 + tx * 8];
        *(float4*)dst       = make_float4(acc[i][0], acc[i][1], acc[i][2], acc[i][3]);
        *(float4*)(dst + 4) = make_float4(acc[i][4], acc[i][5], acc[i][6], acc[i][7]);
    }
    // transposed tile write (off-diagonal only)
    if (mt != nt) {
        #pragma unroll
        for (int j = 0; j < 8; j++) {
            float* dst = &g_gram[((size_t)b * NP + n0 + tx * 8 + j) * NP + m0 + ty * 8];
            *(float4*)dst       = make_float4(acc[0][j], acc[1][j], acc[2][j], acc[3][j]);
            *(float4*)(dst + 4) = make_float4(acc[4][j], acc[5][j], acc[6][j], acc[7][j]);
        }
    }
}

// ---------------- kNN top-20: REDUX-based, one warp per row ----------------
__global__ void k_knn() {
    int gt = blockIdx.x * blockDim.x + threadIdx.x;
    int w = gt >> 5;
    int lane = gt & 31;
    if (w >= BB * NP) return;
    const float* row = g_gram + (size_t)w * NP;

    unsigned key[32];
    #pragma unroll
    for (int j = 0; j < 32; j++) {
        unsigned u = __float_as_uint(row[lane + j * 32]);
        key[j] = (u & 0x80000000u) ? ~u : (u | 0x80000000u);  // order-preserving
    }
    unsigned used = 0u;

    // initial local min (strict <, ascending j => smallest idx on ties)
    unsigned lmin = 0xFFFFFFFFu; int lj = 0;
    #pragma unroll
    for (int j = 0; j < 32; j++)
        if (key[j] < lmin) { lmin = key[j]; lj = j; }

    for (int t = 0; t < KNN; t++) {
        unsigned wmin = __reduce_min_sync(0xFFFFFFFFu, lmin);
        unsigned myidx = (lmin == wmin) ? (unsigned)(lane + lj * 32) : 0xFFFFFFFFu;
        unsigned widx = __reduce_min_sync(0xFFFFFFFFu, myidx);
        if (lane == 0) g_idx[w * KNN + t] = (int)widx;
        if ((widx & 31u) == (unsigned)lane && (widx >> 5) == (unsigned)lj) {
            used |= 1u << lj;
            lmin = 0xFFFFFFFFu; lj = 0;
            #pragma unroll
            for (int j = 0; j < 32; j++)
                if (!((used >> j) & 1u) && key[j] < lmin) { lmin = key[j]; lj = j; }
        }
    }
}

// ---------------- fused GEMM: g_uv[M, 2*cout] = A[M,K] @ [Wa | Wb-Wa] ----------------
__global__ __launch_bounds__(256, 2) void k_gemm128(const float* Ain, const float* W,
                                                    int M, int K, int cout) {
    const float* A = xsel(Ain);
    int N = 2 * cout;
    float* C = g_uv;

    __shared__ float As[2][TK][TM + 4];
    __shared__ float Bs[2][TK][TN];

    int tid = threadIdx.x;
    int m0 = blockIdx.y * TM, n0 = blockIdx.x * TN;
    int tx = tid & 15, ty = tid >> 4;

    float acc[8][8];
    #pragma unroll
    for (int i = 0; i < 8; i++)
        #pragma unroll
        for (int j = 0; j < 8; j++) acc[i][j] = 0.f;

    int KT = (K + TK - 1) / TK;
    int bk = tid >> 5, bn = (tid & 31) * 4;

    // B loader: on-the-fly [Wa | Wb-Wa]
    auto loadB = [&](int k) -> float4 {
        if (k >= K) return make_float4(0.f, 0.f, 0.f, 0.f);
        int col = n0 + bn;
        if (col < cout) {
            return *(const float4*)&W[(size_t)k * cout + col];
        } else {
            int c2 = col - cout;
            float4 wa = *(const float4*)&W[(size_t)k * cout + c2];
            float4 wb = *(const float4*)&W[(size_t)(K + k) * cout + c2];
            return make_float4(wb.x - wa.x, wb.y - wa.y, wb.z - wa.z, wb.w - wa.w);
        }
    };

    #pragma unroll
    for (int i = 0; i < 4; i++) {
        int e = i * 256 + tid; int m = e >> 3, k = e & 7;
        As[0][k][m] = (k < K) ? A[(size_t)(m0 + m) * K + k] : 0.f;
    }
    *(float4*)&Bs[0][bk][bn] = loadB(bk);
    __syncthreads();

    int cur = 0;
    for (int kt = 0; kt < KT; kt++) {
        int k0n = (kt + 1) * TK;
        bool has_next = (kt + 1 < KT);
        float a_st[4]; float4 b_st;
        if (has_next) {
            #pragma unroll
            for (int i = 0; i < 4; i++) {
                int e = i * 256 + tid; int m = e >> 3, k = e & 7;
                a_st[i] = (k0n + k < K) ? A[(size_t)(m0 + m) * K + k0n + k] : 0.f;
            }
            b_st = loadB(k0n + bk);
        }
        #pragma unroll
        for (int kk = 0; kk < TK; kk++) {
            float ra[8], rb[8];
            #pragma unroll
            for (int i = 0; i < 8; i++) ra[i] = As[cur][kk][ty * 8 + i];
            #pragma unroll
            for (int j = 0; j < 8; j++) rb[j] = Bs[cur][kk][tx * 8 + j];
            #pragma unroll
            for (int i = 0; i < 8; i++)
                #pragma unroll
                for (int j = 0; j < 8; j++) acc[i][j] += ra[i] * rb[j];
        }
        if (has_next) {
            #pragma unroll
            for (int i = 0; i < 4; i++) {
                int e = i * 256 + tid;
                As[cur ^ 1][e & 7][e >> 3] = a_st[i];
            }
            *(float4*)&Bs[cur ^ 1][bk][bn] = b_st;
            __syncthreads();
            cur ^= 1;
        }
    }

    #pragma unroll
    for (int i = 0; i < 8; i++) {
        int m = m0 + ty * 8 + i;
        float* dst = &C[(size_t)m * N + n0 + tx * 8];
        *(float4*)dst       = make_float4(acc[i][0], acc[i][1], acc[i][2], acc[i][3]);
        *(float4*)(dst + 4) = make_float4(acc[i][4], acc[i][5], acc[i][6], acc[i][7]);
    }
}

// ---------------- zero accumulators ----------------
__global__ void k_zero() {
    int i = blockIdx.x * 256 + threadIdx.x;
    if (i < 1024) g_sum[i] = 0.f;
    else if (i < 2048) g_sum2[i - 1024] = 0.f;
}

// ---------------- gather over k : max + channel stats ----------------
#define PTS 16
__global__ __launch_bounds__(256) void k_edge(int cout) {
    int tid = threadIdx.x;
    int base = blockIdx.x * PTS;
    int b = base / NP;
    int C2 = 2 * cout;
    float sume[4]  = {0.f, 0.f, 0.f, 0.f};
    float sume2[4] = {0.f, 0.f, 0.f, 0.f};

    for (int p = 0; p < PTS; p++) {
        int bn = base + p;
        const int* idxp = g_idx + (size_t)bn * KNN;
        int jj[KNN];
        #pragma unroll
        for (int k = 0; k < KNN; k++) jj[k] = __ldg(&idxp[k]);

        for (int co = 0; co < 4 && co * 256 + tid < cout; co++) {
            int o = co * 256 + tid;
            float uv = g_uv[(size_t)bn * C2 + o];
            float mv = -FLT_MAX;
            float se = 0.f, se2 = 0.f;
            #pragma unroll
            for (int k = 0; k < KNN; k++) {
                float vv = g_uv[((size_t)b * NP + jj[k]) * C2 + cout + o];
                mv = fmaxf(mv, vv);
                float e = uv + vv;
                se  += e;
                se2 += e * e;
            }
            sume[co]  += se;
            sume2[co] += se2;
            g_u[(size_t)bn * cout + o] = uv + mv;
        }
    }
    for (int co = 0; co < 4 && co * 256 + tid < cout; co++) {
        atomicAdd(&g_sum[co * 256 + tid],  sume[co]);
        atomicAdd(&g_sum2[co * 256 + tid], sume2[co]);
    }
}

// ---------------- BN finalize ----------------
__global__ void k_fin(const float* gam, const float* bet, int cout) {
    int o = blockIdx.x * 256 + threadIdx.x;
    if (o >= cout) return;
    float inv = 1.f / (float)EDGES;
    float mean = g_sum[o] * inv;
    float var  = g_sum2[o] * inv - mean * mean;
    float s = rsqrtf(var + 1e-5f) * gam[o];
    g_scale[o] = s;
    g_shift[o] = bet[o] - mean * s;
}

// ---------------- apply BN + relu (layers 1-3) ----------------
__global__ void k_apply(int cout) {
    int i = blockIdx.x * 256 + threadIdx.x;
    int o = i & (cout - 1);
    float v = g_u[i] * g_scale[o] + g_shift[o];
    g_x[i] = fmaxf(v, 0.f);
}

// ---------------- layer-4 fused BN + relu + global max pool ----------------
__global__ void k_pzero() {
    int i = blockIdx.x * 256 + threadIdx.x;
    if (i < BB * 1024) g_pool[i] = 0.f;
}

__global__ void k_pool4() {
    int b = blockIdx.z;
    int o = blockIdx.x * 256 + threadIdx.x;
    int n0 = blockIdx.y * 256;
    float s = g_scale[o], t = g_shift[o];
    float m = -FLT_MAX;
    #pragma unroll 4
    for (int n = n0; n < n0 + 256; n++)
        m = fmaxf(m, g_u[((size_t)b * NP + n) * 1024 + o]);
    float v = fmaxf(s * m + t, 0.f);   // s > 0 (gamma=1), monotone -> commutes with max
    atomicMax((int*)&g_pool[b * 1024 + o], __float_as_int(v));
}

// ---------------- FC layers ----------------
__global__ void k_fc1(const float* W, const float* bias) {
    int b = blockIdx.x, t = threadIdx.x;
    float a0 = bias[t], a1 = bias[t + 256];
    const float* y = g_pool + b * 1024;
    #pragma unroll 4
    for (int c = 0; c < 1024; c++) {
        float xv = y[c];
        a0 += xv * W[c * 512 + t];
        a1 += xv * W[c * 512 + t + 256];
    }
    g_fc1[b * 512 + t]       = fmaxf(a0, 0.f);
    g_fc1[b * 512 + t + 256] = fmaxf(a1, 0.f);
}

__global__ void k_fc2(const float* W, const float* bias, float* out) {
    int b = blockIdx.x, o = threadIdx.x;
    if (o >= 40) return;
    float a = bias[o];
    const float* y = g_fc1 + b * 512;
    #pragma unroll 4
    for (int c = 0; c < 512; c++) a += y[c] * W[c * 40 + o];
    out[b * 40 + o] = a;
}

// ---------------- launcher ----------------
extern "C" void kernel_launch(void* const* d_in, const int* in_sizes, int n_in,
                              void* d_out, int out_size) {
    (void)in_sizes; (void)n_in; (void)out_size;
    const float* pos = (const float*)d_in[0];
    const float* W[4]  = {(const float*)d_in[1],  (const float*)d_in[5],
                          (const float*)d_in[9],  (const float*)d_in[13]};
    const float* gm[4] = {(const float*)d_in[3],  (const float*)d_in[7],
                          (const float*)d_in[11], (const float*)d_in[15]};
    const float* bt[4] = {(const float*)d_in[4],  (const float*)d_in[8],
                          (const float*)d_in[12], (const float*)d_in[16]};
    const float* Wc1 = (const float*)d_in[17];
    const float* bc1 = (const float*)d_in[18];
    const float* Wc2 = (const float*)d_in[19];
    const float* bc2 = (const float*)d_in[20];

    const int cin[4]  = {3, 64, 64, 128};
    const int cout[4] = {64, 64, 128, 1024};
    const int M = BB * NP;

    k_pzero<<<64, 256>>>();
    for (int l = 0; l < 4; l++) {
        const float* xin = (l == 0) ? pos : nullptr;
        k_sqnorm<<<M / 256, 256>>>(xin, cin[l]);
        k_gram128<<<dim3(36, 1, BB), 256>>>(xin, cin[l]);
        k_knn<<<(M * 32) / 256, 256>>>();
        k_gemm128<<<dim3(2 * cout[l] / TN, M / TM), 256>>>(xin, W[l], M, cin[l], cout[l]);
        k_zero<<<8, 256>>>();
        k_edge<<<M / PTS, 256>>>(cout[l]);
        k_fin<<<4, 256>>>(gm[l], bt[l], cout[l]);
        if (l < 3) k_apply<<<(M * cout[l]) / 256, 256>>>(cout[l]);
        else       k_pool4<<<dim3(4, 4, BB), 256>>>();
    }
    k_fc1<<<BB, 256>>>(Wc1, bc1);
    k_fc2<<<BB, 64>>>(Wc2, bc2, (float*)d_out);
}

// round 4
// speedup vs baseline: 1.5064x; 1.1731x over previous
#include <cuda_runtime.h>
#include <float.h>
#include <math.h>

#define BB 16
#define NP 1024
#define KNN 20
#define EDGES (BB*NP*KNN)
#define TM 128
#define TN 128
#define TK 8

// ---------------- scratch ----------------
__device__ float g_gram[BB*NP*NP];
__device__ float g_uv[BB*NP*2048];        // [u | v], stride 2*cout
__device__ float g_u[BB*NP*1024];         // u + max_k v  (per point)
__device__ float g_x[BB*NP*1024];         // layer features (layers 1-3)
__device__ float g_sq[BB*NP];
__device__ int   g_idx[BB*NP*KNN];
__device__ float g_sum[1024];
__device__ float g_sum2[1024];
__device__ float g_scale[1024];
__device__ float g_shift[1024];
__device__ float g_pool[BB*1024];
__device__ float g_fc1[BB*512];

__device__ __forceinline__ const float* xsel(const float* xin) { return xin ? xin : g_x; }

// ---------------- squared norms ----------------
__global__ void k_sqnorm(const float* xin, int C) {
    const float* x = xsel(xin);
    int i = blockIdx.x * blockDim.x + threadIdx.x;
    if (i >= BB * NP) return;
    const float* r = x + (size_t)i * C;
    float s = 0.f;
    for (int c = 0; c < C; c++) { float v = r[c]; s += v * v; }
    g_sq[i] = s;
}

// ---------------- Gram: symmetric, 36 upper-tri tile pairs, 8x8/thread ----------------
__global__ __launch_bounds__(256, 2) void k_gram128(const float* xin, int C) {
    const float* x = xsel(xin);
    int b = blockIdx.z;
    const float* xb = x + (size_t)b * NP * C;

    int p = blockIdx.x, mt = 0;
    while (p >= 8 - mt) { p -= 8 - mt; mt++; }
    int nt = mt + p;

    int m0 = mt * TM, n0 = nt * TN;
    int tid = threadIdx.x;
    int tx = tid & 15, ty = tid >> 4;

    __shared__ float As[2][TK][TM + 4];
    __shared__ float Bs[2][TK][TN + 4];

    float acc[8][8];
    #pragma unroll
    for (int i = 0; i < 8; i++)
        #pragma unroll
        for (int j = 0; j < 8; j++) acc[i][j] = 0.f;

    int KT = (C + TK - 1) / TK;

    #pragma unroll
    for (int i = 0; i < 4; i++) {
        int e = i * 256 + tid; int m = e >> 3, k = e & 7;
        As[0][k][m] = (k < C) ? xb[(size_t)(m0 + m) * C + k] : 0.f;
        Bs[0][k][m] = (k < C) ? xb[(size_t)(n0 + m) * C + k] : 0.f;
    }
    __syncthreads();

    int cur = 0;
    for (int kt = 0; kt < KT; kt++) {
        int k0n = (kt + 1) * TK;
        bool has_next = (kt + 1 < KT);
        float a_st[4], b_st[4];
        if (has_next) {
            #pragma unroll
            for (int i = 0; i < 4; i++) {
                int e = i * 256 + tid; int m = e >> 3, k = e & 7;
                a_st[i] = (k0n + k < C) ? xb[(size_t)(m0 + m) * C + k0n + k] : 0.f;
                b_st[i] = (k0n + k < C) ? xb[(size_t)(n0 + m) * C + k0n + k] : 0.f;
            }
        }
        #pragma unroll
        for (int kk = 0; kk < TK; kk++) {
            float ra[8], rb[8];
            #pragma unroll
            for (int i = 0; i < 8; i++) ra[i] = As[cur][kk][ty * 8 + i];
            #pragma unroll
            for (int j = 0; j < 8; j++) rb[j] = Bs[cur][kk][tx * 8 + j];
            #pragma unroll
            for (int i = 0; i < 8; i++)
                #pragma unroll
                for (int j = 0; j < 8; j++) acc[i][j] += ra[i] * rb[j];
        }
        if (has_next) {
            #pragma unroll
            for (int i = 0; i < 4; i++) {
                int e = i * 256 + tid; int m = e >> 3, k = e & 7;
                As[cur ^ 1][k][m] = a_st[i];
                Bs[cur ^ 1][k][m] = b_st[i];
            }
            __syncthreads();
            cur ^= 1;
        }
    }

    float sqr[8], sqn[8];
    #pragma unroll
    for (int i = 0; i < 8; i++) sqr[i] = g_sq[b * NP + m0 + ty * 8 + i];
    #pragma unroll
    for (int j = 0; j < 8; j++) sqn[j] = g_sq[b * NP + n0 + tx * 8 + j];
    #pragma unroll
    for (int i = 0; i < 8; i++)
        #pragma unroll
        for (int j = 0; j < 8; j++) {
            float d = sqr[i] + sqn[j] - 2.f * acc[i][j];
            if (mt == nt && (m0 + ty * 8 + i) == (n0 + tx * 8 + j)) d += 1e10f;
            acc[i][j] = d;
        }

    #pragma unroll
    for (int i = 0; i < 8; i++) {
        float* dst = &g_gram[((size_t)b * NP + m0 + ty * 8 + i) * NP + n0 + tx * 8];
        *(float4*)dst       = make_float4(acc[i][0], acc[i][1], acc[i][2], acc[i][3]);
        *(float4*)(dst + 4) = make_float4(acc[i][4], acc[i][5], acc[i][6], acc[i][7]);
    }
    if (mt != nt) {
        #pragma unroll
        for (int j = 0; j < 8; j++) {
            float* dst = &g_gram[((size_t)b * NP + n0 + tx * 8 + j) * NP + m0 + ty * 8];
            *(float4*)dst       = make_float4(acc[0][j], acc[1][j], acc[2][j], acc[3][j]);
            *(float4*)(dst + 4) = make_float4(acc[4][j], acc[5][j], acc[6][j], acc[7][j]);
        }
    }
}

// ---------------- kNN top-20: per-lane top-2 cache + rare rescan ----------------
__global__ void k_knn() {
    int gt = blockIdx.x * blockDim.x + threadIdx.x;
    int w = gt >> 5;
    int lane = gt & 31;
    if (w >= BB * NP) return;
    const float* row = g_gram + (size_t)w * NP;

    unsigned key[32];
    #pragma unroll
    for (int j = 0; j < 32; j++) {
        unsigned u = __float_as_uint(row[lane + j * 32]);
        key[j] = (u & 0x80000000u) ? ~u : (u | 0x80000000u);  // order-preserving map
    }

    // per-lane two smallest (strict < keeps smallest j among equal keys)
    unsigned k1 = 0xFFFFFFFFu, k2 = 0xFFFFFFFFu;
    int j1 = 0, j2 = 0;
    #pragma unroll
    for (int j = 0; j < 32; j++) {
        unsigned kk = key[j];
        if (kk < k1)      { k2 = k1; j2 = j1; k1 = kk; j1 = j; }
        else if (kk < k2) { k2 = kk; j2 = j; }
    }

    unsigned used = 0u;
    unsigned head = k1; int hj = j1;
    int stage = 0;

    for (int t = 0; t < KNN; t++) {
        unsigned wmin = __reduce_min_sync(0xFFFFFFFFu, head);
        unsigned my = (head == wmin) ? (unsigned)(lane + hj * 32) : 0xFFFFFFFFu;
        unsigned widx = __reduce_min_sync(0xFFFFFFFFu, my);   // tie-break: lowest global index
        if (lane == 0) g_idx[w * KNN + t] = (int)widx;
        if (my == widx) {                                     // my head consumed
            used |= 1u << hj;
            stage++;
            if (stage == 1) { head = k2; hj = j2; }
            else {                                            // rare: lane supplies 3rd+
                head = 0xFFFFFFFFu; hj = 0;
                #pragma unroll
                for (int j = 0; j < 32; j++)
                    if (!((used >> j) & 1u) && key[j] < head) { head = key[j]; hj = j; }
            }
        }
    }
}

// ---------------- fused GEMM: g_uv[M, 2*cout] = A[M,K] @ [Wa | Wb-Wa] ----------------
__global__ __launch_bounds__(256, 2) void k_gemm128(const float* Ain, const float* W,
                                                    int M, int K, int cout) {
    const float* A = xsel(Ain);
    int N = 2 * cout;
    float* C = g_uv;

    __shared__ float As[2][TK][TM + 4];
    __shared__ float Bs[2][TK][TN];

    int tid = threadIdx.x;
    int m0 = blockIdx.y * TM, n0 = blockIdx.x * TN;
    int tx = tid & 15, ty = tid >> 4;

    float acc[8][8];
    #pragma unroll
    for (int i = 0; i < 8; i++)
        #pragma unroll
        for (int j = 0; j < 8; j++) acc[i][j] = 0.f;

    int KT = (K + TK - 1) / TK;
    int bk = tid >> 5, bn = (tid & 31) * 4;

    auto loadB = [&](int k) -> float4 {
        if (k >= K) return make_float4(0.f, 0.f, 0.f, 0.f);
        int col = n0 + bn;
        if (col < cout) {
            return *(const float4*)&W[(size_t)k * cout + col];
        } else {
            int c2 = col - cout;
            float4 wa = *(const float4*)&W[(size_t)k * cout + c2];
            float4 wb = *(const float4*)&W[(size_t)(K + k) * cout + c2];
            return make_float4(wb.x - wa.x, wb.y - wa.y, wb.z - wa.z, wb.w - wa.w);
        }
    };

    #pragma unroll
    for (int i = 0; i < 4; i++) {
        int e = i * 256 + tid; int m = e >> 3, k = e & 7;
        As[0][k][m] = (k < K) ? A[(size_t)(m0 + m) * K + k] : 0.f;
    }
    *(float4*)&Bs[0][bk][bn] = loadB(bk);
    __syncthreads();

    int cur = 0;
    for (int kt = 0; kt < KT; kt++) {
        int k0n = (kt + 1) * TK;
        bool has_next = (kt + 1 < KT);
        float a_st[4]; float4 b_st;
        if (has_next) {
            #pragma unroll
            for (int i = 0; i < 4; i++) {
                int e = i * 256 + tid; int m = e >> 3, k = e & 7;
                a_st[i] = (k0n + k < K) ? A[(size_t)(m0 + m) * K + k0n + k] : 0.f;
            }
            b_st = loadB(k0n + bk);
        }
        #pragma unroll
        for (int kk = 0; kk < TK; kk++) {
            float ra[8], rb[8];
            #pragma unroll
            for (int i = 0; i < 8; i++) ra[i] = As[cur][kk][ty * 8 + i];
            #pragma unroll
            for (int j = 0; j < 8; j++) rb[j] = Bs[cur][kk][tx * 8 + j];
            #pragma unroll
            for (int i = 0; i < 8; i++)
                #pragma unroll
                for (int j = 0; j < 8; j++) acc[i][j] += ra[i] * rb[j];
        }
        if (has_next) {
            #pragma unroll
            for (int i = 0; i < 4; i++) {
                int e = i * 256 + tid;
                As[cur ^ 1][e & 7][e >> 3] = a_st[i];
            }
            *(float4*)&Bs[cur ^ 1][bk][bn] = b_st;
            __syncthreads();
            cur ^= 1;
        }
    }

    #pragma unroll
    for (int i = 0; i < 8; i++) {
        int m = m0 + ty * 8 + i;
        float* dst = &C[(size_t)m * N + n0 + tx * 8];
        *(float4*)dst       = make_float4(acc[i][0], acc[i][1], acc[i][2], acc[i][3]);
        *(float4*)(dst + 4) = make_float4(acc[i][4], acc[i][5], acc[i][6], acc[i][7]);
    }
}

// ---------------- zero accumulators ----------------
__global__ void k_zero() {
    int i = blockIdx.x * 256 + threadIdx.x;
    if (i < 1024) g_sum[i] = 0.f;
    else if (i < 2048) g_sum2[i - 1024] = 0.f;
}

// ---------------- gather over k : max + channel stats ----------------
#define PTS 16
__global__ __launch_bounds__(256) void k_edge(int cout) {
    int tid = threadIdx.x;
    int base = blockIdx.x * PTS;
    int b = base / NP;
    int C2 = 2 * cout;
    float sume[4]  = {0.f, 0.f, 0.f, 0.f};
    float sume2[4] = {0.f, 0.f, 0.f, 0.f};

    for (int p = 0; p < PTS; p++) {
        int bn = base + p;
        const int* idxp = g_idx + (size_t)bn * KNN;
        int jj[KNN];
        #pragma unroll
        for (int k = 0; k < KNN; k++) jj[k] = __ldg(&idxp[k]);

        for (int co = 0; co < 4 && co * 256 + tid < cout; co++) {
            int o = co * 256 + tid;
            float uv = g_uv[(size_t)bn * C2 + o];
            float mv = -FLT_MAX;
            float se = 0.f, se2 = 0.f;
            #pragma unroll
            for (int k = 0; k < KNN; k++) {
                float vv = g_uv[((size_t)b * NP + jj[k]) * C2 + cout + o];
                mv = fmaxf(mv, vv);
                float e = uv + vv;
                se  += e;
                se2 += e * e;
            }
            sume[co]  += se;
            sume2[co] += se2;
            g_u[(size_t)bn * cout + o] = uv + mv;
        }
    }
    for (int co = 0; co < 4 && co * 256 + tid < cout; co++) {
        atomicAdd(&g_sum[co * 256 + tid],  sume[co]);
        atomicAdd(&g_sum2[co * 256 + tid], sume2[co]);
    }
}

// ---------------- BN finalize ----------------
__global__ void k_fin(const float* gam, const float* bet, int cout) {
    int o = blockIdx.x * 256 + threadIdx.x;
    if (o >= cout) return;
    float inv = 1.f / (float)EDGES;
    float mean = g_sum[o] * inv;
    float var  = g_sum2[o] * inv - mean * mean;
    float s = rsqrtf(var + 1e-5f) * gam[o];
    g_scale[o] = s;
    g_shift[o] = bet[o] - mean * s;
}

// ---------------- apply BN + relu (layers 1-3) ----------------
__global__ void k_apply(int cout) {
    int i = blockIdx.x * 256 + threadIdx.x;
    int o = i & (cout - 1);
    float v = g_u[i] * g_scale[o] + g_shift[o];
    g_x[i] = fmaxf(v, 0.f);
}

// ---------------- layer-4 fused BN + relu + global max pool ----------------
__global__ void k_pzero() {
    int i = blockIdx.x * 256 + threadIdx.x;
    if (i < BB * 1024) g_pool[i] = 0.f;
}

__global__ void k_pool4() {
    int b = blockIdx.z;
    int o = blockIdx.x * 256 + threadIdx.x;
    int n0 = blockIdx.y * 256;
    float s = g_scale[o], t = g_shift[o];
    float m = -FLT_MAX;
    #pragma unroll 4
    for (int n = n0; n < n0 + 256; n++)
        m = fmaxf(m, g_u[((size_t)b * NP + n) * 1024 + o]);
    float v = fmaxf(s * m + t, 0.f);
    atomicMax((int*)&g_pool[b * 1024 + o], __float_as_int(v));
}

// ---------------- FC layers ----------------
__global__ void k_fc1(const float* W, const float* bias) {
    int b = blockIdx.x, t = threadIdx.x;
    float a0 = bias[t], a1 = bias[t + 256];
    const float* y = g_pool + b * 1024;
    #pragma unroll 4
    for (int c = 0; c < 1024; c++) {
        float xv = y[c];
        a0 += xv * W[c * 512 + t];
        a1 += xv * W[c * 512 + t + 256];
    }
    g_fc1[b * 512 + t]       = fmaxf(a0, 0.f);
    g_fc1[b * 512 + t + 256] = fmaxf(a1, 0.f);
}

__global__ void k_fc2(const float* W, const float* bias, float* out) {
    int b = blockIdx.x, o = threadIdx.x;
    if (o >= 40) return;
    float a = bias[o];
    const float* y = g_fc1 + b * 512;
    #pragma unroll 4
    for (int c = 0; c < 512; c++) a += y[c] * W[c * 40 + o];
    out[b * 40 + o] = a;
}

// ---------------- launcher ----------------
extern "C" void kernel_launch(void* const* d_in, const int* in_sizes, int n_in,
                              void* d_out, int out_size) {
    (void)in_sizes; (void)n_in; (void)out_size;
    const float* pos = (const float*)d_in[0];
    const float* W[4]  = {(const float*)d_in[1],  (const float*)d_in[5],
                          (const float*)d_in[9],  (const float*)d_in[13]};
    const float* gm[4] = {(const float*)d_in[3],  (const float*)d_in[7],
                          (const float*)d_in[11], (const float*)d_in[15]};
    const float* bt[4] = {(const float*)d_in[4],  (const float*)d_in[8],
                          (const float*)d_in[12], (const float*)d_in[16]};
    const float* Wc1 = (const float*)d_in[17];
    const float* bc1 = (const float*)d_in[18];
    const float* Wc2 = (const float*)d_in[19];
    const float* bc2 = (const float*)d_in[20];

    const int cin[4]  = {3, 64, 64, 128};
    const int cout[4] = {64, 64, 128, 1024};
    const int M = BB * NP;

    k_pzero<<<64, 256>>>();
    for (int l = 0; l < 4; l++) {
        const float* xin = (l == 0) ? pos : nullptr;
        k_sqnorm<<<M / 256, 256>>>(xin, cin[l]);
        k_gram128<<<dim3(36, 1, BB), 256>>>(xin, cin[l]);
        k_knn<<<(M * 32) / 256, 256>>>();
        k_gemm128<<<dim3(2 * cout[l] / TN, M / TM), 256>>>(xin, W[l], M, cin[l], cout[l]);
        k_zero<<<8, 256>>>();
        k_edge<<<M / PTS, 256>>>(cout[l]);
        k_fin<<<4, 256>>>(gm[l], bt[l], cout[l]);
        if (l < 3) k_apply<<<(M * cout[l]) / 256, 256>>>(cout[l]);
        else       k_pool4<<<dim3(4, 4, BB), 256>>>();
    }
    k_fc1<<<BB, 256>>>(Wc1, bc1);
    k_fc2<<<BB, 64>>>(Wc2, bc2, (float*)d_out);
}

// round 6
// speedup vs baseline: 1.5065x; 1.0001x over previous
#include <cuda_runtime.h>
#include <float.h>
#include <math.h>

#define BB 16
#define NP 1024
#define KNN 20
#define EDGES (BB*NP*KNN)
#define TM 128
#define TN 128
#define TK 8

// ---------------- scratch ----------------
__device__ float g_gram[BB*NP*NP];
__device__ float g_uv[BB*NP*2048];        // [u | v], stride 2*cout
__device__ float g_u[BB*NP*1024];         // u + max_k v  (per point)
__device__ float g_x[BB*NP*1024];         // layer features (layers 1-3)
__device__ float g_sq[BB*NP];
__device__ int   g_idx[BB*NP*KNN];
__device__ float g_sum[1024];
__device__ float g_sum2[1024];
__device__ float g_scale[1024];
__device__ float g_shift[1024];
__device__ float g_pool[BB*1024];
__device__ float g_fc1[BB*512];

__device__ __forceinline__ const float* xsel(const float* xin) { return xin ? xin : g_x; }

__device__ __forceinline__ float f2tf32f(float f) {
    unsigned r;
    asm("cvt.rna.tf32.f32 %0, %1;" : "=r"(r) : "f"(f));
    return __uint_as_float(r);
}

// ---------------- squared norms ----------------
__global__ void k_sqnorm(const float* xin, int C) {
    const float* x = xsel(xin);
    int i = blockIdx.x * blockDim.x + threadIdx.x;
    if (i >= BB * NP) return;
    const float* r = x + (size_t)i * C;
    float s = 0.f;
    for (int c = 0; c < C; c++) { float v = r[c]; s += v * v; }
    g_sq[i] = s;
}

// ---------------- Gram: symmetric, 36 upper-tri tile pairs, 8x8/thread (fp32) ----------------
__global__ __launch_bounds__(256, 2) void k_gram128(const float* xin, int C) {
    const float* x = xsel(xin);
    int b = blockIdx.z;
    const float* xb = x + (size_t)b * NP * C;

    int p = blockIdx.x, mt = 0;
    while (p >= 8 - mt) { p -= 8 - mt; mt++; }
    int nt = mt + p;

    int m0 = mt * TM, n0 = nt * TN;
    int tid = threadIdx.x;
    int tx = tid & 15, ty = tid >> 4;

    __shared__ float As[2][TK][TM + 4];
    __shared__ float Bs[2][TK][TN + 4];

    float acc[8][8];
    #pragma unroll
    for (int i = 0; i < 8; i++)
        #pragma unroll
        for (int j = 0; j < 8; j++) acc[i][j] = 0.f;

    int KT = (C + TK - 1) / TK;

    #pragma unroll
    for (int i = 0; i < 4; i++) {
        int e = i * 256 + tid; int m = e >> 3, k = e & 7;
        As[0][k][m] = (k < C) ? xb[(size_t)(m0 + m) * C + k] : 0.f;
        Bs[0][k][m] = (k < C) ? xb[(size_t)(n0 + m) * C + k] : 0.f;
    }
    __syncthreads();

    int cur = 0;
    for (int kt = 0; kt < KT; kt++) {
        int k0n = (kt + 1) * TK;
        bool has_next = (kt + 1 < KT);
        float a_st[4], b_st[4];
        if (has_next) {
            #pragma unroll
            for (int i = 0; i < 4; i++) {
                int e = i * 256 + tid; int m = e >> 3, k = e & 7;
                a_st[i] = (k0n + k < C) ? xb[(size_t)(m0 + m) * C + k0n + k] : 0.f;
                b_st[i] = (k0n + k < C) ? xb[(size_t)(n0 + m) * C + k0n + k] : 0.f;
            }
        }
        #pragma unroll
        for (int kk = 0; kk < TK; kk++) {
            float ra[8], rb[8];
            #pragma unroll
            for (int i = 0; i < 8; i++) ra[i] = As[cur][kk][ty * 8 + i];
            #pragma unroll
            for (int j = 0; j < 8; j++) rb[j] = Bs[cur][kk][tx * 8 + j];
            #pragma unroll
            for (int i = 0; i < 8; i++)
                #pragma unroll
                for (int j = 0; j < 8; j++) acc[i][j] += ra[i] * rb[j];
        }
        if (has_next) {
            #pragma unroll
            for (int i = 0; i < 4; i++) {
                int e = i * 256 + tid; int m = e >> 3, k = e & 7;
                As[cur ^ 1][k][m] = a_st[i];
                Bs[cur ^ 1][k][m] = b_st[i];
            }
            __syncthreads();
            cur ^= 1;
        }
    }

    float sqr[8], sqn[8];
    #pragma unroll
    for (int i = 0; i < 8; i++) sqr[i] = g_sq[b * NP + m0 + ty * 8 + i];
    #pragma unroll
    for (int j = 0; j < 8; j++) sqn[j] = g_sq[b * NP + n0 + tx * 8 + j];
    #pragma unroll
    for (int i = 0; i < 8; i++)
        #pragma unroll
        for (int j = 0; j < 8; j++) {
            float d = sqr[i] + sqn[j] - 2.f * acc[i][j];
            if (mt == nt && (m0 + ty * 8 + i) == (n0 + tx * 8 + j)) d += 1e10f;
            acc[i][j] = d;
        }

    #pragma unroll
    for (int i = 0; i < 8; i++) {
        float* dst = &g_gram[((size_t)b * NP + m0 + ty * 8 + i) * NP + n0 + tx * 8];
        *(float4*)dst       = make_float4(acc[i][0], acc[i][1], acc[i][2], acc[i][3]);
        *(float4*)(dst + 4) = make_float4(acc[i][4], acc[i][5], acc[i][6], acc[i][7]);
    }
    if (mt != nt) {
        #pragma unroll
        for (int j = 0; j < 8; j++) {
            float* dst = &g_gram[((size_t)b * NP + n0 + tx * 8 + j) * NP + m0 + ty * 8];
            *(float4*)dst       = make_float4(acc[0][j], acc[1][j], acc[2][j], acc[3][j]);
            *(float4*)(dst + 4) = make_float4(acc[4][j], acc[5][j], acc[6][j], acc[7][j]);
        }
    }
}

// ---------------- kNN top-20: per-lane top-2 cache + rare rescan ----------------
__global__ void k_knn() {
    int gt = blockIdx.x * blockDim.x + threadIdx.x;
    int w = gt >> 5;
    int lane = gt & 31;
    if (w >= BB * NP) return;
    const float* row = g_gram + (size_t)w * NP;

    unsigned key[32];
    #pragma unroll
    for (int j = 0; j < 32; j++) {
        unsigned u = __float_as_uint(row[lane + j * 32]);
        key[j] = (u & 0x80000000u) ? ~u : (u | 0x80000000u);
    }

    unsigned k1 = 0xFFFFFFFFu, k2 = 0xFFFFFFFFu;
    int j1 = 0, j2 = 0;
    #pragma unroll
    for (int j = 0; j < 32; j++) {
        unsigned kk = key[j];
        if (kk < k1)      { k2 = k1; j2 = j1; k1 = kk; j1 = j; }
        else if (kk < k2) { k2 = kk; j2 = j; }
    }

    unsigned used = 0u;
    unsigned head = k1; int hj = j1;
    int stage = 0;

    for (int t = 0; t < KNN; t++) {
        unsigned wmin = __reduce_min_sync(0xFFFFFFFFu, head);
        unsigned my = (head == wmin) ? (unsigned)(lane + hj * 32) : 0xFFFFFFFFu;
        unsigned widx = __reduce_min_sync(0xFFFFFFFFu, my);
        if (lane == 0) g_idx[w * KNN + t] = (int)widx;
        if (my == widx) {
            used |= 1u << hj;
            stage++;
            if (stage == 1) { head = k2; hj = j2; }
            else {
                head = 0xFFFFFFFFu; hj = 0;
                #pragma unroll
                for (int j = 0; j < 32; j++)
                    if (!((used >> j) & 1u) && key[j] < head) { head = key[j]; hj = j; }
            }
        }
    }
}

// ---------------- 3xTF32 tensor-core GEMM: g_uv[M, 2*cout] = A @ [Wa | Wb-Wa] ----------------
// 128x128x16 block tile, 8 warps (2m x 4n), warp tile 64x32, m16n8k8 mma.
// Operands split hi/lo (tf32 each); accumulate hi*hi + hi*lo + lo*hi in fp32.
#define GBK 16
__global__ __launch_bounds__(256) void k_gemm_tc(const float* Ain, const float* W,
                                                 int M, int K, int cout) {
    const float* A = xsel(Ain);
    int N = 2 * cout;

    __shared__ float AsH[128][20], AsL[128][20];   // [m][k], stride 20
    __shared__ float BsH[GBK][136], BsL[GBK][136]; // [k][n], stride 136

    int tid = threadIdx.x;
    int m0 = blockIdx.y * 128, n0 = blockIdx.x * 128;
    int wid = tid >> 5, lane = tid & 31;
    int wm = wid >> 2, wn = wid & 3;
    int gid = lane >> 2, tig = lane & 3;

    float acc[4][4][4];
    #pragma unroll
    for (int mi = 0; mi < 4; mi++)
        #pragma unroll
        for (int ni = 0; ni < 4; ni++)
            #pragma unroll
            for (int r = 0; r < 4; r++) acc[mi][ni][r] = 0.f;

    // raw B value: 4 cols at (k, n0+nq*4) from [Wa | Wb-Wa]
    auto loadB4 = [&](int k, int nq) -> float4 {
        if (k >= K) return make_float4(0.f, 0.f, 0.f, 0.f);
        int col = n0 + nq * 4;
        if (col < cout) {
            return *(const float4*)&W[(size_t)k * cout + col];
        } else {
            int c2 = col - cout;
            float4 wa = *(const float4*)&W[(size_t)k * cout + c2];
            float4 wb = *(const float4*)&W[(size_t)(K + k) * cout + c2];
            return make_float4(wb.x - wa.x, wb.y - wa.y, wb.z - wa.z, wb.w - wa.w);
        }
    };

    int KT = (K + GBK - 1) / GBK;

    for (int kt = 0; kt < KT; kt++) {
        int k0 = kt * GBK;
        if (kt > 0) __syncthreads();
        // load A tile, split hi/lo
        #pragma unroll
        for (int i = 0; i < 8; i++) {
            int e = i * 256 + tid;                  // 2048 scalars
            int m = e >> 4, k = e & 15;
            float v = (k0 + k < K) ? A[(size_t)(m0 + m) * K + k0 + k] : 0.f;
            float h = f2tf32f(v);
            AsH[m][k] = h;
            AsL[m][k] = f2tf32f(v - h);
        }
        // load B tile, split hi/lo
        #pragma unroll
        for (int i = 0; i < 2; i++) {
            int e = i * 256 + tid;                  // 512 float4s
            int k = e >> 5, nq = e & 31;
            float4 v = loadB4(k0 + k, nq);
            float h0 = f2tf32f(v.x), h1 = f2tf32f(v.y), h2 = f2tf32f(v.z), h3 = f2tf32f(v.w);
            BsH[k][nq * 4 + 0] = h0;  BsL[k][nq * 4 + 0] = f2tf32f(v.x - h0);
            BsH[k][nq * 4 + 1] = h1;  BsL[k][nq * 4 + 1] = f2tf32f(v.y - h1);
            BsH[k][nq * 4 + 2] = h2;  BsL[k][nq * 4 + 2] = f2tf32f(v.z - h2);
            BsH[k][nq * 4 + 3] = h3;  BsL[k][nq * 4 + 3] = f2tf32f(v.w - h3);
        }
        __syncthreads();

        #pragma unroll
        for (int kk = 0; kk < GBK; kk += 8) {
            unsigned bfH[4][2], bfL[4][2];
            #pragma unroll
            for (int ni = 0; ni < 4; ni++) {
                int cb = wn * 32 + ni * 8;
                bfH[ni][0] = __float_as_uint(BsH[kk + tig][cb + gid]);
                bfH[ni][1] = __float_as_uint(BsH[kk + tig + 4][cb + gid]);
                bfL[ni][0] = __float_as_uint(BsL[kk + tig][cb + gid]);
                bfL[ni][1] = __float_as_uint(BsL[kk + tig + 4][cb + gid]);
            }
            #pragma unroll
            for (int mi = 0; mi < 4; mi++) {
                int rb = wm * 64 + mi * 16;
                unsigned aH[4], aL[4];
                aH[0] = __float_as_uint(AsH[rb + gid][kk + tig]);
                aH[1] = __float_as_uint(AsH[rb + gid + 8][kk + tig]);
                aH[2] = __float_as_uint(AsH[rb + gid][kk + tig + 4]);
                aH[3] = __float_as_uint(AsH[rb + gid + 8][kk + tig + 4]);
                aL[0] = __float_as_uint(AsL[rb + gid][kk + tig]);
                aL[1] = __float_as_uint(AsL[rb + gid + 8][kk + tig]);
                aL[2] = __float_as_uint(AsL[rb + gid][kk + tig + 4]);
                aL[3] = __float_as_uint(AsL[rb + gid + 8][kk + tig + 4]);
                #pragma unroll
                for (int ni = 0; ni < 4; ni++) {
                    #define MMA(AF0,AF1,AF2,AF3,BF0,BF1)                                         \
                        asm volatile(                                                            \
                            "mma.sync.aligned.m16n8k8.row.col.f32.tf32.tf32.f32 "               \
                            "{%0,%1,%2,%3}, {%4,%5,%6,%7}, {%8,%9}, {%0,%1,%2,%3};"             \
                            : "+f"(acc[mi][ni][0]), "+f"(acc[mi][ni][1]),                        \
                              "+f"(acc[mi][ni][2]), "+f"(acc[mi][ni][3])                         \
                            : "r"(AF0), "r"(AF1), "r"(AF2), "r"(AF3), "r"(BF0), "r"(BF1))
                    MMA(aH[0], aH[1], aH[2], aH[3], bfL[ni][0], bfL[ni][1]);  // hi*lo
                    MMA(aL[0], aL[1], aL[2], aL[3], bfH[ni][0], bfH[ni][1]);  // lo*hi
                    MMA(aH[0], aH[1], aH[2], aH[3], bfH[ni][0], bfH[ni][1]);  // hi*hi
                    #undef MMA
                }
            }
        }
    }

    // epilogue
    #pragma unroll
    for (int mi = 0; mi < 4; mi++) {
        int row0 = m0 + wm * 64 + mi * 16 + gid;
        #pragma unroll
        for (int ni = 0; ni < 4; ni++) {
            int col = n0 + wn * 32 + ni * 8 + tig * 2;
            *(float2*)&g_uv[(size_t)row0 * N + col]       = make_float2(acc[mi][ni][0], acc[mi][ni][1]);
            *(float2*)&g_uv[(size_t)(row0 + 8) * N + col] = make_float2(acc[mi][ni][2], acc[mi][ni][3]);
        }
    }
}

// ---------------- zero accumulators ----------------
__global__ void k_zero() {
    int i = blockIdx.x * 256 + threadIdx.x;
    if (i < 1024) g_sum[i] = 0.f;
    else if (i < 2048) g_sum2[i - 1024] = 0.f;
}

// ---------------- gather over k : max + channel stats ----------------
#define PTS 16
__global__ __launch_bounds__(256) void k_edge(int cout) {
    int tid = threadIdx.x;
    int base = blockIdx.x * PTS;
    int b = base / NP;
    int C2 = 2 * cout;
    float sume[4]  = {0.f, 0.f, 0.f, 0.f};
    float sume2[4] = {0.f, 0.f, 0.f, 0.f};

    for (int p = 0; p < PTS; p++) {
        int bn = base + p;
        const int* idxp = g_idx + (size_t)bn * KNN;
        int jj[KNN];
        #pragma unroll
        for (int k = 0; k < KNN; k++) jj[k] = __ldg(&idxp[k]);

        for (int co = 0; co < 4 && co * 256 + tid < cout; co++) {
            int o = co * 256 + tid;
            float uv = g_uv[(size_t)bn * C2 + o];
            float mv = -FLT_MAX;
            float se = 0.f, se2 = 0.f;
            #pragma unroll
            for (int k = 0; k < KNN; k++) {
                float vv = g_uv[((size_t)b * NP + jj[k]) * C2 + cout + o];
                mv = fmaxf(mv, vv);
                float e = uv + vv;
                se  += e;
                se2 += e * e;
            }
            sume[co]  += se;
            sume2[co] += se2;
            g_u[(size_t)bn * cout + o] = uv + mv;
        }
    }
    for (int co = 0; co < 4 && co * 256 + tid < cout; co++) {
        atomicAdd(&g_sum[co * 256 + tid],  sume[co]);
        atomicAdd(&g_sum2[co * 256 + tid], sume2[co]);
    }
}

// ---------------- BN finalize ----------------
__global__ void k_fin(const float* gam, const float* bet, int cout) {
    int o = blockIdx.x * 256 + threadIdx.x;
    if (o >= cout) return;
    float inv = 1.f / (float)EDGES;
    float mean = g_sum[o] * inv;
    float var  = g_sum2[o] * inv - mean * mean;
    float s = rsqrtf(var + 1e-5f) * gam[o];
    g_scale[o] = s;
    g_shift[o] = bet[o] - mean * s;
}

// ---------------- apply BN + relu (layers 1-3) ----------------
__global__ void k_apply(int cout) {
    int i = blockIdx.x * 256 + threadIdx.x;
    int o = i & (cout - 1);
    float v = g_u[i] * g_scale[o] + g_shift[o];
    g_x[i] = fmaxf(v, 0.f);
}

// ---------------- layer-4 fused BN + relu + global max pool ----------------
__global__ void k_pzero() {
    int i = blockIdx.x * 256 + threadIdx.x;
    if (i < BB * 1024) g_pool[i] = 0.f;
}

__global__ void k_pool4() {
    int b = blockIdx.z;
    int o = blockIdx.x * 256 + threadIdx.x;
    int n0 = blockIdx.y * 256;
    float s = g_scale[o], t = g_shift[o];
    float m = -FLT_MAX;
    #pragma unroll 4
    for (int n = n0; n < n0 + 256; n++)
        m = fmaxf(m, g_u[((size_t)b * NP + n) * 1024 + o]);
    float v = fmaxf(s * m + t, 0.f);
    atomicMax((int*)&g_pool[b * 1024 + o], __float_as_int(v));
}

// ---------------- FC layers ----------------
__global__ void k_fc1(const float* W, const float* bias) {
    int b = blockIdx.x, t = threadIdx.x;
    float a0 = bias[t], a1 = bias[t + 256];
    const float* y = g_pool + b * 1024;
    #pragma unroll 4
    for (int c = 0; c < 1024; c++) {
        float xv = y[c];
        a0 += xv * W[c * 512 + t];
        a1 += xv * W[c * 512 + t + 256];
    }
    g_fc1[b * 512 + t]       = fmaxf(a0, 0.f);
    g_fc1[b * 512 + t + 256] = fmaxf(a1, 0.f);
}

__global__ void k_fc2(const float* W, const float* bias, float* out) {
    int b = blockIdx.x, o = threadIdx.x;
    if (o >= 40) return;
    float a = bias[o];
    const float* y = g_fc1 + b * 512;
    #pragma unroll 4
    for (int c = 0; c < 512; c++) a += y[c] * W[c * 40 + o];
    out[b * 40 + o] = a;
}

// ---------------- launcher ----------------
extern "C" void kernel_launch(void* const* d_in, const int* in_sizes, int n_in,
                              void* d_out, int out_size) {
    (void)in_sizes; (void)n_in; (void)out_size;
    const float* pos = (const float*)d_in[0];
    const float* W[4]  = {(const float*)d_in[1],  (const float*)d_in[5],
                          (const float*)d_in[9],  (const float*)d_in[13]};
    const float* gm[4] = {(const float*)d_in[3],  (const float*)d_in[7],
                          (const float*)d_in[11], (const float*)d_in[15]};
    const float* bt[4] = {(const float*)d_in[4],  (const float*)d_in[8],
                          (const float*)d_in[12], (const float*)d_in[16]};
    const float* Wc1 = (const float*)d_in[17];
    const float* bc1 = (const float*)d_in[18];
    const float* Wc2 = (const float*)d_in[19];
    const float* bc2 = (const float*)d_in[20];

    const int cin[4]  = {3, 64, 64, 128};
    const int cout[4] = {64, 64, 128, 1024};
    const int M = BB * NP;

    k_pzero<<<64, 256>>>();
    for (int l = 0; l < 4; l++) {
        const float* xin = (l == 0) ? pos : nullptr;
        k_sqnorm<<<M / 256, 256>>>(xin, cin[l]);
        k_gram128<<<dim3(36, 1, BB), 256>>>(xin, cin[l]);
        k_knn<<<(M * 32) / 256, 256>>>();
        k_gemm_tc<<<dim3(2 * cout[l] / 128, M / 128), 256>>>(xin, W[l], M, cin[l], cout[l]);
        k_zero<<<8, 256>>>();
        k_edge<<<M / PTS, 256>>>(cout[l]);
        k_fin<<<4, 256>>>(gm[l], bt[l], cout[l]);
        if (l < 3) k_apply<<<(M * cout[l]) / 256, 256>>>(cout[l]);
        else       k_pool4<<<dim3(4, 4, BB), 256>>>();
    }
    k_fc1<<<BB, 256>>>(Wc1, bc1);
    k_fc2<<<BB, 64>>>(Wc2, bc2, (float*)d_out);
}

// round 7
// speedup vs baseline: 1.7731x; 1.1770x over previous
#include <cuda_runtime.h>
#include <float.h>
#include <math.h>
#include <stdint.h>

#define BB 16
#define NP 1024
#define KNN 20
#define EDGES (BB*NP*KNN)
#define TM 128
#define TN 128
#define TK 8

// ---------------- scratch ----------------
__device__ float g_gram[BB*NP*NP];
__device__ float g_uv[BB*NP*2048];        // [u | v], stride 2*cout
__device__ float g_u[BB*NP*1024];         // u + max_k v  (per point)
__device__ float g_x[BB*NP*1024];         // layer features (layers 1-3)
__device__ float g_ah[BB*NP*128];         // A hi plane [M][Kp]
__device__ float g_al[BB*NP*128];         // A lo plane
__device__ float g_wh[128*2048];          // W hi plane [Kp][N]
__device__ float g_wl[128*2048];          // W lo plane
__device__ float g_sq[BB*NP];
__device__ int   g_idx[BB*NP*KNN];
__device__ float g_sum[1024];
__device__ float g_sum2[1024];
__device__ float g_scale[1024];
__device__ float g_shift[1024];
__device__ float g_pool[BB*1024];
__device__ float g_fc1[BB*512];

__device__ __forceinline__ const float* xsel(const float* xin) { return xin ? xin : g_x; }

__device__ __forceinline__ float f2tf32f(float f) {
    unsigned r;
    asm("cvt.rna.tf32.f32 %0, %1;" : "=r"(r) : "f"(f));
    return __uint_as_float(r);
}

// cp.async helpers
__device__ __forceinline__ void cp16(uint32_t dst, const void* src) {
    asm volatile("cp.async.ca.shared.global [%0], [%1], 16;\n" :: "r"(dst), "l"(src));
}
__device__ __forceinline__ void cp_commit() { asm volatile("cp.async.commit_group;\n"); }
__device__ __forceinline__ void cp_wait1() { asm volatile("cp.async.wait_group 1;\n"); }
__device__ __forceinline__ void cp_wait0() { asm volatile("cp.async.wait_group 0;\n"); }

// ---------------- squared norms (+ zero BN accumulators) ----------------
__global__ void k_sqnorm(const float* xin, int C) {
    const float* x = xsel(xin);
    int i = blockIdx.x * blockDim.x + threadIdx.x;
    if (i < 1024) { g_sum[i] = 0.f; g_sum2[i] = 0.f; }
    if (i >= BB * NP) return;
    const float* r = x + (size_t)i * C;
    float s = 0.f;
    for (int c = 0; c < C; c++) { float v = r[c]; s += v * v; }
    g_sq[i] = s;
}

// ---------------- Gram: symmetric, 36 upper-tri tile pairs, 8x8/thread (fp32) ----------------
__global__ __launch_bounds__(256, 2) void k_gram128(const float* xin, int C) {
    const float* x = xsel(xin);
    int b = blockIdx.z;
    const float* xb = x + (size_t)b * NP * C;

    int p = blockIdx.x, mt = 0;
    while (p >= 8 - mt) { p -= 8 - mt; mt++; }
    int nt = mt + p;

    int m0 = mt * TM, n0 = nt * TN;
    int tid = threadIdx.x;
    int tx = tid & 15, ty = tid >> 4;

    __shared__ float As[2][TK][TM + 4];
    __shared__ float Bs[2][TK][TN + 4];

    float acc[8][8];
    #pragma unroll
    for (int i = 0; i < 8; i++)
        #pragma unroll
        for (int j = 0; j < 8; j++) acc[i][j] = 0.f;

    int KT = (C + TK - 1) / TK;

    #pragma unroll
    for (int i = 0; i < 4; i++) {
        int e = i * 256 + tid; int m = e >> 3, k = e & 7;
        As[0][k][m] = (k < C) ? xb[(size_t)(m0 + m) * C + k] : 0.f;
        Bs[0][k][m] = (k < C) ? xb[(size_t)(n0 + m) * C + k] : 0.f;
    }
    __syncthreads();

    int cur = 0;
    for (int kt = 0; kt < KT; kt++) {
        int k0n = (kt + 1) * TK;
        bool has_next = (kt + 1 < KT);
        float a_st[4], b_st[4];
        if (has_next) {
            #pragma unroll
            for (int i = 0; i < 4; i++) {
                int e = i * 256 + tid; int m = e >> 3, k = e & 7;
                a_st[i] = (k0n + k < C) ? xb[(size_t)(m0 + m) * C + k0n + k] : 0.f;
                b_st[i] = (k0n + k < C) ? xb[(size_t)(n0 + m) * C + k0n + k] : 0.f;
            }
        }
        #pragma unroll
        for (int kk = 0; kk < TK; kk++) {
            float ra[8], rb[8];
            #pragma unroll
            for (int i = 0; i < 8; i++) ra[i] = As[cur][kk][ty * 8 + i];
            #pragma unroll
            for (int j = 0; j < 8; j++) rb[j] = Bs[cur][kk][tx * 8 + j];
            #pragma unroll
            for (int i = 0; i < 8; i++)
                #pragma unroll
                for (int j = 0; j < 8; j++) acc[i][j] += ra[i] * rb[j];
        }
        if (has_next) {
            #pragma unroll
            for (int i = 0; i < 4; i++) {
                int e = i * 256 + tid; int m = e >> 3, k = e & 7;
                As[cur ^ 1][k][m] = a_st[i];
                Bs[cur ^ 1][k][m] = b_st[i];
            }
            __syncthreads();
            cur ^= 1;
        }
    }

    float sqr[8], sqn[8];
    #pragma unroll
    for (int i = 0; i < 8; i++) sqr[i] = g_sq[b * NP + m0 + ty * 8 + i];
    #pragma unroll
    for (int j = 0; j < 8; j++) sqn[j] = g_sq[b * NP + n0 + tx * 8 + j];
    #pragma unroll
    for (int i = 0; i < 8; i++)
        #pragma unroll
        for (int j = 0; j < 8; j++) {
            float d = sqr[i] + sqn[j] - 2.f * acc[i][j];
            if (mt == nt && (m0 + ty * 8 + i) == (n0 + tx * 8 + j)) d += 1e10f;
            acc[i][j] = d;
        }

    #pragma unroll
    for (int i = 0; i < 8; i++) {
        float* dst = &g_gram[((size_t)b * NP + m0 + ty * 8 + i) * NP + n0 + tx * 8];
        *(float4*)dst       = make_float4(acc[i][0], acc[i][1], acc[i][2], acc[i][3]);
        *(float4*)(dst + 4) = make_float4(acc[i][4], acc[i][5], acc[i][6], acc[i][7]);
    }
    if (mt != nt) {
        #pragma unroll
        for (int j = 0; j < 8; j++) {
            float* dst = &g_gram[((size_t)b * NP + n0 + tx * 8 + j) * NP + m0 + ty * 8];
            *(float4*)dst       = make_float4(acc[0][j], acc[1][j], acc[2][j], acc[3][j]);
            *(float4*)(dst + 4) = make_float4(acc[4][j], acc[5][j], acc[6][j], acc[7][j]);
        }
    }
}

// ---------------- kNN top-20: per-lane top-2 cache + rare rescan ----------------
__global__ void k_knn() {
    int gt = blockIdx.x * blockDim.x + threadIdx.x;
    int w = gt >> 5;
    int lane = gt & 31;
    if (w >= BB * NP) return;
    const float* row = g_gram + (size_t)w * NP;

    unsigned key[32];
    #pragma unroll
    for (int j = 0; j < 32; j++) {
        unsigned u = __float_as_uint(row[lane + j * 32]);
        key[j] = (u & 0x80000000u) ? ~u : (u | 0x80000000u);
    }

    unsigned k1 = 0xFFFFFFFFu, k2 = 0xFFFFFFFFu;
    int j1 = 0, j2 = 0;
    #pragma unroll
    for (int j = 0; j < 32; j++) {
        unsigned kk = key[j];
        if (kk < k1)      { k2 = k1; j2 = j1; k1 = kk; j1 = j; }
        else if (kk < k2) { k2 = kk; j2 = j; }
    }

    unsigned used = 0u;
    unsigned head = k1; int hj = j1;
    int stage = 0;

    for (int t = 0; t < KNN; t++) {
        unsigned wmin = __reduce_min_sync(0xFFFFFFFFu, head);
        unsigned my = (head == wmin) ? (unsigned)(lane + hj * 32) : 0xFFFFFFFFu;
        unsigned widx = __reduce_min_sync(0xFFFFFFFFu, my);
        if (lane == 0) g_idx[w * KNN + t] = (int)widx;
        if (my == widx) {
            used |= 1u << hj;
            stage++;
            if (stage == 1) { head = k2; hj = j2; }
            else {
                head = 0xFFFFFFFFu; hj = 0;
                #pragma unroll
                for (int j = 0; j < 32; j++)
                    if (!((used >> j) & 1u) && key[j] < head) { head = key[j]; hj = j; }
            }
        }
    }
}

// ---------------- pre-split operands into tf32 hi/lo planes ----------------
__global__ void k_splitA(const float* xin, int K, int Kp) {
    const float* x = xsel(xin);
    int i = blockIdx.x * 256 + threadIdx.x;     // over M*Kp (grid sized exactly)
    int m = i / Kp, k = i % Kp;
    float v = (k < K) ? x[(size_t)m * K + k] : 0.f;
    float h = f2tf32f(v);
    g_ah[i] = h;
    g_al[i] = f2tf32f(v - h);
}

__global__ void k_splitW(const float* W, int K, int Kp, int cout) {
    int i = blockIdx.x * 256 + threadIdx.x;     // over Kp*N
    int N = 2 * cout;
    int k = i / N, col = i % N;
    float v = 0.f;
    if (k < K) {
        if (col < cout) v = W[(size_t)k * cout + col];
        else {
            int c2 = col - cout;
            v = W[(size_t)(K + k) * cout + c2] - W[(size_t)k * cout + c2];
        }
    }
    float h = f2tf32f(v);
    g_wh[i] = h;
    g_wl[i] = f2tf32f(v - h);
}

// ---------------- 3xTF32 GEMM, pre-split operands, cp.async double-buffered ----------------
// g_uv[M, N] = A @ W,  128x128x16 tile, 8 warps (2m x 4n), warp tile 64x32, m16n8k8.
#define GBK 16
#define A_STR 20
#define B_STR 136
#define A_BUF (128*A_STR)   // floats per buffer
#define B_BUF (GBK*B_STR)
#define GEMM_SMEM ((2*A_BUF*2 + 2*B_BUF*2) * 4)   // 75776 bytes

__global__ __launch_bounds__(256) void k_gemm_tc(int M, int Kp, int N) {
    extern __shared__ float smem[];
    float* AsH = smem;
    float* AsL = AsH + 2 * A_BUF;
    float* BsH = AsL + 2 * A_BUF;
    float* BsL = BsH + 2 * B_BUF;

    uint32_t aH0 = (uint32_t)__cvta_generic_to_shared(AsH);
    uint32_t aL0 = (uint32_t)__cvta_generic_to_shared(AsL);
    uint32_t bH0 = (uint32_t)__cvta_generic_to_shared(BsH);
    uint32_t bL0 = (uint32_t)__cvta_generic_to_shared(BsL);

    int tid = threadIdx.x;
    int m0 = blockIdx.y * 128, n0 = blockIdx.x * 128;
    int wid = tid >> 5, lane = tid & 31;
    int wm = wid >> 2, wn = wid & 3;
    int gid = lane >> 2, tig = lane & 3;

    float acc[4][4][4];
    #pragma unroll
    for (int mi = 0; mi < 4; mi++)
        #pragma unroll
        for (int ni = 0; ni < 4; ni++)
            #pragma unroll
            for (int r = 0; r < 4; r++) acc[mi][ni][r] = 0.f;

    auto prefetch = [&](int buf, int k0) {
        #pragma unroll
        for (int i = 0; i < 2; i++) {
            int e = i * 256 + tid;              // 512 float4s
            int m = e >> 2, kq = e & 3;
            size_t src = (size_t)(m0 + m) * Kp + k0 + kq * 4;
            uint32_t d = (uint32_t)((buf * A_BUF + m * A_STR + kq * 4) * 4);
            cp16(aH0 + d, &g_ah[src]);
            cp16(aL0 + d, &g_al[src]);
        }
        #pragma unroll
        for (int i = 0; i < 2; i++) {
            int e = i * 256 + tid;              // 512 float4s
            int k = e >> 5, nq = e & 31;
            size_t src = (size_t)(k0 + k) * N + n0 + nq * 4;
            uint32_t d = (uint32_t)((buf * B_BUF + k * B_STR + nq * 4) * 4);
            cp16(bH0 + d, &g_wh[src]);
            cp16(bL0 + d, &g_wl[src]);
        }
        cp_commit();
    };

    int KT = Kp / GBK;
    prefetch(0, 0);

    int cur = 0;
    for (int kt = 0; kt < KT; kt++) {
        bool has_next = (kt + 1 < KT);
        if (has_next) prefetch(cur ^ 1, (kt + 1) * GBK);
        if (has_next) cp_wait1(); else cp_wait0();
        __syncthreads();

        const float* aH = AsH + cur * A_BUF;
        const float* aL = AsL + cur * A_BUF;
        const float* bH = BsH + cur * B_BUF;
        const float* bL = BsL + cur * B_BUF;

        #pragma unroll
        for (int kk = 0; kk < GBK; kk += 8) {
            unsigned bfH[4][2], bfL[4][2];
            #pragma unroll
            for (int ni = 0; ni < 4; ni++) {
                int cb = wn * 32 + ni * 8;
                bfH[ni][0] = __float_as_uint(bH[(kk + tig) * B_STR + cb + gid]);
                bfH[ni][1] = __float_as_uint(bH[(kk + tig + 4) * B_STR + cb + gid]);
                bfL[ni][0] = __float_as_uint(bL[(kk + tig) * B_STR + cb + gid]);
                bfL[ni][1] = __float_as_uint(bL[(kk + tig + 4) * B_STR + cb + gid]);
            }
            #pragma unroll
            for (int mi = 0; mi < 4; mi++) {
                int rb = wm * 64 + mi * 16;
                unsigned aHf[4], aLf[4];
                aHf[0] = __float_as_uint(aH[(rb + gid) * A_STR + kk + tig]);
                aHf[1] = __float_as_uint(aH[(rb + gid + 8) * A_STR + kk + tig]);
                aHf[2] = __float_as_uint(aH[(rb + gid) * A_STR + kk + tig + 4]);
                aHf[3] = __float_as_uint(aH[(rb + gid + 8) * A_STR + kk + tig + 4]);
                aLf[0] = __float_as_uint(aL[(rb + gid) * A_STR + kk + tig]);
                aLf[1] = __float_as_uint(aL[(rb + gid + 8) * A_STR + kk + tig]);
                aLf[2] = __float_as_uint(aL[(rb + gid) * A_STR + kk + tig + 4]);
                aLf[3] = __float_as_uint(aL[(rb + gid + 8) * A_STR + kk + tig + 4]);
                #pragma unroll
                for (int ni = 0; ni < 4; ni++) {
                    #define MMA(AF0,AF1,AF2,AF3,BF0,BF1)                                     \
                        asm volatile(                                                        \
                            "mma.sync.aligned.m16n8k8.row.col.f32.tf32.tf32.f32 "           \
                            "{%0,%1,%2,%3}, {%4,%5,%6,%7}, {%8,%9}, {%0,%1,%2,%3};"         \
                            : "+f"(acc[mi][ni][0]), "+f"(acc[mi][ni][1]),                    \
                              "+f"(acc[mi][ni][2]), "+f"(acc[mi][ni][3])                     \
                            : "r"(AF0), "r"(AF1), "r"(AF2), "r"(AF3), "r"(BF0), "r"(BF1))
                    MMA(aHf[0], aHf[1], aHf[2], aHf[3], bfL[ni][0], bfL[ni][1]);
                    MMA(aLf[0], aLf[1], aLf[2], aLf[3], bfH[ni][0], bfH[ni][1]);
                    MMA(aHf[0], aHf[1], aHf[2], aHf[3], bfH[ni][0], bfH[ni][1]);
                    #undef MMA
                }
            }
        }
        __syncthreads();
        cur ^= 1;
    }

    #pragma unroll
    for (int mi = 0; mi < 4; mi++) {
        int row0 = m0 + wm * 64 + mi * 16 + gid;
        #pragma unroll
        for (int ni = 0; ni < 4; ni++) {
            int col = n0 + wn * 32 + ni * 8 + tig * 2;
            *(float2*)&g_uv[(size_t)row0 * N + col]       = make_float2(acc[mi][ni][0], acc[mi][ni][1]);
            *(float2*)&g_uv[(size_t)(row0 + 8) * N + col] = make_float2(acc[mi][ni][2], acc[mi][ni][3]);
        }
    }
}

// ---------------- gather over k : max + channel stats (float4, 2D mapping) ----------------
#define PTS 16
__global__ __launch_bounds__(256) void k_edge(int cout) {
    __shared__ float ssum[1024], ssum2[1024];
    int tid = threadIdx.x;
    for (int i = tid; i < cout; i += 256) { ssum[i] = 0.f; ssum2[i] = 0.f; }
    __syncthreads();

    int cpg = cout >> 2;                 // float4 chunks per point (16..256)
    int pp  = 256 / cpg;                 // points processed in parallel
    int pi = tid / cpg, ci = tid % cpg;
    int base = blockIdx.x * PTS;
    int b = base / NP;
    int C2 = 2 * cout;
    int o = ci * 4;

    float4 se  = make_float4(0.f, 0.f, 0.f, 0.f);
    float4 se2 = make_float4(0.f, 0.f, 0.f, 0.f);

    for (int p0 = 0; p0 < PTS; p0 += pp) {
        int bn = base + p0 + pi;
        const int* idxp = g_idx + (size_t)bn * KNN;
        int jj[KNN];
        #pragma unroll
        for (int k = 0; k < KNN; k++) jj[k] = __ldg(&idxp[k]);

        float4 u = *(const float4*)&g_uv[(size_t)bn * C2 + o];
        float4 mv = make_float4(-FLT_MAX, -FLT_MAX, -FLT_MAX, -FLT_MAX);
        #pragma unroll
        for (int k = 0; k < KNN; k++) {
            float4 v = *(const float4*)&g_uv[((size_t)b * NP + jj[k]) * C2 + cout + o];
            mv.x = fmaxf(mv.x, v.x); mv.y = fmaxf(mv.y, v.y);
            mv.z = fmaxf(mv.z, v.z); mv.w = fmaxf(mv.w, v.w);
            float4 e = make_float4(u.x + v.x, u.y + v.y, u.z + v.z, u.w + v.w);
            se.x += e.x; se.y += e.y; se.z += e.z; se.w += e.w;
            se2.x += e.x * e.x; se2.y += e.y * e.y; se2.z += e.z * e.z; se2.w += e.w * e.w;
        }
        *(float4*)&g_u[(size_t)bn * cout + o] =
            make_float4(u.x + mv.x, u.y + mv.y, u.z + mv.z, u.w + mv.w);
    }

    atomicAdd(&ssum[o + 0], se.x);  atomicAdd(&ssum[o + 1], se.y);
    atomicAdd(&ssum[o + 2], se.z);  atomicAdd(&ssum[o + 3], se.w);
    atomicAdd(&ssum2[o + 0], se2.x); atomicAdd(&ssum2[o + 1], se2.y);
    atomicAdd(&ssum2[o + 2], se2.z); atomicAdd(&ssum2[o + 3], se2.w);
    __syncthreads();
    for (int i = tid; i < cout; i += 256) {
        atomicAdd(&g_sum[i],  ssum[i]);
        atomicAdd(&g_sum2[i], ssum2[i]);
    }
}

// ---------------- BN finalize ----------------
__global__ void k_fin(const float* gam, const float* bet, int cout) {
    int o = blockIdx.x * 256 + threadIdx.x;
    if (o >= cout) return;
    float inv = 1.f / (float)EDGES;
    float mean = g_sum[o] * inv;
    float var  = g_sum2[o] * inv - mean * mean;
    float s = rsqrtf(var + 1e-5f) * gam[o];
    g_scale[o] = s;
    g_shift[o] = bet[o] - mean * s;
}

// ---------------- apply BN + relu (layers 1-3), float4 ----------------
__global__ void k_apply(int cout) {
    int i = blockIdx.x * 256 + threadIdx.x;      // over M*cout/4
    int i4 = i * 4;
    int o = i4 & (cout - 1);
    float4 u = *(const float4*)&g_u[i4];
    float4 s = *(const float4*)&g_scale[o];
    float4 t = *(const float4*)&g_shift[o];
    float4 v;
    v.x = fmaxf(u.x * s.x + t.x, 0.f);
    v.y = fmaxf(u.y * s.y + t.y, 0.f);
    v.z = fmaxf(u.z * s.z + t.z, 0.f);
    v.w = fmaxf(u.w * s.w + t.w, 0.f);
    *(float4*)&g_x[i4] = v;
}

// ---------------- layer-4 fused BN + relu + global max pool ----------------
__global__ void k_pzero() {
    int i = blockIdx.x * 256 + threadIdx.x;
    if (i < BB * 1024) g_pool[i] = 0.f;
}

__global__ void k_pool4() {
    int b = blockIdx.z;
    int o = blockIdx.x * 256 + threadIdx.x;
    int n0 = blockIdx.y * 256;
    float s = g_scale[o], t = g_shift[o];
    float m = -FLT_MAX;
    #pragma unroll 4
    for (int n = n0; n < n0 + 256; n++)
        m = fmaxf(m, g_u[((size_t)b * NP + n) * 1024 + o]);
    float v = fmaxf(s * m + t, 0.f);
    atomicMax((int*)&g_pool[b * 1024 + o], __float_as_int(v));
}

// ---------------- FC layers ----------------
__global__ void k_fc1(const float* W, const float* bias) {
    int b = blockIdx.x, t = threadIdx.x;
    float a0 = bias[t], a1 = bias[t + 256];
    const float* y = g_pool + b * 1024;
    #pragma unroll 4
    for (int c = 0; c < 1024; c++) {
        float xv = y[c];
        a0 += xv * W[c * 512 + t];
        a1 += xv * W[c * 512 + t + 256];
    }
    g_fc1[b * 512 + t]       = fmaxf(a0, 0.f);
    g_fc1[b * 512 + t + 256] = fmaxf(a1, 0.f);
}

__global__ void k_fc2(const float* W, const float* bias, float* out) {
    int b = blockIdx.x, o = threadIdx.x;
    if (o >= 40) return;
    float a = bias[o];
    const float* y = g_fc1 + b * 512;
    #pragma unroll 4
    for (int c = 0; c < 512; c++) a += y[c] * W[c * 40 + o];
    out[b * 40 + o] = a;
}

// ---------------- launcher ----------------
extern "C" void kernel_launch(void* const* d_in, const int* in_sizes, int n_in,
                              void* d_out, int out_size) {
    (void)in_sizes; (void)n_in; (void)out_size;
    const float* pos = (const float*)d_in[0];
    const float* W[4]  = {(const float*)d_in[1],  (const float*)d_in[5],
                          (const float*)d_in[9],  (const float*)d_in[13]};
    const float* gm[4] = {(const float*)d_in[3],  (const float*)d_in[7],
                          (const float*)d_in[11], (const float*)d_in[15]};
    const float* bt[4] = {(const float*)d_in[4],  (const float*)d_in[8],
                          (const float*)d_in[12], (const float*)d_in[16]};
    const float* Wc1 = (const float*)d_in[17];
    const float* bc1 = (const float*)d_in[18];
    const float* Wc2 = (const float*)d_in[19];
    const float* bc2 = (const float*)d_in[20];

    const int cin[4]  = {3, 64, 64, 128};
    const int Kp[4]   = {16, 64, 64, 128};
    const int cout[4] = {64, 64, 128, 1024};
    const int M = BB * NP;

    cudaFuncSetAttribute(k_gemm_tc, cudaFuncAttributeMaxDynamicSharedMemorySize, GEMM_SMEM);

    k_pzero<<<64, 256>>>();
    for (int l = 0; l < 4; l++) {
        const float* xin = (l == 0) ? pos : nullptr;
        int N2 = 2 * cout[l];
        k_sqnorm<<<M / 256, 256>>>(xin, cin[l]);
        k_gram128<<<dim3(36, 1, BB), 256>>>(xin, cin[l]);
        k_knn<<<(M * 32) / 256, 256>>>();
        k_splitA<<<(M * Kp[l]) / 256, 256>>>(xin, cin[l], Kp[l]);
        k_splitW<<<(Kp[l] * N2 + 255) / 256, 256>>>(W[l], cin[l], Kp[l], cout[l]);
        k_gemm_tc<<<dim3(N2 / 128, M / 128), 256, GEMM_SMEM>>>(M, Kp[l], N2);
        k_edge<<<M / PTS, 256>>>(cout[l]);
        k_fin<<<4, 256>>>(gm[l], bt[l], cout[l]);
        if (l < 3) k_apply<<<(M * cout[l]) / 1024, 256>>>(cout[l]);
        else       k_pool4<<<dim3(4, 4, BB), 256>>>();
    }
    k_fc1<<<BB, 256>>>(Wc1, bc1);
    k_fc2<<<BB, 64>>>(Wc2, bc2, (float*)d_out);
}

// round 8
// speedup vs baseline: 1.8514x; 1.0441x over previous
#include <cuda_runtime.h>
#include <float.h>
#include <math.h>
#include <stdint.h>

#define BB 16
#define NP 1024
#define KNN 20
#define EDGES (BB*NP*KNN)

// ---------------- scratch ----------------
__device__ float g_gram[BB*NP*NP];
__device__ float g_uv[BB*NP*2048];        // [u | v], stride 2*cout
__device__ float g_u[BB*NP*1024];         // u + max_k v  (per point)
__device__ float g_ah[BB*NP*128];         // A hi plane [M][Kp]
__device__ float g_al[BB*NP*128];         // A lo plane
__device__ float g_wh[128*2048];          // W hi plane [Kp][N]
__device__ float g_wl[128*2048];          // W lo plane
__device__ float g_sq[BB*NP];
__device__ int   g_idx[BB*NP*KNN];
__device__ float g_sum[1024];
__device__ float g_sum2[1024];
__device__ float g_scale[1024];
__device__ float g_shift[1024];
__device__ float g_pool[BB*1024];
__device__ float g_fc1[BB*512];

__device__ __forceinline__ float f2tf32f(float f) {
    unsigned r;
    asm("cvt.rna.tf32.f32 %0, %1;" : "=r"(r) : "f"(f));
    return __uint_as_float(r);
}

// cp.async helpers
__device__ __forceinline__ void cp16(uint32_t dst, const void* src) {
    asm volatile("cp.async.ca.shared.global [%0], [%1], 16;\n" :: "r"(dst), "l"(src));
}
__device__ __forceinline__ void cp_commit() { asm volatile("cp.async.commit_group;\n"); }
__device__ __forceinline__ void cp_wait1() { asm volatile("cp.async.wait_group 1;\n"); }
__device__ __forceinline__ void cp_wait0() { asm volatile("cp.async.wait_group 0;\n"); }

#define MMA3(ACC, AH, AL, BH, BL)                                                \
    do {                                                                         \
        asm volatile("mma.sync.aligned.m16n8k8.row.col.f32.tf32.tf32.f32 "       \
            "{%0,%1,%2,%3}, {%4,%5,%6,%7}, {%8,%9}, {%0,%1,%2,%3};"              \
            : "+f"(ACC[0]), "+f"(ACC[1]), "+f"(ACC[2]), "+f"(ACC[3])             \
            : "r"(AH[0]), "r"(AH[1]), "r"(AH[2]), "r"(AH[3]), "r"(BL[0]), "r"(BL[1])); \
        asm volatile("mma.sync.aligned.m16n8k8.row.col.f32.tf32.tf32.f32 "       \
            "{%0,%1,%2,%3}, {%4,%5,%6,%7}, {%8,%9}, {%0,%1,%2,%3};"              \
            : "+f"(ACC[0]), "+f"(ACC[1]), "+f"(ACC[2]), "+f"(ACC[3])             \
            : "r"(AL[0]), "r"(AL[1]), "r"(AL[2]), "r"(AL[3]), "r"(BH[0]), "r"(BH[1])); \
        asm volatile("mma.sync.aligned.m16n8k8.row.col.f32.tf32.tf32.f32 "       \
            "{%0,%1,%2,%3}, {%4,%5,%6,%7}, {%8,%9}, {%0,%1,%2,%3};"              \
            : "+f"(ACC[0]), "+f"(ACC[1]), "+f"(ACC[2]), "+f"(ACC[3])             \
            : "r"(AH[0]), "r"(AH[1]), "r"(AH[2]), "r"(AH[3]), "r"(BH[0]), "r"(BH[1])); \
    } while (0)

// ---------------- split layer-1 input (pos) into tf32 hi/lo planes ----------------
__global__ void k_splitA(const float* x, int K, int Kp) {
    int i = blockIdx.x * 256 + threadIdx.x;     // over M*Kp
    int m = i / Kp, k = i % Kp;
    float v = (k < K) ? x[(size_t)m * K + k] : 0.f;
    float h = f2tf32f(v);
    g_ah[i] = h;
    g_al[i] = f2tf32f(v - h);
}

// ---------------- squared norms from planes (+ zero BN accumulators) ----------------
__global__ void k_sqnorm(int Kp) {
    int i = blockIdx.x * blockDim.x + threadIdx.x;
    if (i < 1024) { g_sum[i] = 0.f; g_sum2[i] = 0.f; }
    if (i >= BB * NP) return;
    const float* rh = g_ah + (size_t)i * Kp;
    const float* rl = g_al + (size_t)i * Kp;
    float s = 0.f;
    for (int c = 0; c < Kp; c++) { float v = rh[c] + rl[c]; s += v * v; }
    g_sq[i] = s;
}

// ---------------- 3xTF32 Gram: symmetric, 36 tile pairs, tensor-core ----------------
#define GBK 16
#define P_STR 20
#define P_BUF (128*P_STR)                 // floats per plane buffer
#define GRAM_SMEM (8 * P_BUF * 4)         // 4 planes x 2 buffers = 81920 B
#define T_STR 132

__global__ __launch_bounds__(256) void k_gram_tc(int Kp) {
    extern __shared__ float smem[];
    float* MH = smem;                 // m-tile hi  [2][P_BUF]
    float* ML = MH + 2 * P_BUF;
    float* NH = ML + 2 * P_BUF;       // n-tile hi
    float* NL = NH + 2 * P_BUF;

    uint32_t mh0 = (uint32_t)__cvta_generic_to_shared(MH);
    uint32_t ml0 = (uint32_t)__cvta_generic_to_shared(ML);
    uint32_t nh0 = (uint32_t)__cvta_generic_to_shared(NH);
    uint32_t nl0 = (uint32_t)__cvta_generic_to_shared(NL);

    int b = blockIdx.z;
    int p = blockIdx.x, mt = 0;
    while (p >= 8 - mt) { p -= 8 - mt; mt++; }
    int nt = mt + p;
    int m0 = mt * 128, n0 = nt * 128;
    int M0 = b * NP + m0, N0 = b * NP + n0;

    int tid = threadIdx.x;
    int wid = tid >> 5, lane = tid & 31;
    int wm = wid >> 2, wn = wid & 3;
    int gid = lane >> 2, tig = lane & 3;

    float acc[4][4][4];
    #pragma unroll
    for (int mi = 0; mi < 4; mi++)
        #pragma unroll
        for (int ni = 0; ni < 4; ni++)
            #pragma unroll
            for (int r = 0; r < 4; r++) acc[mi][ni][r] = 0.f;

    auto prefetch = [&](int buf, int k0) {
        #pragma unroll
        for (int i = 0; i < 2; i++) {
            int e = i * 256 + tid;            // 512 float4s per plane
            int m = e >> 2, kq = e & 3;
            uint32_t d = (uint32_t)((buf * P_BUF + m * P_STR + kq * 4) * 4);
            size_t srm = (size_t)(M0 + m) * Kp + k0 + kq * 4;
            size_t srn = (size_t)(N0 + m) * Kp + k0 + kq * 4;
            cp16(mh0 + d, &g_ah[srm]);
            cp16(ml0 + d, &g_al[srm]);
            cp16(nh0 + d, &g_ah[srn]);
            cp16(nl0 + d, &g_al[srn]);
        }
        cp_commit();
    };

    int KT = Kp / GBK;
    prefetch(0, 0);

    int cur = 0;
    for (int kt = 0; kt < KT; kt++) {
        bool has_next = (kt + 1 < KT);
        if (has_next) prefetch(cur ^ 1, (kt + 1) * GBK);
        if (has_next) cp_wait1(); else cp_wait0();
        __syncthreads();

        const float* mh = MH + cur * P_BUF;
        const float* ml = ML + cur * P_BUF;
        const float* nh = NH + cur * P_BUF;
        const float* nl = NL + cur * P_BUF;

        #pragma unroll
        for (int kk = 0; kk < GBK; kk += 8) {
            unsigned bfH[4][2], bfL[4][2];
            #pragma unroll
            for (int ni = 0; ni < 4; ni++) {
                int cb = wn * 32 + ni * 8 + gid;
                bfH[ni][0] = __float_as_uint(nh[cb * P_STR + kk + tig]);
                bfH[ni][1] = __float_as_uint(nh[cb * P_STR + kk + tig + 4]);
                bfL[ni][0] = __float_as_uint(nl[cb * P_STR + kk + tig]);
                bfL[ni][1] = __float_as_uint(nl[cb * P_STR + kk + tig + 4]);
            }
            #pragma unroll
            for (int mi = 0; mi < 4; mi++) {
                int rb = wm * 64 + mi * 16;
                unsigned aH[4], aL[4];
                aH[0] = __float_as_uint(mh[(rb + gid) * P_STR + kk + tig]);
                aH[1] = __float_as_uint(mh[(rb + gid + 8) * P_STR + kk + tig]);
                aH[2] = __float_as_uint(mh[(rb + gid) * P_STR + kk + tig + 4]);
                aH[3] = __float_as_uint(mh[(rb + gid + 8) * P_STR + kk + tig + 4]);
                aL[0] = __float_as_uint(ml[(rb + gid) * P_STR + kk + tig]);
                aL[1] = __float_as_uint(ml[(rb + gid + 8) * P_STR + kk + tig]);
                aL[2] = __float_as_uint(ml[(rb + gid) * P_STR + kk + tig + 4]);
                aL[3] = __float_as_uint(ml[(rb + gid + 8) * P_STR + kk + tig + 4]);
                #pragma unroll
                for (int ni = 0; ni < 4; ni++)
                    MMA3(acc[mi][ni], aH, aL, bfH[ni], bfL[ni]);
            }
        }
        __syncthreads();
        cur ^= 1;
    }

    // epilogue: distances
    float d_store[4][4][4];
    #pragma unroll
    for (int mi = 0; mi < 4; mi++) {
        int rl0 = wm * 64 + mi * 16 + gid;
        float sr0 = g_sq[M0 + rl0], sr1 = g_sq[M0 + rl0 + 8];
        #pragma unroll
        for (int ni = 0; ni < 4; ni++) {
            int cl = wn * 32 + ni * 8 + tig * 2;
            float sc0 = g_sq[N0 + cl], sc1 = g_sq[N0 + cl + 1];
            float d00 = sr0 + sc0 - 2.f * acc[mi][ni][0];
            float d01 = sr0 + sc1 - 2.f * acc[mi][ni][1];
            float d10 = sr1 + sc0 - 2.f * acc[mi][ni][2];
            float d11 = sr1 + sc1 - 2.f * acc[mi][ni][3];
            if (mt == nt) {
                if (m0 + rl0 == n0 + cl)         d00 += 1e10f;
                if (m0 + rl0 == n0 + cl + 1)     d01 += 1e10f;
                if (m0 + rl0 + 8 == n0 + cl)     d10 += 1e10f;
                if (m0 + rl0 + 8 == n0 + cl + 1) d11 += 1e10f;
            }
            *(float2*)&g_gram[(size_t)(M0 + rl0) * NP + n0 + cl]     = make_float2(d00, d01);
            *(float2*)&g_gram[(size_t)(M0 + rl0 + 8) * NP + n0 + cl] = make_float2(d10, d11);
            d_store[mi][ni][0] = d00; d_store[mi][ni][1] = d01;
            d_store[mi][ni][2] = d10; d_store[mi][ni][3] = d11;
        }
    }

    // transposed tile via smem staging (off-diagonal only)
    if (mt != nt) {
        float* T = smem;   // [128][T_STR]
        __syncthreads();
        #pragma unroll
        for (int mi = 0; mi < 4; mi++) {
            int rl0 = wm * 64 + mi * 16 + gid;
            #pragma unroll
            for (int ni = 0; ni < 4; ni++) {
                int cl = wn * 32 + ni * 8 + tig * 2;
                T[(cl) * T_STR + rl0]         = d_store[mi][ni][0];
                T[(cl + 1) * T_STR + rl0]     = d_store[mi][ni][1];
                T[(cl) * T_STR + rl0 + 8]     = d_store[mi][ni][2];
                T[(cl + 1) * T_STR + rl0 + 8] = d_store[mi][ni][3];
            }
        }
        __syncthreads();
        for (int e = tid; e < 128 * 32; e += 256) {
            int r = e >> 5, q = (e & 31) * 4;
            *(float4*)&g_gram[(size_t)(N0 + r) * NP + m0 + q] =
                make_float4(T[r * T_STR + q], T[r * T_STR + q + 1],
                            T[r * T_STR + q + 2], T[r * T_STR + q + 3]);
        }
    }
}

// ---------------- kNN top-20: per-lane top-2 cache + rare rescan ----------------
__global__ void k_knn() {
    int gt = blockIdx.x * blockDim.x + threadIdx.x;
    int w = gt >> 5;
    int lane = gt & 31;
    if (w >= BB * NP) return;
    const float* row = g_gram + (size_t)w * NP;

    unsigned key[32];
    #pragma unroll
    for (int j = 0; j < 32; j++) {
        unsigned u = __float_as_uint(row[lane + j * 32]);
        key[j] = (u & 0x80000000u) ? ~u : (u | 0x80000000u);
    }

    unsigned k1 = 0xFFFFFFFFu, k2 = 0xFFFFFFFFu;
    int j1 = 0, j2 = 0;
    #pragma unroll
    for (int j = 0; j < 32; j++) {
        unsigned kk = key[j];
        if (kk < k1)      { k2 = k1; j2 = j1; k1 = kk; j1 = j; }
        else if (kk < k2) { k2 = kk; j2 = j; }
    }

    unsigned used = 0u;
    unsigned head = k1; int hj = j1;
    int stage = 0;

    for (int t = 0; t < KNN; t++) {
        unsigned wmin = __reduce_min_sync(0xFFFFFFFFu, head);
        unsigned my = (head == wmin) ? (unsigned)(lane + hj * 32) : 0xFFFFFFFFu;
        unsigned widx = __reduce_min_sync(0xFFFFFFFFu, my);
        if (lane == 0) g_idx[w * KNN + t] = (int)widx;
        if (my == widx) {
            used |= 1u << hj;
            stage++;
            if (stage == 1) { head = k2; hj = j2; }
            else {
                head = 0xFFFFFFFFu; hj = 0;
                #pragma unroll
                for (int j = 0; j < 32; j++)
                    if (!((used >> j) & 1u) && key[j] < head) { head = key[j]; hj = j; }
            }
        }
    }
}

// ---------------- split W into tf32 hi/lo planes ----------------
__global__ void k_splitW(const float* W, int K, int Kp, int cout) {
    int i = blockIdx.x * 256 + threadIdx.x;     // over Kp*N
    int N = 2 * cout;
    int k = i / N, col = i % N;
    float v = 0.f;
    if (k < K) {
        if (col < cout) v = W[(size_t)k * cout + col];
        else {
            int c2 = col - cout;
            v = W[(size_t)(K + k) * cout + c2] - W[(size_t)k * cout + c2];
        }
    }
    float h = f2tf32f(v);
    g_wh[i] = h;
    g_wl[i] = f2tf32f(v - h);
}

// ---------------- 3xTF32 GEMM, pre-split operands, cp.async double-buffered ----------------
#define A_STR 20
#define B_STR 136
#define A_BUF (128*A_STR)
#define B_BUF (GBK*B_STR)
#define GEMM_SMEM ((2*A_BUF*2 + 2*B_BUF*2) * 4)   // 75776 bytes

__global__ __launch_bounds__(256) void k_gemm_tc(int M, int Kp, int N) {
    extern __shared__ float smem[];
    float* AsH = smem;
    float* AsL = AsH + 2 * A_BUF;
    float* BsH = AsL + 2 * A_BUF;
    float* BsL = BsH + 2 * B_BUF;

    uint32_t aH0 = (uint32_t)__cvta_generic_to_shared(AsH);
    uint32_t aL0 = (uint32_t)__cvta_generic_to_shared(AsL);
    uint32_t bH0 = (uint32_t)__cvta_generic_to_shared(BsH);
    uint32_t bL0 = (uint32_t)__cvta_generic_to_shared(BsL);

    int tid = threadIdx.x;
    int m0 = blockIdx.y * 128, n0 = blockIdx.x * 128;
    int wid = tid >> 5, lane = tid & 31;
    int wm = wid >> 2, wn = wid & 3;
    int gid = lane >> 2, tig = lane & 3;

    float acc[4][4][4];
    #pragma unroll
    for (int mi = 0; mi < 4; mi++)
        #pragma unroll
        for (int ni = 0; ni < 4; ni++)
            #pragma unroll
            for (int r = 0; r < 4; r++) acc[mi][ni][r] = 0.f;

    auto prefetch = [&](int buf, int k0) {
        #pragma unroll
        for (int i = 0; i < 2; i++) {
            int e = i * 256 + tid;
            int m = e >> 2, kq = e & 3;
            size_t src = (size_t)(m0 + m) * Kp + k0 + kq * 4;
            uint32_t d = (uint32_t)((buf * A_BUF + m * A_STR + kq * 4) * 4);
            cp16(aH0 + d, &g_ah[src]);
            cp16(aL0 + d, &g_al[src]);
        }
        #pragma unroll
        for (int i = 0; i < 2; i++) {
            int e = i * 256 + tid;
            int k = e >> 5, nq = e & 31;
            size_t src = (size_t)(k0 + k) * N + n0 + nq * 4;
            uint32_t d = (uint32_t)((buf * B_BUF + k * B_STR + nq * 4) * 4);
            cp16(bH0 + d, &g_wh[src]);
            cp16(bL0 + d, &g_wl[src]);
        }
        cp_commit();
    };

    int KT = Kp / GBK;
    prefetch(0, 0);

    int cur = 0;
    for (int kt = 0; kt < KT; kt++) {
        bool has_next = (kt + 1 < KT);
        if (has_next) prefetch(cur ^ 1, (kt + 1) * GBK);
        if (has_next) cp_wait1(); else cp_wait0();
        __syncthreads();

        const float* aH = AsH + cur * A_BUF;
        const float* aL = AsL + cur * A_BUF;
        const float* bH = BsH + cur * B_BUF;
        const float* bL = BsL + cur * B_BUF;

        #pragma unroll
        for (int kk = 0; kk < GBK; kk += 8) {
            unsigned bfH[4][2], bfL[4][2];
            #pragma unroll
            for (int ni = 0; ni < 4; ni++) {
                int cb = wn * 32 + ni * 8;
                bfH[ni][0] = __float_as_uint(bH[(kk + tig) * B_STR + cb + gid]);
                bfH[ni][1] = __float_as_uint(bH[(kk + tig + 4) * B_STR + cb + gid]);
                bfL[ni][0] = __float_as_uint(bL[(kk + tig) * B_STR + cb + gid]);
                bfL[ni][1] = __float_as_uint(bL[(kk + tig + 4) * B_STR + cb + gid]);
            }
            #pragma unroll
            for (int mi = 0; mi < 4; mi++) {
                int rb = wm * 64 + mi * 16;
                unsigned aHf[4], aLf[4];
                aHf[0] = __float_as_uint(aH[(rb + gid) * A_STR + kk + tig]);
                aHf[1] = __float_as_uint(aH[(rb + gid + 8) * A_STR + kk + tig]);
                aHf[2] = __float_as_uint(aH[(rb + gid) * A_STR + kk + tig + 4]);
                aHf[3] = __float_as_uint(aH[(rb + gid + 8) * A_STR + kk + tig + 4]);
                aLf[0] = __float_as_uint(aL[(rb + gid) * A_STR + kk + tig]);
                aLf[1] = __float_as_uint(aL[(rb + gid + 8) * A_STR + kk + tig]);
                aLf[2] = __float_as_uint(aL[(rb + gid) * A_STR + kk + tig + 4]);
                aLf[3] = __float_as_uint(aL[(rb + gid + 8) * A_STR + kk + tig + 4]);
                #pragma unroll
                for (int ni = 0; ni < 4; ni++)
                    MMA3(acc[mi][ni], aHf, aLf, bfH[ni], bfL[ni]);
            }
        }
        __syncthreads();
        cur ^= 1;
    }

    #pragma unroll
    for (int mi = 0; mi < 4; mi++) {
        int row0 = m0 + wm * 64 + mi * 16 + gid;
        #pragma unroll
        for (int ni = 0; ni < 4; ni++) {
            int col = n0 + wn * 32 + ni * 8 + tig * 2;
            *(float2*)&g_uv[(size_t)row0 * N + col]       = make_float2(acc[mi][ni][0], acc[mi][ni][1]);
            *(float2*)&g_uv[(size_t)(row0 + 8) * N + col] = make_float2(acc[mi][ni][2], acc[mi][ni][3]);
        }
    }
}

// ---------------- gather over k : max + channel stats (float4, 2D mapping) ----------------
#define PTS 16
__global__ __launch_bounds__(256) void k_edge(int cout) {
    __shared__ float ssum[1024], ssum2[1024];
    int tid = threadIdx.x;
    for (int i = tid; i < cout; i += 256) { ssum[i] = 0.f; ssum2[i] = 0.f; }
    __syncthreads();

    int cpg = cout >> 2;
    int pp  = 256 / cpg;
    int pi = tid / cpg, ci = tid % cpg;
    int base = blockIdx.x * PTS;
    int b = base / NP;
    int C2 = 2 * cout;
    int o = ci * 4;

    float4 se  = make_float4(0.f, 0.f, 0.f, 0.f);
    float4 se2 = make_float4(0.f, 0.f, 0.f, 0.f);

    for (int p0 = 0; p0 < PTS; p0 += pp) {
        int bn = base + p0 + pi;
        const int* idxp = g_idx + (size_t)bn * KNN;
        int jj[KNN];
        #pragma unroll
        for (int k = 0; k < KNN; k++) jj[k] = __ldg(&idxp[k]);

        float4 u = *(const float4*)&g_uv[(size_t)bn * C2 + o];
        float4 mv = make_float4(-FLT_MAX, -FLT_MAX, -FLT_MAX, -FLT_MAX);
        #pragma unroll
        for (int k = 0; k < KNN; k++) {
            float4 v = *(const float4*)&g_uv[((size_t)b * NP + jj[k]) * C2 + cout + o];
            mv.x = fmaxf(mv.x, v.x); mv.y = fmaxf(mv.y, v.y);
            mv.z = fmaxf(mv.z, v.z); mv.w = fmaxf(mv.w, v.w);
            float4 e = make_float4(u.x + v.x, u.y + v.y, u.z + v.z, u.w + v.w);
            se.x += e.x; se.y += e.y; se.z += e.z; se.w += e.w;
            se2.x += e.x * e.x; se2.y += e.y * e.y; se2.z += e.z * e.z; se2.w += e.w * e.w;
        }
        *(float4*)&g_u[(size_t)bn * cout + o] =
            make_float4(u.x + mv.x, u.y + mv.y, u.z + mv.z, u.w + mv.w);
    }

    atomicAdd(&ssum[o + 0], se.x);  atomicAdd(&ssum[o + 1], se.y);
    atomicAdd(&ssum[o + 2], se.z);  atomicAdd(&ssum[o + 3], se.w);
    atomicAdd(&ssum2[o + 0], se2.x); atomicAdd(&ssum2[o + 1], se2.y);
    atomicAdd(&ssum2[o + 2], se2.z); atomicAdd(&ssum2[o + 3], se2.w);
    __syncthreads();
    for (int i = tid; i < cout; i += 256) {
        atomicAdd(&g_sum[i],  ssum[i]);
        atomicAdd(&g_sum2[i], ssum2[i]);
    }
}

// ---------------- BN finalize ----------------
__global__ void k_fin(const float* gam, const float* bet, int cout) {
    int o = blockIdx.x * 256 + threadIdx.x;
    if (o >= cout) return;
    float inv = 1.f / (float)EDGES;
    float mean = g_sum[o] * inv;
    float var  = g_sum2[o] * inv - mean * mean;
    float s = rsqrtf(var + 1e-5f) * gam[o];
    g_scale[o] = s;
    g_shift[o] = bet[o] - mean * s;
}

// ---------------- apply BN + relu, write next-layer tf32 planes ----------------
__global__ void k_apply(int cout) {
    int i = blockIdx.x * 256 + threadIdx.x;      // over M*cout/4
    int i4 = i * 4;
    int o = i4 & (cout - 1);
    float4 u = *(const float4*)&g_u[i4];
    float4 s = *(const float4*)&g_scale[o];
    float4 t = *(const float4*)&g_shift[o];
    float4 v, h, l;
    v.x = fmaxf(u.x * s.x + t.x, 0.f);
    v.y = fmaxf(u.y * s.y + t.y, 0.f);
    v.z = fmaxf(u.z * s.z + t.z, 0.f);
    v.w = fmaxf(u.w * s.w + t.w, 0.f);
    h.x = f2tf32f(v.x); h.y = f2tf32f(v.y); h.z = f2tf32f(v.z); h.w = f2tf32f(v.w);
    l.x = f2tf32f(v.x - h.x); l.y = f2tf32f(v.y - h.y);
    l.z = f2tf32f(v.z - h.z); l.w = f2tf32f(v.w - h.w);
    *(float4*)&g_ah[i4] = h;
    *(float4*)&g_al[i4] = l;
}

// ---------------- layer-4 fused BN + relu + global max pool ----------------
__global__ void k_pzero() {
    int i = blockIdx.x * 256 + threadIdx.x;
    if (i < BB * 1024) g_pool[i] = 0.f;
}

__global__ void k_pool4() {
    int b = blockIdx.z;
    int o = blockIdx.x * 256 + threadIdx.x;
    int n0 = blockIdx.y * 256;
    float s = g_scale[o], t = g_shift[o];
    float m = -FLT_MAX;
    #pragma unroll 4
    for (int n = n0; n < n0 + 256; n++)
        m = fmaxf(m, g_u[((size_t)b * NP + n) * 1024 + o]);
    float v = fmaxf(s * m + t, 0.f);
    atomicMax((int*)&g_pool[b * 1024 + o], __float_as_int(v));
}

// ---------------- FC layers ----------------
__global__ void k_fc1(const float* W, const float* bias) {
    int b = blockIdx.x, t = threadIdx.x;
    float a0 = bias[t], a1 = bias[t + 256];
    const float* y = g_pool + b * 1024;
    #pragma unroll 4
    for (int c = 0; c < 1024; c++) {
        float xv = y[c];
        a0 += xv * W[c * 512 + t];
        a1 += xv * W[c * 512 + t + 256];
    }
    g_fc1[b * 512 + t]       = fmaxf(a0, 0.f);
    g_fc1[b * 512 + t + 256] = fmaxf(a1, 0.f);
}

__global__ void k_fc2(const float* W, const float* bias, float* out) {
    int b = blockIdx.x, o = threadIdx.x;
    if (o >= 40) return;
    float a = bias[o];
    const float* y = g_fc1 + b * 512;
    #pragma unroll 4
    for (int c = 0; c < 512; c++) a += y[c] * W[c * 40 + o];
    out[b * 40 + o] = a;
}

// ---------------- launcher ----------------
extern "C" void kernel_launch(void* const* d_in, const int* in_sizes, int n_in,
                              void* d_out, int out_size) {
    (void)in_sizes; (void)n_in; (void)out_size;
    const float* pos = (const float*)d_in[0];
    const float* W[4]  = {(const float*)d_in[1],  (const float*)d_in[5],
                          (const float*)d_in[9],  (const float*)d_in[13]};
    const float* gm[4] = {(const float*)d_in[3],  (const float*)d_in[7],
                          (const float*)d_in[11], (const float*)d_in[15]};
    const float* bt[4] = {(const float*)d_in[4],  (const float*)d_in[8],
                          (const float*)d_in[12], (const float*)d_in[16]};
    const float* Wc1 = (const float*)d_in[17];
    const float* bc1 = (const float*)d_in[18];
    const float* Wc2 = (const float*)d_in[19];
    const float* bc2 = (const float*)d_in[20];

    const int cin[4]  = {3, 64, 64, 128};
    const int Kp[4]   = {16, 64, 64, 128};
    const int cout[4] = {64, 64, 128, 1024};
    const int M = BB * NP;

    cudaFuncSetAttribute(k_gemm_tc, cudaFuncAttributeMaxDynamicSharedMemorySize, GEMM_SMEM);
    cudaFuncSetAttribute(k_gram_tc, cudaFuncAttributeMaxDynamicSharedMemorySize, GRAM_SMEM);

    k_pzero<<<64, 256>>>();
    for (int l = 0; l < 4; l++) {
        int N2 = 2 * cout[l];
        if (l == 0) k_splitA<<<(M * Kp[0]) / 256, 256>>>(pos, cin[0], Kp[0]);
        k_sqnorm<<<M / 256, 256>>>(Kp[l]);
        k_gram_tc<<<dim3(36, 1, BB), 256, GRAM_SMEM>>>(Kp[l]);
        k_knn<<<(M * 32) / 256, 256>>>();
        k_splitW<<<(Kp[l] * N2 + 255) / 256, 256>>>(W[l], cin[l], Kp[l], cout[l]);
        k_gemm_tc<<<dim3(N2 / 128, M / 128), 256, GEMM_SMEM>>>(M, Kp[l], N2);
        k_edge<<<M / PTS, 256>>>(cout[l]);
        k_fin<<<4, 256>>>(gm[l], bt[l], cout[l]);
        if (l < 3) k_apply<<<(M * cout[l]) / 1024, 256>>>(cout[l]);
        else       k_pool4<<<dim3(4, 4, BB), 256>>>();
    }
    k_fc1<<<BB, 256>>>(Wc1, bc1);
    k_fc2<<<BB, 64>>>(Wc2, bc2, (float*)d_out);
}

// round 9
// speedup vs baseline: 2.0509x; 1.1077x over previous
#include <cuda_runtime.h>
#include <float.h>
#include <math.h>
#include <stdint.h>

#define BB 16
#define NP 1024
#define KNN 20
#define EDGES (BB*NP*KNN)

// ---------------- scratch ----------------
__device__ float g_gram[BB*NP*NP];
__device__ float g_uv[BB*NP*2048];        // [u | v], stride 2*cout
__device__ float g_u[BB*NP*1024];         // u + max_k v  (per point)
__device__ float g_ah[BB*NP*128];         // A hi plane [M][Kp]
__device__ float g_al[BB*NP*128];         // A lo plane
__device__ float g_wh[128*2048];          // W hi plane [Kp][N]
__device__ float g_wl[128*2048];          // W lo plane
__device__ float g_sq[BB*NP];
__device__ int   g_idx[BB*NP*KNN];
__device__ float g_sum[1024];             // zero at load; k_fin re-zeros each layer
__device__ float g_sum2[1024];
__device__ float g_scale[1024];
__device__ float g_shift[1024];
__device__ float g_pool[BB*1024];
__device__ float g_fc1[BB*512];

__device__ __forceinline__ float f2tf32f(float f) {
    unsigned r;
    asm("cvt.rna.tf32.f32 %0, %1;" : "=r"(r) : "f"(f));
    return __uint_as_float(r);
}

// cp.async helpers
__device__ __forceinline__ void cp16(uint32_t dst, const void* src) {
    asm volatile("cp.async.ca.shared.global [%0], [%1], 16;\n" :: "r"(dst), "l"(src));
}
__device__ __forceinline__ void cp_commit() { asm volatile("cp.async.commit_group;\n"); }
__device__ __forceinline__ void cp_wait1() { asm volatile("cp.async.wait_group 1;\n"); }
__device__ __forceinline__ void cp_wait0() { asm volatile("cp.async.wait_group 0;\n"); }

#define MMA3(ACC, AH, AL, BH, BL)                                                \
    do {                                                                         \
        asm volatile("mma.sync.aligned.m16n8k8.row.col.f32.tf32.tf32.f32 "       \
            "{%0,%1,%2,%3}, {%4,%5,%6,%7}, {%8,%9}, {%0,%1,%2,%3};"              \
            : "+f"(ACC[0]), "+f"(ACC[1]), "+f"(ACC[2]), "+f"(ACC[3])             \
            : "r"(AH[0]), "r"(AH[1]), "r"(AH[2]), "r"(AH[3]), "r"(BL[0]), "r"(BL[1])); \
        asm volatile("mma.sync.aligned.m16n8k8.row.col.f32.tf32.tf32.f32 "       \
            "{%0,%1,%2,%3}, {%4,%5,%6,%7}, {%8,%9}, {%0,%1,%2,%3};"              \
            : "+f"(ACC[0]), "+f"(ACC[1]), "+f"(ACC[2]), "+f"(ACC[3])             \
            : "r"(AL[0]), "r"(AL[1]), "r"(AL[2]), "r"(AL[3]), "r"(BH[0]), "r"(BH[1])); \
        asm volatile("mma.sync.aligned.m16n8k8.row.col.f32.tf32.tf32.f32 "       \
            "{%0,%1,%2,%3}, {%4,%5,%6,%7}, {%8,%9}, {%0,%1,%2,%3};"              \
            : "+f"(ACC[0]), "+f"(ACC[1]), "+f"(ACC[2]), "+f"(ACC[3])             \
            : "r"(AH[0]), "r"(AH[1]), "r"(AH[2]), "r"(AH[3]), "r"(BH[0]), "r"(BH[1])); \
    } while (0)

// ---------------- split layer-1 input (pos) into planes + squared norms ----------------
__global__ void k_splitA(const float* x, int K, int Kp) {
    int m = blockIdx.x * 256 + threadIdx.x;     // one thread per point
    if (m >= BB * NP) return;
    float s = 0.f;
    for (int k = 0; k < Kp; k++) {
        float v = (k < K) ? x[(size_t)m * K + k] : 0.f;
        float h = f2tf32f(v);
        g_ah[(size_t)m * Kp + k] = h;
        g_al[(size_t)m * Kp + k] = f2tf32f(v - h);
        s += v * v;
    }
    g_sq[m] = s;
}

// ---------------- 3xTF32 Gram: symmetric, 36 tile pairs, tensor-core ----------------
#define GBK 16
#define P_STR 20
#define P_BUF (128*P_STR)
#define GRAM_SMEM (8 * P_BUF * 4)         // 81920 B
#define T_STR 132

__global__ __launch_bounds__(256) void k_gram_tc(int Kp) {
    extern __shared__ float smem[];
    float* MH = smem;
    float* ML = MH + 2 * P_BUF;
    float* NH = ML + 2 * P_BUF;
    float* NL = NH + 2 * P_BUF;

    uint32_t mh0 = (uint32_t)__cvta_generic_to_shared(MH);
    uint32_t ml0 = (uint32_t)__cvta_generic_to_shared(ML);
    uint32_t nh0 = (uint32_t)__cvta_generic_to_shared(NH);
    uint32_t nl0 = (uint32_t)__cvta_generic_to_shared(NL);

    int b = blockIdx.z;
    int p = blockIdx.x, mt = 0;
    while (p >= 8 - mt) { p -= 8 - mt; mt++; }
    int nt = mt + p;
    int m0 = mt * 128, n0 = nt * 128;
    int M0 = b * NP + m0, N0 = b * NP + n0;

    int tid = threadIdx.x;
    int wid = tid >> 5, lane = tid & 31;
    int wm = wid >> 2, wn = wid & 3;
    int gid = lane >> 2, tig = lane & 3;

    float acc[4][4][4];
    #pragma unroll
    for (int mi = 0; mi < 4; mi++)
        #pragma unroll
        for (int ni = 0; ni < 4; ni++)
            #pragma unroll
            for (int r = 0; r < 4; r++) acc[mi][ni][r] = 0.f;

    auto prefetch = [&](int buf, int k0) {
        #pragma unroll
        for (int i = 0; i < 2; i++) {
            int e = i * 256 + tid;
            int m = e >> 2, kq = e & 3;
            uint32_t d = (uint32_t)((buf * P_BUF + m * P_STR + kq * 4) * 4);
            size_t srm = (size_t)(M0 + m) * Kp + k0 + kq * 4;
            size_t srn = (size_t)(N0 + m) * Kp + k0 + kq * 4;
            cp16(mh0 + d, &g_ah[srm]);
            cp16(ml0 + d, &g_al[srm]);
            cp16(nh0 + d, &g_ah[srn]);
            cp16(nl0 + d, &g_al[srn]);
        }
        cp_commit();
    };

    int KT = Kp / GBK;
    prefetch(0, 0);

    int cur = 0;
    for (int kt = 0; kt < KT; kt++) {
        bool has_next = (kt + 1 < KT);
        if (has_next) prefetch(cur ^ 1, (kt + 1) * GBK);
        if (has_next) cp_wait1(); else cp_wait0();
        __syncthreads();

        const float* mh = MH + cur * P_BUF;
        const float* ml = ML + cur * P_BUF;
        const float* nh = NH + cur * P_BUF;
        const float* nl = NL + cur * P_BUF;

        #pragma unroll
        for (int kk = 0; kk < GBK; kk += 8) {
            unsigned bfH[4][2], bfL[4][2];
            #pragma unroll
            for (int ni = 0; ni < 4; ni++) {
                int cb = wn * 32 + ni * 8 + gid;
                bfH[ni][0] = __float_as_uint(nh[cb * P_STR + kk + tig]);
                bfH[ni][1] = __float_as_uint(nh[cb * P_STR + kk + tig + 4]);
                bfL[ni][0] = __float_as_uint(nl[cb * P_STR + kk + tig]);
                bfL[ni][1] = __float_as_uint(nl[cb * P_STR + kk + tig + 4]);
            }
            #pragma unroll
            for (int mi = 0; mi < 4; mi++) {
                int rb = wm * 64 + mi * 16;
                unsigned aH[4], aL[4];
                aH[0] = __float_as_uint(mh[(rb + gid) * P_STR + kk + tig]);
                aH[1] = __float_as_uint(mh[(rb + gid + 8) * P_STR + kk + tig]);
                aH[2] = __float_as_uint(mh[(rb + gid) * P_STR + kk + tig + 4]);
                aH[3] = __float_as_uint(mh[(rb + gid + 8) * P_STR + kk + tig + 4]);
                aL[0] = __float_as_uint(ml[(rb + gid) * P_STR + kk + tig]);
                aL[1] = __float_as_uint(ml[(rb + gid + 8) * P_STR + kk + tig]);
                aL[2] = __float_as_uint(ml[(rb + gid) * P_STR + kk + tig + 4]);
                aL[3] = __float_as_uint(ml[(rb + gid + 8) * P_STR + kk + tig + 4]);
                #pragma unroll
                for (int ni = 0; ni < 4; ni++)
                    MMA3(acc[mi][ni], aH, aL, bfH[ni], bfL[ni]);
            }
        }
        __syncthreads();
        cur ^= 1;
    }

    float d_store[4][4][4];
    #pragma unroll
    for (int mi = 0; mi < 4; mi++) {
        int rl0 = wm * 64 + mi * 16 + gid;
        float sr0 = g_sq[M0 + rl0], sr1 = g_sq[M0 + rl0 + 8];
        #pragma unroll
        for (int ni = 0; ni < 4; ni++) {
            int cl = wn * 32 + ni * 8 + tig * 2;
            float sc0 = g_sq[N0 + cl], sc1 = g_sq[N0 + cl + 1];
            float d00 = sr0 + sc0 - 2.f * acc[mi][ni][0];
            float d01 = sr0 + sc1 - 2.f * acc[mi][ni][1];
            float d10 = sr1 + sc0 - 2.f * acc[mi][ni][2];
            float d11 = sr1 + sc1 - 2.f * acc[mi][ni][3];
            if (mt == nt) {
                if (m0 + rl0 == n0 + cl)         d00 += 1e10f;
                if (m0 + rl0 == n0 + cl + 1)     d01 += 1e10f;
                if (m0 + rl0 + 8 == n0 + cl)     d10 += 1e10f;
                if (m0 + rl0 + 8 == n0 + cl + 1) d11 += 1e10f;
            }
            *(float2*)&g_gram[(size_t)(M0 + rl0) * NP + n0 + cl]     = make_float2(d00, d01);
            *(float2*)&g_gram[(size_t)(M0 + rl0 + 8) * NP + n0 + cl] = make_float2(d10, d11);
            d_store[mi][ni][0] = d00; d_store[mi][ni][1] = d01;
            d_store[mi][ni][2] = d10; d_store[mi][ni][3] = d11;
        }
    }

    if (mt != nt) {
        float* T = smem;
        __syncthreads();
        #pragma unroll
        for (int mi = 0; mi < 4; mi++) {
            int rl0 = wm * 64 + mi * 16 + gid;
            #pragma unroll
            for (int ni = 0; ni < 4; ni++) {
                int cl = wn * 32 + ni * 8 + tig * 2;
                T[(cl) * T_STR + rl0]         = d_store[mi][ni][0];
                T[(cl + 1) * T_STR + rl0]     = d_store[mi][ni][1];
                T[(cl) * T_STR + rl0 + 8]     = d_store[mi][ni][2];
                T[(cl + 1) * T_STR + rl0 + 8] = d_store[mi][ni][3];
            }
        }
        __syncthreads();
        for (int e = tid; e < 128 * 32; e += 256) {
            int r = e >> 5, q = (e & 31) * 4;
            *(float4*)&g_gram[(size_t)(N0 + r) * NP + m0 + q] =
                make_float4(T[r * T_STR + q], T[r * T_STR + q + 1],
                            T[r * T_STR + q + 2], T[r * T_STR + q + 3]);
        }
    }
}

// ---------------- kNN top-20: per-lane top-2 cache + rare rescan ----------------
__global__ void k_knn() {
    int gt = blockIdx.x * blockDim.x + threadIdx.x;
    int w = gt >> 5;
    int lane = gt & 31;
    if (w >= BB * NP) return;
    const float* row = g_gram + (size_t)w * NP;

    unsigned key[32];
    #pragma unroll
    for (int j = 0; j < 32; j++) {
        unsigned u = __float_as_uint(row[lane + j * 32]);
        key[j] = (u & 0x80000000u) ? ~u : (u | 0x80000000u);
    }

    unsigned k1 = 0xFFFFFFFFu, k2 = 0xFFFFFFFFu;
    int j1 = 0, j2 = 0;
    #pragma unroll
    for (int j = 0; j < 32; j++) {
        unsigned kk = key[j];
        if (kk < k1)      { k2 = k1; j2 = j1; k1 = kk; j1 = j; }
        else if (kk < k2) { k2 = kk; j2 = j; }
    }

    unsigned used = 0u;
    unsigned head = k1; int hj = j1;
    int stage = 0;

    for (int t = 0; t < KNN; t++) {
        unsigned wmin = __reduce_min_sync(0xFFFFFFFFu, head);
        unsigned my = (head == wmin) ? (unsigned)(lane + hj * 32) : 0xFFFFFFFFu;
        unsigned widx = __reduce_min_sync(0xFFFFFFFFu, my);
        if (lane == 0) g_idx[w * KNN + t] = (int)widx;
        if (my == widx) {
            used |= 1u << hj;
            stage++;
            if (stage == 1) { head = k2; hj = j2; }
            else {
                head = 0xFFFFFFFFu; hj = 0;
                #pragma unroll
                for (int j = 0; j < 32; j++)
                    if (!((used >> j) & 1u) && key[j] < head) { head = key[j]; hj = j; }
            }
        }
    }
}

// ---------------- split W into tf32 hi/lo planes ----------------
__global__ void k_splitW(const float* W, int K, int Kp, int cout) {
    int i = blockIdx.x * 256 + threadIdx.x;
    int N = 2 * cout;
    int k = i / N, col = i % N;
    float v = 0.f;
    if (k < K) {
        if (col < cout) v = W[(size_t)k * cout + col];
        else {
            int c2 = col - cout;
            v = W[(size_t)(K + k) * cout + c2] - W[(size_t)k * cout + c2];
        }
    }
    float h = f2tf32f(v);
    g_wh[i] = h;
    g_wl[i] = f2tf32f(v - h);
}

// ---------------- 3xTF32 GEMM, pre-split operands, cp.async double-buffered ----------------
#define A_STR 20
#define B_STR 136
#define A_BUF (128*A_STR)
#define B_BUF (GBK*B_STR)
#define GEMM_SMEM ((2*A_BUF*2 + 2*B_BUF*2) * 4)   // 75776 bytes

__global__ __launch_bounds__(256) void k_gemm_tc(int M, int Kp, int N) {
    extern __shared__ float smem[];
    float* AsH = smem;
    float* AsL = AsH + 2 * A_BUF;
    float* BsH = AsL + 2 * A_BUF;
    float* BsL = BsH + 2 * B_BUF;

    uint32_t aH0 = (uint32_t)__cvta_generic_to_shared(AsH);
    uint32_t aL0 = (uint32_t)__cvta_generic_to_shared(AsL);
    uint32_t bH0 = (uint32_t)__cvta_generic_to_shared(BsH);
    uint32_t bL0 = (uint32_t)__cvta_generic_to_shared(BsL);

    int tid = threadIdx.x;
    int m0 = blockIdx.y * 128, n0 = blockIdx.x * 128;
    int wid = tid >> 5, lane = tid & 31;
    int wm = wid >> 2, wn = wid & 3;
    int gid = lane >> 2, tig = lane & 3;

    float acc[4][4][4];
    #pragma unroll
    for (int mi = 0; mi < 4; mi++)
        #pragma unroll
        for (int ni = 0; ni < 4; ni++)
            #pragma unroll
            for (int r = 0; r < 4; r++) acc[mi][ni][r] = 0.f;

    auto prefetch = [&](int buf, int k0) {
        #pragma unroll
        for (int i = 0; i < 2; i++) {
            int e = i * 256 + tid;
            int m = e >> 2, kq = e & 3;
            size_t src = (size_t)(m0 + m) * Kp + k0 + kq * 4;
            uint32_t d = (uint32_t)((buf * A_BUF + m * A_STR + kq * 4) * 4);
            cp16(aH0 + d, &g_ah[src]);
            cp16(aL0 + d, &g_al[src]);
        }
        #pragma unroll
        for (int i = 0; i < 2; i++) {
            int e = i * 256 + tid;
            int k = e >> 5, nq = e & 31;
            size_t src = (size_t)(k0 + k) * N + n0 + nq * 4;
            uint32_t d = (uint32_t)((buf * B_BUF + k * B_STR + nq * 4) * 4);
            cp16(bH0 + d, &g_wh[src]);
            cp16(bL0 + d, &g_wl[src]);
        }
        cp_commit();
    };

    int KT = Kp / GBK;
    prefetch(0, 0);

    int cur = 0;
    for (int kt = 0; kt < KT; kt++) {
        bool has_next = (kt + 1 < KT);
        if (has_next) prefetch(cur ^ 1, (kt + 1) * GBK);
        if (has_next) cp_wait1(); else cp_wait0();
        __syncthreads();

        const float* aH = AsH + cur * A_BUF;
        const float* aL = AsL + cur * A_BUF;
        const float* bH = BsH + cur * B_BUF;
        const float* bL = BsL + cur * B_BUF;

        #pragma unroll
        for (int kk = 0; kk < GBK; kk += 8) {
            unsigned bfH[4][2], bfL[4][2];
            #pragma unroll
            for (int ni = 0; ni < 4; ni++) {
                int cb = wn * 32 + ni * 8;
                bfH[ni][0] = __float_as_uint(bH[(kk + tig) * B_STR + cb + gid]);
                bfH[ni][1] = __float_as_uint(bH[(kk + tig + 4) * B_STR + cb + gid]);
                bfL[ni][0] = __float_as_uint(bL[(kk + tig) * B_STR + cb + gid]);
                bfL[ni][1] = __float_as_uint(bL[(kk + tig + 4) * B_STR + cb + gid]);
            }
            #pragma unroll
            for (int mi = 0; mi < 4; mi++) {
                int rb = wm * 64 + mi * 16;
                unsigned aHf[4], aLf[4];
                aHf[0] = __float_as_uint(aH[(rb + gid) * A_STR + kk + tig]);
                aHf[1] = __float_as_uint(aH[(rb + gid + 8) * A_STR + kk + tig]);
                aHf[2] = __float_as_uint(aH[(rb + gid) * A_STR + kk + tig + 4]);
                aHf[3] = __float_as_uint(aH[(rb + gid + 8) * A_STR + kk + tig + 4]);
                aLf[0] = __float_as_uint(aL[(rb + gid) * A_STR + kk + tig]);
                aLf[1] = __float_as_uint(aL[(rb + gid + 8) * A_STR + kk + tig]);
                aLf[2] = __float_as_uint(aL[(rb + gid) * A_STR + kk + tig + 4]);
                aLf[3] = __float_as_uint(aL[(rb + gid + 8) * A_STR + kk + tig + 4]);
                #pragma unroll
                for (int ni = 0; ni < 4; ni++)
                    MMA3(acc[mi][ni], aHf, aLf, bfH[ni], bfL[ni]);
            }
        }
        __syncthreads();
        cur ^= 1;
    }

    #pragma unroll
    for (int mi = 0; mi < 4; mi++) {
        int row0 = m0 + wm * 64 + mi * 16 + gid;
        #pragma unroll
        for (int ni = 0; ni < 4; ni++) {
            int col = n0 + wn * 32 + ni * 8 + tig * 2;
            *(float2*)&g_uv[(size_t)row0 * N + col]       = make_float2(acc[mi][ni][0], acc[mi][ni][1]);
            *(float2*)&g_uv[(size_t)(row0 + 8) * N + col] = make_float2(acc[mi][ni][2], acc[mi][ni][3]);
        }
    }
}

// ---------------- gather over k : max + channel stats (float4, 2D mapping) ----------------
#define PTS 16
__global__ __launch_bounds__(256) void k_edge(int cout) {
    __shared__ float ssum[1024], ssum2[1024];
    int tid = threadIdx.x;
    for (int i = tid; i < cout; i += 256) { ssum[i] = 0.f; ssum2[i] = 0.f; }
    __syncthreads();

    int cpg = cout >> 2;
    int pp  = 256 / cpg;
    int pi = tid / cpg, ci = tid % cpg;
    int base = blockIdx.x * PTS;
    int b = base / NP;
    int C2 = 2 * cout;
    int o = ci * 4;

    float4 se  = make_float4(0.f, 0.f, 0.f, 0.f);
    float4 se2 = make_float4(0.f, 0.f, 0.f, 0.f);

    for (int p0 = 0; p0 < PTS; p0 += pp) {
        int bn = base + p0 + pi;
        const int* idxp = g_idx + (size_t)bn * KNN;
        int jj[KNN];
        #pragma unroll
        for (int k = 0; k < KNN; k++) jj[k] = __ldg(&idxp[k]);

        float4 u = *(const float4*)&g_uv[(size_t)bn * C2 + o];
        float4 mv = make_float4(-FLT_MAX, -FLT_MAX, -FLT_MAX, -FLT_MAX);
        #pragma unroll
        for (int k = 0; k < KNN; k++) {
            float4 v = *(const float4*)&g_uv[((size_t)b * NP + jj[k]) * C2 + cout + o];
            mv.x = fmaxf(mv.x, v.x); mv.y = fmaxf(mv.y, v.y);
            mv.z = fmaxf(mv.z, v.z); mv.w = fmaxf(mv.w, v.w);
            float4 e = make_float4(u.x + v.x, u.y + v.y, u.z + v.z, u.w + v.w);
            se.x += e.x; se.y += e.y; se.z += e.z; se.w += e.w;
            se2.x += e.x * e.x; se2.y += e.y * e.y; se2.z += e.z * e.z; se2.w += e.w * e.w;
        }
        *(float4*)&g_u[(size_t)bn * cout + o] =
            make_float4(u.x + mv.x, u.y + mv.y, u.z + mv.z, u.w + mv.w);
    }

    atomicAdd(&ssum[o + 0], se.x);  atomicAdd(&ssum[o + 1], se.y);
    atomicAdd(&ssum[o + 2], se.z);  atomicAdd(&ssum[o + 3], se.w);
    atomicAdd(&ssum2[o + 0], se2.x); atomicAdd(&ssum2[o + 1], se2.y);
    atomicAdd(&ssum2[o + 2], se2.z); atomicAdd(&ssum2[o + 3], se2.w);
    __syncthreads();
    for (int i = tid; i < cout; i += 256) {
        atomicAdd(&g_sum[i],  ssum[i]);
        atomicAdd(&g_sum2[i], ssum2[i]);
    }
}

// ---------------- BN finalize (+ re-zero accumulators for next layer) ----------------
__global__ void k_fin(const float* gam, const float* bet, int cout) {
    int o = blockIdx.x * 256 + threadIdx.x;     // 1024 threads
    float s_ = g_sum[o], s2_ = g_sum2[o];
    g_sum[o] = 0.f;  g_sum2[o] = 0.f;           // leave zeroed for next layer / replay
    if (o >= cout) return;
    float inv = 1.f / (float)EDGES;
    float mean = s_ * inv;
    float var  = s2_ * inv - mean * mean;
    float s = rsqrtf(var + 1e-5f) * gam[o];
    g_scale[o] = s;
    g_shift[o] = bet[o] - mean * s;
}

// ---------------- apply BN + relu, write next-layer planes + squared norms ----------------
__global__ void k_apply(int cout) {
    __shared__ float ssq[16];
    int tid = threadIdx.x;
    int ppb = 1024 / cout;                      // points per block: 16,16,8
    if (tid < ppb) ssq[tid] = 0.f;
    __syncthreads();

    int i4 = (blockIdx.x * 256 + tid) * 4;
    int o = i4 & (cout - 1);
    int pl = tid / (cout >> 2);                 // local point index
    float4 u = *(const float4*)&g_u[i4];
    float4 s = *(const float4*)&g_scale[o];
    float4 t = *(const float4*)&g_shift[o];
    float4 v, h, l;
    v.x = fmaxf(u.x * s.x + t.x, 0.f);
    v.y = fmaxf(u.y * s.y + t.y, 0.f);
    v.z = fmaxf(u.z * s.z + t.z, 0.f);
    v.w = fmaxf(u.w * s.w + t.w, 0.f);
    h.x = f2tf32f(v.x); h.y = f2tf32f(v.y); h.z = f2tf32f(v.z); h.w = f2tf32f(v.w);
    l.x = f2tf32f(v.x - h.x); l.y = f2tf32f(v.y - h.y);
    l.z = f2tf32f(v.z - h.z); l.w = f2tf32f(v.w - h.w);
    *(float4*)&g_ah[i4] = h;
    *(float4*)&g_al[i4] = l;

    atomicAdd(&ssq[pl], v.x * v.x + v.y * v.y + v.z * v.z + v.w * v.w);
    __syncthreads();
    if (tid < ppb) g_sq[blockIdx.x * ppb + tid] = ssq[tid];
}

// ---------------- layer-4 fused BN + relu + global max pool ----------------
__global__ void k_pzero() {
    int i = blockIdx.x * 256 + threadIdx.x;
    if (i < BB * 1024) g_pool[i] = 0.f;
}

__global__ void k_pool4() {
    int b = blockIdx.z;
    int o = blockIdx.x * 256 + threadIdx.x;
    int n0 = blockIdx.y * 256;
    float s = g_scale[o], t = g_shift[o];
    float m = -FLT_MAX;
    #pragma unroll 4
    for (int n = n0; n < n0 + 256; n++)
        m = fmaxf(m, g_u[((size_t)b * NP + n) * 1024 + o]);
    float v = fmaxf(s * m + t, 0.f);
    atomicMax((int*)&g_pool[b * 1024 + o], __float_as_int(v));
}

// ---------------- FC layers ----------------
__global__ void k_fc1(const float* W, const float* bias) {
    int b = blockIdx.x, t = threadIdx.x;
    float a0 = bias[t], a1 = bias[t + 256];
    const float* y = g_pool + b * 1024;
    #pragma unroll 4
    for (int c = 0; c < 1024; c++) {
        float xv = y[c];
        a0 += xv * W[c * 512 + t];
        a1 += xv * W[c * 512 + t + 256];
    }
    g_fc1[b * 512 + t]       = fmaxf(a0, 0.f);
    g_fc1[b * 512 + t + 256] = fmaxf(a1, 0.f);
}

__global__ void k_fc2(const float* W, const float* bias, float* out) {
    int b = blockIdx.x, o = threadIdx.x;
    if (o >= 40) return;
    float a = bias[o];
    const float* y = g_fc1 + b * 512;
    #pragma unroll 4
    for (int c = 0; c < 512; c++) a += y[c] * W[c * 40 + o];
    out[b * 40 + o] = a;
}

// ---------------- launcher (fork/join overlap: gram+knn || splitW+gemm) ----------------
extern "C" void kernel_launch(void* const* d_in, const int* in_sizes, int n_in,
                              void* d_out, int out_size) {
    (void)in_sizes; (void)n_in; (void)out_size;
    const float* pos = (const float*)d_in[0];
    const float* W[4]  = {(const float*)d_in[1],  (const float*)d_in[5],
                          (const float*)d_in[9],  (const float*)d_in[13]};
    const float* gm[4] = {(const float*)d_in[3],  (const float*)d_in[7],
                          (const float*)d_in[11], (const float*)d_in[15]};
    const float* bt[4] = {(const float*)d_in[4],  (const float*)d_in[8],
                          (const float*)d_in[12], (const float*)d_in[16]};
    const float* Wc1 = (const float*)d_in[17];
    const float* bc1 = (const float*)d_in[18];
    const float* Wc2 = (const float*)d_in[19];
    const float* bc2 = (const float*)d_in[20];

    const int cin[4]  = {3, 64, 64, 128};
    const int Kp[4]   = {16, 64, 64, 128};
    const int cout[4] = {64, 64, 128, 1024};
    const int M = BB * NP;

    static cudaStream_t s2 = nullptr;
    static cudaEvent_t evF[4], evJ[4];
    if (!s2) {
        cudaStreamCreateWithFlags(&s2, cudaStreamNonBlocking);
        for (int i = 0; i < 4; i++) {
            cudaEventCreateWithFlags(&evF[i], cudaEventDisableTiming);
            cudaEventCreateWithFlags(&evJ[i], cudaEventDisableTiming);
        }
        cudaFuncSetAttribute(k_gemm_tc, cudaFuncAttributeMaxDynamicSharedMemorySize, GEMM_SMEM);
        cudaFuncSetAttribute(k_gram_tc, cudaFuncAttributeMaxDynamicSharedMemorySize, GRAM_SMEM);
    }

    k_pzero<<<64, 256>>>();
    for (int l = 0; l < 4; l++) {
        int N2 = 2 * cout[l];
        if (l == 0) k_splitA<<<64, 256>>>(pos, cin[0], Kp[0]);

        // fork: activation planes ready on main stream
        cudaEventRecord(evF[l], 0);
        cudaStreamWaitEvent(s2, evF[l], 0);
        k_splitW<<<(Kp[l] * N2 + 255) / 256, 256, 0, s2>>>(W[l], cin[l], Kp[l], cout[l]);
        k_gemm_tc<<<dim3(N2 / 128, M / 128), 256, GEMM_SMEM, s2>>>(M, Kp[l], N2);
        cudaEventRecord(evJ[l], s2);

        // main: neighbor pipeline
        k_gram_tc<<<dim3(36, 1, BB), 256, GRAM_SMEM>>>(Kp[l]);
        k_knn<<<(M * 32) / 256, 256>>>();

        // join: edge needs gemm output + knn indices
        cudaStreamWaitEvent(0, evJ[l], 0);
        k_edge<<<M / PTS, 256>>>(cout[l]);
        k_fin<<<4, 256>>>(gm[l], bt[l], cout[l]);
        if (l < 3) k_apply<<<(M * cout[l]) / 1024, 256>>>(cout[l]);
        else       k_pool4<<<dim3(4, 4, BB), 256>>>();
    }
    k_fc1<<<BB, 256>>>(Wc1, bc1);
    k_fc2<<<BB, 64>>>(Wc2, bc2, (float*)d_out);
}

// round 10
// speedup vs baseline: 2.0788x; 1.0136x over previous
#include <cuda_runtime.h>
#include <float.h>
#include <math.h>
#include <stdint.h>

#define BB 16
#define NP 1024
#define KNN 20
#define EDGES (BB*NP*KNN)

// ---------------- scratch ----------------
__device__ float g_gram[BB*NP*NP];
__device__ float g_uv[BB*NP*2048];        // [u | v], stride 2*cout
__device__ float g_u[BB*NP*1024];         // u + max_k v  (layers 1-3)
__device__ float g_ah[BB*NP*128];         // A hi plane [M][Kp]
__device__ float g_al[BB*NP*128];         // A lo plane
__device__ float g_wh[128*2048];          // W hi plane [Kp][N]
__device__ float g_wl[128*2048];          // W lo plane
__device__ float g_sq[BB*NP];
__device__ int   g_idx[BB*NP*KNN];
__device__ float g_sum[1024];             // zero at load; k_fin re-zeros each layer
__device__ float g_sum2[1024];
__device__ float g_scale[1024];
__device__ float g_shift[1024];
__device__ int   g_pool[BB*1024];         // encoded raw max, then float after k_pfin
__device__ float g_fc1[BB*512];

__device__ __forceinline__ float f2tf32f(float f) {
    unsigned r;
    asm("cvt.rna.tf32.f32 %0, %1;" : "=r"(r) : "f"(f));
    return __uint_as_float(r);
}

// order-preserving float<->int (handles negatives) for atomicMax
__device__ __forceinline__ int encf(float f) {
    int i = __float_as_int(f);
    return i >= 0 ? i : (i ^ 0x7fffffff);
}
__device__ __forceinline__ float decf(int i) {
    return __int_as_float(i >= 0 ? i : (i ^ 0x7fffffff));
}

// cp.async helpers
__device__ __forceinline__ void cp16(uint32_t dst, const void* src) {
    asm volatile("cp.async.ca.shared.global [%0], [%1], 16;\n" :: "r"(dst), "l"(src));
}
__device__ __forceinline__ void cp_commit() { asm volatile("cp.async.commit_group;\n"); }
__device__ __forceinline__ void cp_wait1() { asm volatile("cp.async.wait_group 1;\n"); }
__device__ __forceinline__ void cp_wait0() { asm volatile("cp.async.wait_group 0;\n"); }

#define MMA3(ACC, AH, AL, BH, BL)                                                \
    do {                                                                         \
        asm volatile("mma.sync.aligned.m16n8k8.row.col.f32.tf32.tf32.f32 "       \
            "{%0,%1,%2,%3}, {%4,%5,%6,%7}, {%8,%9}, {%0,%1,%2,%3};"              \
            : "+f"(ACC[0]), "+f"(ACC[1]), "+f"(ACC[2]), "+f"(ACC[3])             \
            : "r"(AH[0]), "r"(AH[1]), "r"(AH[2]), "r"(AH[3]), "r"(BL[0]), "r"(BL[1])); \
        asm volatile("mma.sync.aligned.m16n8k8.row.col.f32.tf32.tf32.f32 "       \
            "{%0,%1,%2,%3}, {%4,%5,%6,%7}, {%8,%9}, {%0,%1,%2,%3};"              \
            : "+f"(ACC[0]), "+f"(ACC[1]), "+f"(ACC[2]), "+f"(ACC[3])             \
            : "r"(AL[0]), "r"(AL[1]), "r"(AL[2]), "r"(AL[3]), "r"(BH[0]), "r"(BH[1])); \
        asm volatile("mma.sync.aligned.m16n8k8.row.col.f32.tf32.tf32.f32 "       \
            "{%0,%1,%2,%3}, {%4,%5,%6,%7}, {%8,%9}, {%0,%1,%2,%3};"              \
            : "+f"(ACC[0]), "+f"(ACC[1]), "+f"(ACC[2]), "+f"(ACC[3])             \
            : "r"(AH[0]), "r"(AH[1]), "r"(AH[2]), "r"(AH[3]), "r"(BH[0]), "r"(BH[1])); \
    } while (0)

// ---------------- split layer-1 input (pos) into planes + squared norms ----------------
__global__ void k_splitA(const float* x, int K, int Kp) {
    int m = blockIdx.x * 256 + threadIdx.x;
    if (m >= BB * NP) return;
    float s = 0.f;
    for (int k = 0; k < Kp; k++) {
        float v = (k < K) ? x[(size_t)m * K + k] : 0.f;
        float h = f2tf32f(v);
        g_ah[(size_t)m * Kp + k] = h;
        g_al[(size_t)m * Kp + k] = f2tf32f(v - h);
        s += v * v;
    }
    g_sq[m] = s;
}

// ---------------- 3xTF32 Gram: symmetric, 36 tile pairs, tensor-core ----------------
#define GBK 16
#define P_STR 20
#define P_BUF (128*P_STR)
#define GRAM_SMEM (8 * P_BUF * 4)         // 81920 B
#define T_STR 132

__global__ __launch_bounds__(256) void k_gram_tc(int Kp) {
    extern __shared__ float smem[];
    float* MH = smem;
    float* ML = MH + 2 * P_BUF;
    float* NH = ML + 2 * P_BUF;
    float* NL = NH + 2 * P_BUF;

    uint32_t mh0 = (uint32_t)__cvta_generic_to_shared(MH);
    uint32_t ml0 = (uint32_t)__cvta_generic_to_shared(ML);
    uint32_t nh0 = (uint32_t)__cvta_generic_to_shared(NH);
    uint32_t nl0 = (uint32_t)__cvta_generic_to_shared(NL);

    int b = blockIdx.z;
    int p = blockIdx.x, mt = 0;
    while (p >= 8 - mt) { p -= 8 - mt; mt++; }
    int nt = mt + p;
    int m0 = mt * 128, n0 = nt * 128;
    int M0 = b * NP + m0, N0 = b * NP + n0;

    int tid = threadIdx.x;
    int wid = tid >> 5, lane = tid & 31;
    int wm = wid >> 2, wn = wid & 3;
    int gid = lane >> 2, tig = lane & 3;

    float acc[4][4][4];
    #pragma unroll
    for (int mi = 0; mi < 4; mi++)
        #pragma unroll
        for (int ni = 0; ni < 4; ni++)
            #pragma unroll
            for (int r = 0; r < 4; r++) acc[mi][ni][r] = 0.f;

    auto prefetch = [&](int buf, int k0) {
        #pragma unroll
        for (int i = 0; i < 2; i++) {
            int e = i * 256 + tid;
            int m = e >> 2, kq = e & 3;
            uint32_t d = (uint32_t)((buf * P_BUF + m * P_STR + kq * 4) * 4);
            size_t srm = (size_t)(M0 + m) * Kp + k0 + kq * 4;
            size_t srn = (size_t)(N0 + m) * Kp + k0 + kq * 4;
            cp16(mh0 + d, &g_ah[srm]);
            cp16(ml0 + d, &g_al[srm]);
            cp16(nh0 + d, &g_ah[srn]);
            cp16(nl0 + d, &g_al[srn]);
        }
        cp_commit();
    };

    int KT = Kp / GBK;
    prefetch(0, 0);

    int cur = 0;
    for (int kt = 0; kt < KT; kt++) {
        bool has_next = (kt + 1 < KT);
        if (has_next) prefetch(cur ^ 1, (kt + 1) * GBK);
        if (has_next) cp_wait1(); else cp_wait0();
        __syncthreads();

        const float* mh = MH + cur * P_BUF;
        const float* ml = ML + cur * P_BUF;
        const float* nh = NH + cur * P_BUF;
        const float* nl = NL + cur * P_BUF;

        #pragma unroll
        for (int kk = 0; kk < GBK; kk += 8) {
            unsigned bfH[4][2], bfL[4][2];
            #pragma unroll
            for (int ni = 0; ni < 4; ni++) {
                int cb = wn * 32 + ni * 8 + gid;
                bfH[ni][0] = __float_as_uint(nh[cb * P_STR + kk + tig]);
                bfH[ni][1] = __float_as_uint(nh[cb * P_STR + kk + tig + 4]);
                bfL[ni][0] = __float_as_uint(nl[cb * P_STR + kk + tig]);
                bfL[ni][1] = __float_as_uint(nl[cb * P_STR + kk + tig + 4]);
            }
            #pragma unroll
            for (int mi = 0; mi < 4; mi++) {
                int rb = wm * 64 + mi * 16;
                unsigned aH[4], aL[4];
                aH[0] = __float_as_uint(mh[(rb + gid) * P_STR + kk + tig]);
                aH[1] = __float_as_uint(mh[(rb + gid + 8) * P_STR + kk + tig]);
                aH[2] = __float_as_uint(mh[(rb + gid) * P_STR + kk + tig + 4]);
                aH[3] = __float_as_uint(mh[(rb + gid + 8) * P_STR + kk + tig + 4]);
                aL[0] = __float_as_uint(ml[(rb + gid) * P_STR + kk + tig]);
                aL[1] = __float_as_uint(ml[(rb + gid + 8) * P_STR + kk + tig]);
                aL[2] = __float_as_uint(ml[(rb + gid) * P_STR + kk + tig + 4]);
                aL[3] = __float_as_uint(ml[(rb + gid + 8) * P_STR + kk + tig + 4]);
                #pragma unroll
                for (int ni = 0; ni < 4; ni++)
                    MMA3(acc[mi][ni], aH, aL, bfH[ni], bfL[ni]);
            }
        }
        __syncthreads();
        cur ^= 1;
    }

    float d_store[4][4][4];
    #pragma unroll
    for (int mi = 0; mi < 4; mi++) {
        int rl0 = wm * 64 + mi * 16 + gid;
        float sr0 = g_sq[M0 + rl0], sr1 = g_sq[M0 + rl0 + 8];
        #pragma unroll
        for (int ni = 0; ni < 4; ni++) {
            int cl = wn * 32 + ni * 8 + tig * 2;
            float sc0 = g_sq[N0 + cl], sc1 = g_sq[N0 + cl + 1];
            float d00 = sr0 + sc0 - 2.f * acc[mi][ni][0];
            float d01 = sr0 + sc1 - 2.f * acc[mi][ni][1];
            float d10 = sr1 + sc0 - 2.f * acc[mi][ni][2];
            float d11 = sr1 + sc1 - 2.f * acc[mi][ni][3];
            if (mt == nt) {
                if (m0 + rl0 == n0 + cl)         d00 += 1e10f;
                if (m0 + rl0 == n0 + cl + 1)     d01 += 1e10f;
                if (m0 + rl0 + 8 == n0 + cl)     d10 += 1e10f;
                if (m0 + rl0 + 8 == n0 + cl + 1) d11 += 1e10f;
            }
            *(float2*)&g_gram[(size_t)(M0 + rl0) * NP + n0 + cl]     = make_float2(d00, d01);
            *(float2*)&g_gram[(size_t)(M0 + rl0 + 8) * NP + n0 + cl] = make_float2(d10, d11);
            d_store[mi][ni][0] = d00; d_store[mi][ni][1] = d01;
            d_store[mi][ni][2] = d10; d_store[mi][ni][3] = d11;
        }
    }

    if (mt != nt) {
        float* T = smem;
        __syncthreads();
        #pragma unroll
        for (int mi = 0; mi < 4; mi++) {
            int rl0 = wm * 64 + mi * 16 + gid;
            #pragma unroll
            for (int ni = 0; ni < 4; ni++) {
                int cl = wn * 32 + ni * 8 + tig * 2;
                T[(cl) * T_STR + rl0]         = d_store[mi][ni][0];
                T[(cl + 1) * T_STR + rl0]     = d_store[mi][ni][1];
                T[(cl) * T_STR + rl0 + 8]     = d_store[mi][ni][2];
                T[(cl + 1) * T_STR + rl0 + 8] = d_store[mi][ni][3];
            }
        }
        __syncthreads();
        for (int e = tid; e < 128 * 32; e += 256) {
            int r = e >> 5, q = (e & 31) * 4;
            *(float4*)&g_gram[(size_t)(N0 + r) * NP + m0 + q] =
                make_float4(T[r * T_STR + q], T[r * T_STR + q + 1],
                            T[r * T_STR + q + 2], T[r * T_STR + q + 3]);
        }
    }
}

// ---------------- kNN top-20: 2 rows per warp (interleaved REDUX chains) ----------------
__device__ __forceinline__ unsigned ordkey(float f) {
    unsigned u = __float_as_uint(f);
    return (u & 0x80000000u) ? ~u : (u | 0x80000000u);
}

__global__ __launch_bounds__(256) void k_knn() {
    int warp = (blockIdx.x * 256 + threadIdx.x) >> 5;
    int lane = threadIdx.x & 31;
    int wA = warp * 2, wB = wA + 1;
    if (wA >= BB * NP) return;
    const float* rowA = g_gram + (size_t)wA * NP;
    const float* rowB = g_gram + (size_t)wB * NP;

    unsigned kA[32], kB[32];
    #pragma unroll
    for (int jq = 0; jq < 8; jq++) {
        float4 a = *(const float4*)&rowA[lane * 4 + jq * 128];
        float4 b = *(const float4*)&rowB[lane * 4 + jq * 128];
        kA[jq*4+0] = ordkey(a.x); kA[jq*4+1] = ordkey(a.y);
        kA[jq*4+2] = ordkey(a.z); kA[jq*4+3] = ordkey(a.w);
        kB[jq*4+0] = ordkey(b.x); kB[jq*4+1] = ordkey(b.y);
        kB[jq*4+2] = ordkey(b.z); kB[jq*4+3] = ordkey(b.w);
    }
    // global column of key j: lane*4 + (j>>2)*128 + (j&3)  (monotone in j)
    #define COLOF(j) (unsigned)(lane * 4 + ((j) >> 2) * 128 + ((j) & 3))

    // per-lane top-2 for each row (strict < keeps smallest j among ties)
    unsigned hA = 0xFFFFFFFFu, sA = 0xFFFFFFFFu; int hjA = 0, sjA = 0;
    unsigned hB = 0xFFFFFFFFu, sB = 0xFFFFFFFFu; int hjB = 0, sjB = 0;
    #pragma unroll
    for (int j = 0; j < 32; j++) {
        unsigned a = kA[j];
        if (a < hA)      { sA = hA; sjA = hjA; hA = a; hjA = j; }
        else if (a < sA) { sA = a; sjA = j; }
        unsigned b = kB[j];
        if (b < hB)      { sB = hB; sjB = hjB; hB = b; hjB = j; }
        else if (b < sB) { sB = b; sjB = j; }
    }

    unsigned usedA = 0u, usedB = 0u;
    int stA = 0, stB = 0;

    for (int t = 0; t < KNN; t++) {
        unsigned wminA = __reduce_min_sync(0xFFFFFFFFu, hA);
        unsigned wminB = __reduce_min_sync(0xFFFFFFFFu, hB);
        unsigned myA = (hA == wminA) ? COLOF(hjA) : 0xFFFFFFFFu;
        unsigned myB = (hB == wminB) ? COLOF(hjB) : 0xFFFFFFFFu;
        unsigned wiA = __reduce_min_sync(0xFFFFFFFFu, myA);
        unsigned wiB = __reduce_min_sync(0xFFFFFFFFu, myB);
        if (lane == 0) {
            g_idx[wA * KNN + t] = (int)wiA;
            g_idx[wB * KNN + t] = (int)wiB;
        }
        if (myA == wiA) {
            usedA |= 1u << hjA;
            stA++;
            if (stA == 1) { hA = sA; hjA = sjA; }
            else {
                hA = 0xFFFFFFFFu; hjA = 0;
                #pragma unroll
                for (int j = 0; j < 32; j++)
                    if (!((usedA >> j) & 1u) && kA[j] < hA) { hA = kA[j]; hjA = j; }
            }
        }
        if (myB == wiB) {
            usedB |= 1u << hjB;
            stB++;
            if (stB == 1) { hB = sB; hjB = sjB; }
            else {
                hB = 0xFFFFFFFFu; hjB = 0;
                #pragma unroll
                for (int j = 0; j < 32; j++)
                    if (!((usedB >> j) & 1u) && kB[j] < hB) { hB = kB[j]; hjB = j; }
            }
        }
    }
    #undef COLOF
}

// ---------------- split W into tf32 hi/lo planes ----------------
__global__ void k_splitW(const float* W, int K, int Kp, int cout) {
    int i = blockIdx.x * 256 + threadIdx.x;
    int N = 2 * cout;
    int k = i / N, col = i % N;
    float v = 0.f;
    if (k < K) {
        if (col < cout) v = W[(size_t)k * cout + col];
        else {
            int c2 = col - cout;
            v = W[(size_t)(K + k) * cout + c2] - W[(size_t)k * cout + c2];
        }
    }
    float h = f2tf32f(v);
    g_wh[i] = h;
    g_wl[i] = f2tf32f(v - h);
}

// ---------------- 3xTF32 GEMM, pre-split operands, cp.async double-buffered ----------------
#define A_STR 20
#define B_STR 136
#define A_BUF (128*A_STR)
#define B_BUF (GBK*B_STR)
#define GEMM_SMEM ((2*A_BUF*2 + 2*B_BUF*2) * 4)   // 75776 bytes

__global__ __launch_bounds__(256) void k_gemm_tc(int M, int Kp, int N) {
    extern __shared__ float smem[];
    float* AsH = smem;
    float* AsL = AsH + 2 * A_BUF;
    float* BsH = AsL + 2 * A_BUF;
    float* BsL = BsH + 2 * B_BUF;

    uint32_t aH0 = (uint32_t)__cvta_generic_to_shared(AsH);
    uint32_t aL0 = (uint32_t)__cvta_generic_to_shared(AsL);
    uint32_t bH0 = (uint32_t)__cvta_generic_to_shared(BsH);
    uint32_t bL0 = (uint32_t)__cvta_generic_to_shared(BsL);

    int tid = threadIdx.x;
    int m0 = blockIdx.y * 128, n0 = blockIdx.x * 128;
    int wid = tid >> 5, lane = tid & 31;
    int wm = wid >> 2, wn = wid & 3;
    int gid = lane >> 2, tig = lane & 3;

    float acc[4][4][4];
    #pragma unroll
    for (int mi = 0; mi < 4; mi++)
        #pragma unroll
        for (int ni = 0; ni < 4; ni++)
            #pragma unroll
            for (int r = 0; r < 4; r++) acc[mi][ni][r] = 0.f;

    auto prefetch = [&](int buf, int k0) {
        #pragma unroll
        for (int i = 0; i < 2; i++) {
            int e = i * 256 + tid;
            int m = e >> 2, kq = e & 3;
            size_t src = (size_t)(m0 + m) * Kp + k0 + kq * 4;
            uint32_t d = (uint32_t)((buf * A_BUF + m * A_STR + kq * 4) * 4);
            cp16(aH0 + d, &g_ah[src]);
            cp16(aL0 + d, &g_al[src]);
        }
        #pragma unroll
        for (int i = 0; i < 2; i++) {
            int e = i * 256 + tid;
            int k = e >> 5, nq = e & 31;
            size_t src = (size_t)(k0 + k) * N + n0 + nq * 4;
            uint32_t d = (uint32_t)((buf * B_BUF + k * B_STR + nq * 4) * 4);
            cp16(bH0 + d, &g_wh[src]);
            cp16(bL0 + d, &g_wl[src]);
        }
        cp_commit();
    };

    int KT = Kp / GBK;
    prefetch(0, 0);

    int cur = 0;
    for (int kt = 0; kt < KT; kt++) {
        bool has_next = (kt + 1 < KT);
        if (has_next) prefetch(cur ^ 1, (kt + 1) * GBK);
        if (has_next) cp_wait1(); else cp_wait0();
        __syncthreads();

        const float* aH = AsH + cur * A_BUF;
        const float* aL = AsL + cur * A_BUF;
        const float* bH = BsH + cur * B_BUF;
        const float* bL = BsL + cur * B_BUF;

        #pragma unroll
        for (int kk = 0; kk < GBK; kk += 8) {
            unsigned bfH[4][2], bfL[4][2];
            #pragma unroll
            for (int ni = 0; ni < 4; ni++) {
                int cb = wn * 32 + ni * 8;
                bfH[ni][0] = __float_as_uint(bH[(kk + tig) * B_STR + cb + gid]);
                bfH[ni][1] = __float_as_uint(bH[(kk + tig + 4) * B_STR + cb + gid]);
                bfL[ni][0] = __float_as_uint(bL[(kk + tig) * B_STR + cb + gid]);
                bfL[ni][1] = __float_as_uint(bL[(kk + tig + 4) * B_STR + cb + gid]);
            }
            #pragma unroll
            for (int mi = 0; mi < 4; mi++) {
                int rb = wm * 64 + mi * 16;
                unsigned aHf[4], aLf[4];
                aHf[0] = __float_as_uint(aH[(rb + gid) * A_STR + kk + tig]);
                aHf[1] = __float_as_uint(aH[(rb + gid + 8) * A_STR + kk + tig]);
                aHf[2] = __float_as_uint(aH[(rb + gid) * A_STR + kk + tig + 4]);
                aHf[3] = __float_as_uint(aH[(rb + gid + 8) * A_STR + kk + tig + 4]);
                aLf[0] = __float_as_uint(aL[(rb + gid) * A_STR + kk + tig]);
                aLf[1] = __float_as_uint(aL[(rb + gid + 8) * A_STR + kk + tig]);
                aLf[2] = __float_as_uint(aL[(rb + gid) * A_STR + kk + tig + 4]);
                aLf[3] = __float_as_uint(aL[(rb + gid + 8) * A_STR + kk + tig + 4]);
                #pragma unroll
                for (int ni = 0; ni < 4; ni++)
                    MMA3(acc[mi][ni], aHf, aLf, bfH[ni], bfL[ni]);
            }
        }
        __syncthreads();
        cur ^= 1;
    }

    #pragma unroll
    for (int mi = 0; mi < 4; mi++) {
        int row0 = m0 + wm * 64 + mi * 16 + gid;
        #pragma unroll
        for (int ni = 0; ni < 4; ni++) {
            int col = n0 + wn * 32 + ni * 8 + tig * 2;
            *(float2*)&g_uv[(size_t)row0 * N + col]       = make_float2(acc[mi][ni][0], acc[mi][ni][1]);
            *(float2*)&g_uv[(size_t)(row0 + 8) * N + col] = make_float2(acc[mi][ni][2], acc[mi][ni][3]);
        }
    }
}

// ---------------- gather over k : max + stats; layer 4 fuses global pool ----------------
#define PTS 16
__global__ __launch_bounds__(256) void k_edge(int cout, int dopool) {
    __shared__ float ssum[1024], ssum2[1024];
    int tid = threadIdx.x;
    for (int i = tid; i < cout; i += 256) { ssum[i] = 0.f; ssum2[i] = 0.f; }
    __syncthreads();

    int cpg = cout >> 2;
    int pp  = 256 / cpg;
    int pi = tid / cpg, ci = tid % cpg;
    int base = blockIdx.x * PTS;
    int b = base / NP;
    int C2 = 2 * cout;
    int o = ci * 4;

    float4 se  = make_float4(0.f, 0.f, 0.f, 0.f);
    float4 se2 = make_float4(0.f, 0.f, 0.f, 0.f);
    float4 pm  = make_float4(-FLT_MAX, -FLT_MAX, -FLT_MAX, -FLT_MAX);

    for (int p0 = 0; p0 < PTS; p0 += pp) {
        int bn = base + p0 + pi;
        const int* idxp = g_idx + (size_t)bn * KNN;
        int jj[KNN];
        #pragma unroll
        for (int k = 0; k < KNN; k++) jj[k] = __ldg(&idxp[k]);

        float4 u = *(const float4*)&g_uv[(size_t)bn * C2 + o];
        float4 mv = make_float4(-FLT_MAX, -FLT_MAX, -FLT_MAX, -FLT_MAX);
        #pragma unroll
        for (int k = 0; k < KNN; k++) {
            float4 v = *(const float4*)&g_uv[((size_t)b * NP + jj[k]) * C2 + cout + o];
            mv.x = fmaxf(mv.x, v.x); mv.y = fmaxf(mv.y, v.y);
            mv.z = fmaxf(mv.z, v.z); mv.w = fmaxf(mv.w, v.w);
            float4 e = make_float4(u.x + v.x, u.y + v.y, u.z + v.z, u.w + v.w);
            se.x += e.x; se.y += e.y; se.z += e.z; se.w += e.w;
            se2.x += e.x * e.x; se2.y += e.y * e.y; se2.z += e.z * e.z; se2.w += e.w * e.w;
        }
        float4 tot = make_float4(u.x + mv.x, u.y + mv.y, u.z + mv.z, u.w + mv.w);
        if (!dopool) {
            *(float4*)&g_u[(size_t)bn * cout + o] = tot;
        } else {
            pm.x = fmaxf(pm.x, tot.x); pm.y = fmaxf(pm.y, tot.y);
            pm.z = fmaxf(pm.z, tot.z); pm.w = fmaxf(pm.w, tot.w);
        }
    }

    if (dopool) {
        int* dst = &g_pool[b * 1024 + o];
        atomicMax(dst + 0, encf(pm.x));
        atomicMax(dst + 1, encf(pm.y));
        atomicMax(dst + 2, encf(pm.z));
        atomicMax(dst + 3, encf(pm.w));
    }

    atomicAdd(&ssum[o + 0], se.x);  atomicAdd(&ssum[o + 1], se.y);
    atomicAdd(&ssum[o + 2], se.z);  atomicAdd(&ssum[o + 3], se.w);
    atomicAdd(&ssum2[o + 0], se2.x); atomicAdd(&ssum2[o + 1], se2.y);
    atomicAdd(&ssum2[o + 2], se2.z); atomicAdd(&ssum2[o + 3], se2.w);
    __syncthreads();
    for (int i = tid; i < cout; i += 256) {
        atomicAdd(&g_sum[i],  ssum[i]);
        atomicAdd(&g_sum2[i], ssum2[i]);
    }
}

// ---------------- BN finalize (+ re-zero accumulators) ----------------
__global__ void k_fin(const float* gam, const float* bet, int cout) {
    int o = blockIdx.x * 256 + threadIdx.x;
    float s_ = g_sum[o], s2_ = g_sum2[o];
    g_sum[o] = 0.f;  g_sum2[o] = 0.f;
    if (o >= cout) return;
    float inv = 1.f / (float)EDGES;
    float mean = s_ * inv;
    float var  = s2_ * inv - mean * mean;
    float s = rsqrtf(var + 1e-5f) * gam[o];
    g_scale[o] = s;
    g_shift[o] = bet[o] - mean * s;
}

// ---------------- apply BN + relu, write next-layer planes + squared norms ----------------
__global__ void k_apply(int cout) {
    __shared__ float ssq[16];
    int tid = threadIdx.x;
    int ppb = 1024 / cout;
    if (tid < ppb) ssq[tid] = 0.f;
    __syncthreads();

    int i4 = (blockIdx.x * 256 + tid) * 4;
    int o = i4 & (cout - 1);
    int pl = tid / (cout >> 2);
    float4 u = *(const float4*)&g_u[i4];
    float4 s = *(const float4*)&g_scale[o];
    float4 t = *(const float4*)&g_shift[o];
    float4 v, h, l;
    v.x = fmaxf(u.x * s.x + t.x, 0.f);
    v.y = fmaxf(u.y * s.y + t.y, 0.f);
    v.z = fmaxf(u.z * s.z + t.z, 0.f);
    v.w = fmaxf(u.w * s.w + t.w, 0.f);
    h.x = f2tf32f(v.x); h.y = f2tf32f(v.y); h.z = f2tf32f(v.z); h.w = f2tf32f(v.w);
    l.x = f2tf32f(v.x - h.x); l.y = f2tf32f(v.y - h.y);
    l.z = f2tf32f(v.z - h.z); l.w = f2tf32f(v.w - h.w);
    *(float4*)&g_ah[i4] = h;
    *(float4*)&g_al[i4] = l;

    atomicAdd(&ssq[pl], v.x * v.x + v.y * v.y + v.z * v.z + v.w * v.w);
    __syncthreads();
    if (tid < ppb) g_sq[blockIdx.x * ppb + tid] = ssq[tid];
}

// ---------------- pool init (encoded -inf) + pooled BN finalize ----------------
__global__ void k_pzero() {
    int i = blockIdx.x * 256 + threadIdx.x;
    if (i < BB * 1024) g_pool[i] = (int)0x80000000;
}

__global__ void k_pfin() {
    int i = blockIdx.x * 256 + threadIdx.x;     // 16K threads
    int o = i & 1023;
    float m = decf(g_pool[i]);
    float v = fmaxf(g_scale[o] * m + g_shift[o], 0.f);
    ((float*)g_pool)[i] = v;
}

// ---------------- FC layers ----------------
__global__ void k_fc1(const float* W, const float* bias) {
    int b = blockIdx.x, t = threadIdx.x;
    float a0 = bias[t], a1 = bias[t + 256];
    const float* y = (const float*)g_pool + b * 1024;
    #pragma unroll 4
    for (int c = 0; c < 1024; c++) {
        float xv = y[c];
        a0 += xv * W[c * 512 + t];
        a1 += xv * W[c * 512 + t + 256];
    }
    g_fc1[b * 512 + t]       = fmaxf(a0, 0.f);
    g_fc1[b * 512 + t + 256] = fmaxf(a1, 0.f);
}

__global__ void k_fc2(const float* W, const float* bias, float* out) {
    int b = blockIdx.x, o = threadIdx.x;
    if (o >= 40) return;
    float a = bias[o];
    const float* y = g_fc1 + b * 512;
    #pragma unroll 4
    for (int c = 0; c < 512; c++) a += y[c] * W[c * 40 + o];
    out[b * 40 + o] = a;
}

// ---------------- launcher (fork/join overlap: gram+knn || splitW+gemm) ----------------
extern "C" void kernel_launch(void* const* d_in, const int* in_sizes, int n_in,
                              void* d_out, int out_size) {
    (void)in_sizes; (void)n_in; (void)out_size;
    const float* pos = (const float*)d_in[0];
    const float* W[4]  = {(const float*)d_in[1],  (const float*)d_in[5],
                          (const float*)d_in[9],  (const float*)d_in[13]};
    const float* gm[4] = {(const float*)d_in[3],  (const float*)d_in[7],
                          (const float*)d_in[11], (const float*)d_in[15]};
    const float* bt[4] = {(const float*)d_in[4],  (const float*)d_in[8],
                          (const float*)d_in[12], (const float*)d_in[16]};
    const float* Wc1 = (const float*)d_in[17];
    const float* bc1 = (const float*)d_in[18];
    const float* Wc2 = (const float*)d_in[19];
    const float* bc2 = (const float*)d_in[20];

    const int cin[4]  = {3, 64, 64, 128};
    const int Kp[4]   = {16, 64, 64, 128};
    const int cout[4] = {64, 64, 128, 1024};
    const int M = BB * NP;

    static cudaStream_t s2 = nullptr;
    static cudaEvent_t evF[4], evJ[4];
    if (!s2) {
        cudaStreamCreateWithFlags(&s2, cudaStreamNonBlocking);
        for (int i = 0; i < 4; i++) {
            cudaEventCreateWithFlags(&evF[i], cudaEventDisableTiming);
            cudaEventCreateWithFlags(&evJ[i], cudaEventDisableTiming);
        }
        cudaFuncSetAttribute(k_gemm_tc, cudaFuncAttributeMaxDynamicSharedMemorySize, GEMM_SMEM);
        cudaFuncSetAttribute(k_gram_tc, cudaFuncAttributeMaxDynamicSharedMemorySize, GRAM_SMEM);
    }

    k_pzero<<<64, 256>>>();
    for (int l = 0; l < 4; l++) {
        int N2 = 2 * cout[l];
        if (l == 0) k_splitA<<<64, 256>>>(pos, cin[0], Kp[0]);

        // fork: activation planes ready on main stream
        cudaEventRecord(evF[l], 0);
        cudaStreamWaitEvent(s2, evF[l], 0);
        k_splitW<<<(Kp[l] * N2 + 255) / 256, 256, 0, s2>>>(W[l], cin[l], Kp[l], cout[l]);
        k_gemm_tc<<<dim3(N2 / 128, M / 128), 256, GEMM_SMEM, s2>>>(M, Kp[l], N2);
        cudaEventRecord(evJ[l], s2);

        // main: neighbor pipeline
        k_gram_tc<<<dim3(36, 1, BB), 256, GRAM_SMEM>>>(Kp[l]);
        k_knn<<<(M / 2 * 32) / 256, 256>>>();

        // join: edge needs gemm output + knn indices
        cudaStreamWaitEvent(0, evJ[l], 0);
        k_edge<<<M / PTS, 256>>>(cout[l], l == 3 ? 1 : 0);
        k_fin<<<4, 256>>>(gm[l], bt[l], cout[l]);
        if (l < 3) k_apply<<<(M * cout[l]) / 1024, 256>>>(cout[l]);
        else       k_pfin<<<64, 256>>>();
    }
    k_fc1<<<BB, 256>>>(Wc1, bc1);
    k_fc2<<<BB, 64>>>(Wc2, bc2, (float*)d_out);
}